// round 2
// baseline (speedup 1.0000x reference)
#include <cuda_runtime.h>
#include <math.h>
#include <float.h>

#define BATCH 2
#define NQ    1024
#define NK    4096
#define HID   1024
#define HEADS 16
#define HD    64
#define LN_EPS 1e-5f

// ---------------- scratch (__device__ globals; no allocations allowed) ------
__device__ float g_qn [BATCH*NQ*HID];
__device__ float g_kvn[BATCH*NK*HID];
__device__ float g_q  [BATCH*NQ*HID];
__device__ float g_k  [BATCH*NK*HID];
__device__ float g_v  [BATCH*NK*HID];
__device__ float g_ctx[BATCH*NQ*HID];
__device__ float g_o  [BATCH*NQ*HID];

// ---------------- block reduce (256 threads) --------------------------------
__device__ __forceinline__ float2 block_reduce2(float a, float b, float* sh /*16 floats*/) {
    #pragma unroll
    for (int o = 16; o; o >>= 1) {
        a += __shfl_xor_sync(0xffffffffu, a, o);
        b += __shfl_xor_sync(0xffffffffu, b, o);
    }
    int w = threadIdx.x >> 5;
    if ((threadIdx.x & 31) == 0) { sh[w] = a; sh[8 + w] = b; }
    __syncthreads();
    if (threadIdx.x == 0) {
        float sa = 0.f, sb = 0.f;
        #pragma unroll
        for (int i = 0; i < 8; i++) { sa += sh[i]; sb += sh[8 + i]; }
        sh[0] = sa; sh[8] = sb;
    }
    __syncthreads();
    return make_float2(sh[0], sh[8]);
}

// ---------------- LayerNorm: one block per row of 1024 ----------------------
__global__ void ln_kernel(const float* __restrict__ x,
                          const float* __restrict__ w,
                          const float* __restrict__ b,
                          float* __restrict__ out) {
    __shared__ float sh[16];
    size_t row = blockIdx.x;
    const float4* xr = (const float4*)(x + row * HID);
    float4 v = xr[threadIdx.x];
    float s  = v.x + v.y + v.z + v.w;
    float s2 = v.x*v.x + v.y*v.y + v.z*v.z + v.w*v.w;
    float2 r = block_reduce2(s, s2, sh);
    float mean = r.x * (1.f / HID);
    float var  = r.y * (1.f / HID) - mean * mean;
    float rstd = rsqrtf(var + LN_EPS);
    float4 wv = ((const float4*)w)[threadIdx.x];
    float4 bv = ((const float4*)b)[threadIdx.x];
    float4 o;
    o.x = (v.x - mean) * rstd * wv.x + bv.x;
    o.y = (v.y - mean) * rstd * wv.y + bv.y;
    o.z = (v.z - mean) * rstd * wv.z + bv.z;
    o.w = (v.w - mean) * rstd * wv.w + bv.w;
    ((float4*)(out + row * HID))[threadIdx.x] = o;
}

// -------- residual + LayerNorm: out = LN(x + y) -----------------------------
__global__ void res_ln_kernel(const float* __restrict__ x,
                              const float* __restrict__ y,
                              const float* __restrict__ w,
                              const float* __restrict__ b,
                              float* __restrict__ out) {
    __shared__ float sh[16];
    size_t row = blockIdx.x;
    float4 v  = ((const float4*)(x + row * HID))[threadIdx.x];
    float4 yv = ((const float4*)(y + row * HID))[threadIdx.x];
    v.x += yv.x; v.y += yv.y; v.z += yv.z; v.w += yv.w;
    float s  = v.x + v.y + v.z + v.w;
    float s2 = v.x*v.x + v.y*v.y + v.z*v.z + v.w*v.w;
    float2 r = block_reduce2(s, s2, sh);
    float mean = r.x * (1.f / HID);
    float var  = r.y * (1.f / HID) - mean * mean;
    float rstd = rsqrtf(var + LN_EPS);
    float4 wv = ((const float4*)w)[threadIdx.x];
    float4 bv = ((const float4*)b)[threadIdx.x];
    float4 o;
    o.x = (v.x - mean) * rstd * wv.x + bv.x;
    o.y = (v.y - mean) * rstd * wv.y + bv.y;
    o.z = (v.z - mean) * rstd * wv.z + bv.z;
    o.w = (v.w - mean) * rstd * wv.w + bv.w;
    ((float4*)(out + row * HID))[threadIdx.x] = o;
}

// ---------------- GEMM: C[M,N] = A[M,K] * B[N,K]^T  (both K-contiguous) -----
// 64x64 tile, BK=16, 256 threads, 4x4 micro-tile per thread.
__global__ void __launch_bounds__(256) gemm_abt(const float* __restrict__ A,
                                                const float* __restrict__ Bm,
                                                float* __restrict__ C,
                                                int M, int N, int K) {
    __shared__ float As[16][64];
    __shared__ float Bs[16][64];
    int tid = threadIdx.x;
    int tx = tid & 15, ty = tid >> 4;
    int rowBase = blockIdx.y * 64;
    int colBase = blockIdx.x * 64;

    int lr = tid >> 2;           // 0..63
    int lc = (tid & 3) * 4;      // 0,4,8,12
    const float* Ag = A  + (size_t)(rowBase + lr) * K + lc;
    const float* Bg = Bm + (size_t)(colBase + lr) * K + lc;

    float acc[4][4] = {};
    for (int k0 = 0; k0 < K; k0 += 16) {
        float4 a  = *(const float4*)(Ag + k0);
        float4 bb = *(const float4*)(Bg + k0);
        __syncthreads();
        As[lc + 0][lr] = a.x;  As[lc + 1][lr] = a.y;
        As[lc + 2][lr] = a.z;  As[lc + 3][lr] = a.w;
        Bs[lc + 0][lr] = bb.x; Bs[lc + 1][lr] = bb.y;
        Bs[lc + 2][lr] = bb.z; Bs[lc + 3][lr] = bb.w;
        __syncthreads();
        #pragma unroll
        for (int k = 0; k < 16; k++) {
            float4 ra = *(const float4*)&As[k][ty * 4];
            float4 rb = *(const float4*)&Bs[k][tx * 4];
            acc[0][0] += ra.x * rb.x; acc[0][1] += ra.x * rb.y;
            acc[0][2] += ra.x * rb.z; acc[0][3] += ra.x * rb.w;
            acc[1][0] += ra.y * rb.x; acc[1][1] += ra.y * rb.y;
            acc[1][2] += ra.y * rb.z; acc[1][3] += ra.y * rb.w;
            acc[2][0] += ra.z * rb.x; acc[2][1] += ra.z * rb.y;
            acc[2][2] += ra.z * rb.z; acc[2][3] += ra.z * rb.w;
            acc[3][0] += ra.w * rb.x; acc[3][1] += ra.w * rb.y;
            acc[3][2] += ra.w * rb.z; acc[3][3] += ra.w * rb.w;
        }
    }
    #pragma unroll
    for (int i = 0; i < 4; i++) {
        float4 r = make_float4(acc[i][0], acc[i][1], acc[i][2], acc[i][3]);
        *(float4*)&C[(size_t)(rowBase + ty * 4 + i) * N + colBase + tx * 4] = r;
    }
}

// ---------------- flash attention ------------------------------------------
// 1 thread = 1 query row (for one head). 128 threads/block -> 128 queries.
// grid: (NQ/128, HEADS, BATCH)
__global__ void __launch_bounds__(128) attn_kernel(const int* __restrict__ qt_ids,
                                                   const int* __restrict__ kt_ids,
                                                   const int* __restrict__ pad,
                                                   const float* __restrict__ tb) {
    __shared__ float ks[64][64];
    __shared__ float vs[64][64];
    __shared__ float tbs[9];
    __shared__ int   kti[64];
    __shared__ int   msk[64];   // 1 = masked (invalid)

    int b = blockIdx.z, h = blockIdx.y;
    int tid = threadIdx.x;
    int q = blockIdx.x * 128 + tid;
    if (tid < 9) tbs[tid] = tb[tid];

    float qv[64];
    const float* qp = g_q + ((size_t)(b * NQ + q)) * HID + h * HD;
    #pragma unroll
    for (int i = 0; i < 16; i++) {
        float4 t = ((const float4*)qp)[i];
        qv[4*i] = t.x; qv[4*i+1] = t.y; qv[4*i+2] = t.z; qv[4*i+3] = t.w;
    }
    int qrowt = qt_ids[q] * 3;

    float m = -1e30f, l = 0.f;
    float acc[64];
    #pragma unroll
    for (int d = 0; d < 64; d++) acc[d] = 0.f;

    for (int k0 = 0; k0 < NK; k0 += 64) {
        __syncthreads();
        const float* kg = g_k + ((size_t)(b * NK + k0)) * HID + h * HD;
        const float* vg = g_v + ((size_t)(b * NK + k0)) * HID + h * HD;
        for (int it = tid; it < 64 * 16; it += 128) {
            int j = it >> 4, d4 = it & 15;
            ((float4*)&ks[j][0])[d4] = ((const float4*)(kg + (size_t)j * HID))[d4];
            ((float4*)&vs[j][0])[d4] = ((const float4*)(vg + (size_t)j * HID))[d4];
        }
        if (tid < 64) {
            kti[tid] = kt_ids[k0 + tid];
            msk[tid] = pad[(size_t)b * NK + k0 + tid] ? 0 : 1;
        }
        __syncthreads();

        #pragma unroll 1
        for (int c = 0; c < 4; c++) {
            float s[16];
            float smax = -1e30f;
            #pragma unroll
            for (int j = 0; j < 16; j++) {
                int jj = c * 16 + j;
                float ds = 0.f;
                #pragma unroll
                for (int d4 = 0; d4 < 16; d4++) {
                    float4 kk = ((const float4*)&ks[jj][0])[d4];
                    ds += qv[4*d4]   * kk.x;
                    ds += qv[4*d4+1] * kk.y;
                    ds += qv[4*d4+2] * kk.z;
                    ds += qv[4*d4+3] * kk.w;
                }
                float sc = ds * 0.125f + tbs[qrowt + kti[jj]];
                if (msk[jj]) sc = -3.0e38f;
                s[j] = sc;
                smax = fmaxf(smax, sc);
            }
            if (smax > m) {
                float corr = __expf(m - smax);
                m = smax;
                l *= corr;
                #pragma unroll
                for (int d = 0; d < 64; d++) acc[d] *= corr;
            }
            #pragma unroll
            for (int j = 0; j < 16; j++) {
                float p = __expf(s[j] - m);
                l += p;
                int jj = c * 16 + j;
                #pragma unroll
                for (int d4 = 0; d4 < 16; d4++) {
                    float4 vv = ((const float4*)&vs[jj][0])[d4];
                    acc[4*d4]   += p * vv.x;
                    acc[4*d4+1] += p * vv.y;
                    acc[4*d4+2] += p * vv.z;
                    acc[4*d4+3] += p * vv.w;
                }
            }
        }
    }

    float inv = 1.f / l;
    float* op = g_ctx + ((size_t)(b * NQ + q)) * HID + h * HD;
    #pragma unroll
    for (int d4 = 0; d4 < 16; d4++) {
        float4 o = make_float4(acc[4*d4] * inv, acc[4*d4+1] * inv,
                               acc[4*d4+2] * inv, acc[4*d4+3] * inv);
        ((float4*)op)[d4] = o;
    }
}

// ---------------- launch ----------------------------------------------------
extern "C" void kernel_launch(void* const* d_in, const int* in_sizes, int n_in,
                              void* d_out, int out_size) {
    const float* queries = (const float*)d_in[0];
    const float* kv      = (const float*)d_in[1];
    const int*   qt_ids  = (const int*)d_in[2];
    const int*   kt_ids  = (const int*)d_in[3];
    const int*   pad     = (const int*)d_in[4];    // bool delivered as int32
    const float* Wq   = (const float*)d_in[5];
    const float* Wk   = (const float*)d_in[6];
    const float* Wv   = (const float*)d_in[7];
    const float* Wo   = (const float*)d_in[8];
    const float* qn_w = (const float*)d_in[9];
    const float* qn_b = (const float*)d_in[10];
    const float* kvn_w = (const float*)d_in[11];
    const float* kvn_b = (const float*)d_in[12];
    const float* on_w = (const float*)d_in[13];
    const float* on_b = (const float*)d_in[14];
    const float* tb   = (const float*)d_in[15];
    float* out = (float*)d_out;

    float *p_qn, *p_kvn, *p_q, *p_k, *p_v, *p_ctx, *p_o;
    cudaGetSymbolAddress((void**)&p_qn,  g_qn);
    cudaGetSymbolAddress((void**)&p_kvn, g_kvn);
    cudaGetSymbolAddress((void**)&p_q,   g_q);
    cudaGetSymbolAddress((void**)&p_k,   g_k);
    cudaGetSymbolAddress((void**)&p_v,   g_v);
    cudaGetSymbolAddress((void**)&p_ctx, g_ctx);
    cudaGetSymbolAddress((void**)&p_o,   g_o);

    // 1. LayerNorms
    ln_kernel<<<BATCH * NQ, 256>>>(queries, qn_w, qn_b, p_qn);
    ln_kernel<<<BATCH * NK, 256>>>(kv, kvn_w, kvn_b, p_kvn);

    // 2. projections  C = A @ W^T
    {
        dim3 gq(HID / 64, (BATCH * NQ) / 64);
        dim3 gk(HID / 64, (BATCH * NK) / 64);
        gemm_abt<<<gq, 256>>>(p_qn,  Wq, p_q, BATCH * NQ, HID, HID);
        gemm_abt<<<gk, 256>>>(p_kvn, Wk, p_k, BATCH * NK, HID, HID);
        gemm_abt<<<gk, 256>>>(p_kvn, Wv, p_v, BATCH * NK, HID, HID);
    }

    // 3. attention
    {
        dim3 ga(NQ / 128, HEADS, BATCH);
        attn_kernel<<<ga, 128>>>(qt_ids, kt_ids, pad, tb);
    }

    // 4. output projection
    {
        dim3 go(HID / 64, (BATCH * NQ) / 64);
        gemm_abt<<<go, 256>>>(p_ctx, Wo, p_o, BATCH * NQ, HID, HID);
    }

    // 5. residual + LN -> d_out
    res_ln_kernel<<<BATCH * NQ, 256>>>(queries, p_o, on_w, on_b, out);
}

// round 5
// speedup vs baseline: 1.7110x; 1.7110x over previous
#include <cuda_runtime.h>
#include <cuda_bf16.h>
#include <math.h>
#include <float.h>
#include <stdint.h>

#define BATCH 2
#define NQ    1024
#define NK    4096
#define HID   1024
#define HEADS 16
#define HD    64
#define LN_EPS 1e-5f

#define MQ (BATCH*NQ)   // 2048
#define MK (BATCH*NK)   // 8192

// ---------------- scratch (__device__ globals; no allocations allowed) ------
__device__ float g_q  [MQ*HID];
__device__ float g_k  [MK*HID];
__device__ float g_v  [MK*HID];
__device__ float g_ctx[MQ*HID];
__device__ float g_o  [MQ*HID];

__device__ __nv_bfloat16 g_qn_h [MQ*HID];
__device__ __nv_bfloat16 g_qn_l [MQ*HID];
__device__ __nv_bfloat16 g_kvn_h[MK*HID];
__device__ __nv_bfloat16 g_kvn_l[MK*HID];
__device__ __nv_bfloat16 g_ctx_h[MQ*HID];
__device__ __nv_bfloat16 g_ctx_l[MQ*HID];
__device__ __nv_bfloat16 g_wq_h[HID*HID], g_wq_l[HID*HID];
__device__ __nv_bfloat16 g_wk_h[HID*HID], g_wk_l[HID*HID];
__device__ __nv_bfloat16 g_wv_h[HID*HID], g_wv_l[HID*HID];
__device__ __nv_bfloat16 g_wo_h[HID*HID], g_wo_l[HID*HID];

// ---------------- small helpers ---------------------------------------------
__device__ __forceinline__ uint32_t smem_u32(const void* p) {
    uint32_t a;
    asm("{ .reg .u64 t; cvta.to.shared.u64 t, %1; cvt.u32.u64 %0, t; }" : "=r"(a) : "l"(p));
    return a;
}

__device__ __forceinline__ void split_bf16(float x, __nv_bfloat16& h, __nv_bfloat16& l) {
    h = __float2bfloat16(x);
    l = __float2bfloat16(x - __bfloat162float(h));
}

__device__ __forceinline__ float2 block_reduce2(float a, float b, float* sh) {
    #pragma unroll
    for (int o = 16; o; o >>= 1) {
        a += __shfl_xor_sync(0xffffffffu, a, o);
        b += __shfl_xor_sync(0xffffffffu, b, o);
    }
    int w = threadIdx.x >> 5;
    if ((threadIdx.x & 31) == 0) { sh[w] = a; sh[8 + w] = b; }
    __syncthreads();
    if (threadIdx.x == 0) {
        float sa = 0.f, sb = 0.f;
        #pragma unroll
        for (int i = 0; i < 8; i++) { sa += sh[i]; sb += sh[8 + i]; }
        sh[0] = sa; sh[8] = sb;
    }
    __syncthreads();
    return make_float2(sh[0], sh[8]);
}

#define CP_ASYNC16(dst, src) \
    asm volatile("cp.async.cg.shared.global [%0], [%1], 16;" :: "r"(dst), "l"(src))
#define CP_COMMIT() asm volatile("cp.async.commit_group;" ::: "memory")
#define CP_WAIT0()  asm volatile("cp.async.wait_group 0;" ::: "memory")
#define CP_WAIT1()  asm volatile("cp.async.wait_group 1;" ::: "memory")

__device__ __forceinline__ void ldsm4(uint32_t* r, uint32_t addr) {
    asm volatile("ldmatrix.sync.aligned.m8n8.x4.shared.b16 {%0,%1,%2,%3}, [%4];"
                 : "=r"(r[0]), "=r"(r[1]), "=r"(r[2]), "=r"(r[3]) : "r"(addr));
}

__device__ __forceinline__ void mma16816(float* c, const uint32_t* a, const uint32_t* b) {
    asm volatile(
        "mma.sync.aligned.m16n8k16.row.col.f32.bf16.bf16.f32 "
        "{%0,%1,%2,%3}, {%4,%5,%6,%7}, {%8,%9}, {%0,%1,%2,%3};"
        : "+f"(c[0]), "+f"(c[1]), "+f"(c[2]), "+f"(c[3])
        : "r"(a[0]), "r"(a[1]), "r"(a[2]), "r"(a[3]), "r"(b[0]), "r"(b[1]));
}

// ---------------- LayerNorm -> bf16 hi/lo split ------------------------------
__global__ void ln_split_kernel(const float* __restrict__ x,
                                const float* __restrict__ w,
                                const float* __restrict__ b,
                                __nv_bfloat16* __restrict__ oh,
                                __nv_bfloat16* __restrict__ ol) {
    __shared__ float sh[16];
    size_t row = blockIdx.x;
    float4 v = ((const float4*)(x + row * HID))[threadIdx.x];
    float s  = v.x + v.y + v.z + v.w;
    float s2 = v.x*v.x + v.y*v.y + v.z*v.z + v.w*v.w;
    float2 r = block_reduce2(s, s2, sh);
    float mean = r.x * (1.f / HID);
    float var  = r.y * (1.f / HID) - mean * mean;
    float rstd = rsqrtf(var + LN_EPS);
    float4 wv = ((const float4*)w)[threadIdx.x];
    float4 bv = ((const float4*)b)[threadIdx.x];
    float o0 = (v.x - mean) * rstd * wv.x + bv.x;
    float o1 = (v.y - mean) * rstd * wv.y + bv.y;
    float o2 = (v.z - mean) * rstd * wv.z + bv.z;
    float o3 = (v.w - mean) * rstd * wv.w + bv.w;
    __nv_bfloat16 h0,h1,h2,h3,l0,l1,l2,l3;
    split_bf16(o0,h0,l0); split_bf16(o1,h1,l1);
    split_bf16(o2,h2,l2); split_bf16(o3,h3,l3);
    __nv_bfloat162* ph = (__nv_bfloat162*)(oh + row * HID + threadIdx.x * 4);
    __nv_bfloat162* pl = (__nv_bfloat162*)(ol + row * HID + threadIdx.x * 4);
    ph[0] = __nv_bfloat162(h0, h1); ph[1] = __nv_bfloat162(h2, h3);
    pl[0] = __nv_bfloat162(l0, l1); pl[1] = __nv_bfloat162(l2, l3);
}

// ---------------- generic fp32 -> bf16 hi/lo split ---------------------------
__global__ void split_kernel(const float* __restrict__ x,
                             __nv_bfloat16* __restrict__ oh,
                             __nv_bfloat16* __restrict__ ol, int n4) {
    for (int i = blockIdx.x * blockDim.x + threadIdx.x; i < n4; i += gridDim.x * blockDim.x) {
        float4 v = ((const float4*)x)[i];
        __nv_bfloat16 h0,h1,h2,h3,l0,l1,l2,l3;
        split_bf16(v.x,h0,l0); split_bf16(v.y,h1,l1);
        split_bf16(v.z,h2,l2); split_bf16(v.w,h3,l3);
        __nv_bfloat162* ph = (__nv_bfloat162*)(oh + (size_t)i * 4);
        __nv_bfloat162* pl = (__nv_bfloat162*)(ol + (size_t)i * 4);
        ph[0] = __nv_bfloat162(h0, h1); ph[1] = __nv_bfloat162(h2, h3);
        pl[0] = __nv_bfloat162(l0, l1); pl[1] = __nv_bfloat162(l2, l3);
    }
}

// -------- residual + LayerNorm: out = LN(x + y) -----------------------------
__global__ void res_ln_kernel(const float* __restrict__ x,
                              const float* __restrict__ y,
                              const float* __restrict__ w,
                              const float* __restrict__ b,
                              float* __restrict__ out) {
    __shared__ float sh[16];
    size_t row = blockIdx.x;
    float4 v  = ((const float4*)(x + row * HID))[threadIdx.x];
    float4 yv = ((const float4*)(y + row * HID))[threadIdx.x];
    v.x += yv.x; v.y += yv.y; v.z += yv.z; v.w += yv.w;
    float s  = v.x + v.y + v.z + v.w;
    float s2 = v.x*v.x + v.y*v.y + v.z*v.z + v.w*v.w;
    float2 r = block_reduce2(s, s2, sh);
    float mean = r.x * (1.f / HID);
    float var  = r.y * (1.f / HID) - mean * mean;
    float rstd = rsqrtf(var + LN_EPS);
    float4 wv = ((const float4*)w)[threadIdx.x];
    float4 bv = ((const float4*)b)[threadIdx.x];
    float4 o;
    o.x = (v.x - mean) * rstd * wv.x + bv.x;
    o.y = (v.y - mean) * rstd * wv.y + bv.y;
    o.z = (v.z - mean) * rstd * wv.z + bv.z;
    o.w = (v.w - mean) * rstd * wv.w + bv.w;
    ((float4*)(out + row * HID))[threadIdx.x] = o;
}

// ================= HMMA bf16 split GEMM =====================================
// C[M,1024] = A[M,1024] @ B[1024,1024]^T, A/B pre-split bf16 hi/lo.
// CTA tile 128M x 64N, BK=64, 256 threads (8 warps, 4Mx2N), warp tile 32x32.
// smem: 2 stages x (Ah 16K | Al 16K | Bh 8K | Bl 8K) = 98304 B, cp.async pipe.

#define STG_AH 0
#define STG_AL 16384
#define STG_BH 32768
#define STG_BL 40960
#define STAGE_SZ 49152
#define GT_SMEM (2*STAGE_SZ)

__global__ void __launch_bounds__(256, 2) gemm_hmma(
    const __nv_bfloat16* __restrict__ Ah, const __nv_bfloat16* __restrict__ Al,
    const __nv_bfloat16* __restrict__ Bh, const __nv_bfloat16* __restrict__ Bl,
    float* __restrict__ C) {
    extern __shared__ char sm[];
    uint32_t sb = smem_u32(sm);
    int tid = threadIdx.x;
    int wid = tid >> 5, lane = tid & 31;
    int wm = wid >> 1, wn = wid & 1;
    int rowBase = blockIdx.y * 128;
    int colBase = blockIdx.x * 64;

    int q = lane >> 3, ln8 = lane & 7;

    float acc[2][4][4];
    #pragma unroll
    for (int i = 0; i < 2; i++)
        #pragma unroll
        for (int j = 0; j < 4; j++)
            #pragma unroll
            for (int r = 0; r < 4; r++) acc[i][j][r] = 0.f;

    // ---- async loader for one K-chunk into stage st ----
    auto load_chunk = [&](int c, int st) {
        int k0 = c * 64;
        uint32_t so = sb + st * STAGE_SZ;
        #pragma unroll
        for (int s = 0; s < 4; s++) {            // A hi + lo: 128 rows x 8 chunks
            int idx = tid + s * 256;
            int row = idx >> 3, ch = idx & 7;
            uint32_t off = (uint32_t)row * 128 + (uint32_t)((ch ^ (row & 7)) * 16);
            const __nv_bfloat16* sa = Ah + (size_t)(rowBase + row) * HID + k0 + ch * 8;
            const __nv_bfloat16* sl = Al + (size_t)(rowBase + row) * HID + k0 + ch * 8;
            CP_ASYNC16(so + STG_AH + off, sa);
            CP_ASYNC16(so + STG_AL + off, sl);
        }
        #pragma unroll
        for (int s = 0; s < 2; s++) {            // B hi + lo: 64 rows x 8 chunks
            int idx = tid + s * 256;
            int row = idx >> 3, ch = idx & 7;
            uint32_t off = (uint32_t)row * 128 + (uint32_t)((ch ^ (row & 7)) * 16);
            const __nv_bfloat16* sa = Bh + (size_t)(colBase + row) * HID + k0 + ch * 8;
            const __nv_bfloat16* sl = Bl + (size_t)(colBase + row) * HID + k0 + ch * 8;
            CP_ASYNC16(so + STG_BH + off, sa);
            CP_ASYNC16(so + STG_BL + off, sl);
        }
        CP_COMMIT();
    };

    load_chunk(0, 0);

    for (int c = 0; c < 16; c++) {
        if (c < 15) { load_chunk(c + 1, (c + 1) & 1); CP_WAIT1(); }
        else        { CP_WAIT0(); }
        __syncthreads();

        uint32_t stBase = sb + (c & 1) * STAGE_SZ;
        #pragma unroll
        for (int pass = 0; pass < 3; pass++) {
            uint32_t Ab = stBase + ((pass < 2) ? STG_AH : STG_AL);
            uint32_t Bb = stBase + ((pass == 1) ? STG_BL : STG_BH);
            #pragma unroll
            for (int ti = 0; ti < 4; ti++) {
                uint32_t af[2][4];
                #pragma unroll
                for (int mi = 0; mi < 2; mi++) {
                    int row = wm * 32 + mi * 16 + (q & 1) * 8 + ln8;
                    int ch = ti * 2 + (q >> 1);
                    ldsm4(af[mi], Ab + row * 128 + ((ch ^ (row & 7)) * 16));
                }
                uint32_t bf[2][4];
                #pragma unroll
                for (int g = 0; g < 2; g++) {
                    int row = wn * 32 + g * 16 + (q >> 1) * 8 + ln8;
                    int ch = ti * 2 + (q & 1);
                    ldsm4(bf[g], Bb + row * 128 + ((ch ^ (row & 7)) * 16));
                }
                #pragma unroll
                for (int mi = 0; mi < 2; mi++) {
                    mma16816(acc[mi][0], af[mi], &bf[0][0]);
                    mma16816(acc[mi][1], af[mi], &bf[0][2]);
                    mma16816(acc[mi][2], af[mi], &bf[1][0]);
                    mma16816(acc[mi][3], af[mi], &bf[1][2]);
                }
            }
        }
        __syncthreads();
    }

    // epilogue
    int r0 = rowBase + wm * 32 + (lane >> 2);
    int c0 = colBase + wn * 32 + (lane & 3) * 2;
    #pragma unroll
    for (int mi = 0; mi < 2; mi++) {
        #pragma unroll
        for (int ni = 0; ni < 4; ni++) {
            int rr = r0 + mi * 16;
            int cc = c0 + ni * 8;
            *(float2*)&C[(size_t)rr * HID + cc] = make_float2(acc[mi][ni][0], acc[mi][ni][1]);
            *(float2*)&C[(size_t)(rr + 8) * HID + cc] = make_float2(acc[mi][ni][2], acc[mi][ni][3]);
        }
    }
}

// ---------------- flash attention (fp32) -------------------------------------
__global__ void __launch_bounds__(128) attn_kernel(const int* __restrict__ qt_ids,
                                                   const int* __restrict__ kt_ids,
                                                   const int* __restrict__ pad,
                                                   const float* __restrict__ tb) {
    __shared__ float ks[64][64];
    __shared__ float vs[64][64];
    __shared__ float tbs[9];
    __shared__ int   kti[64];
    __shared__ int   msk[64];

    int b = blockIdx.z, h = blockIdx.y;
    int tid = threadIdx.x;
    int q = blockIdx.x * 128 + tid;
    if (tid < 9) tbs[tid] = tb[tid];

    float qv[64];
    const float* qp = g_q + ((size_t)(b * NQ + q)) * HID + h * HD;
    #pragma unroll
    for (int i = 0; i < 16; i++) {
        float4 t = ((const float4*)qp)[i];
        qv[4*i] = t.x; qv[4*i+1] = t.y; qv[4*i+2] = t.z; qv[4*i+3] = t.w;
    }
    int qrowt = qt_ids[q] * 3;

    float m = -1e30f, l = 0.f;
    float acc[64];
    #pragma unroll
    for (int d = 0; d < 64; d++) acc[d] = 0.f;

    for (int k0 = 0; k0 < NK; k0 += 64) {
        __syncthreads();
        const float* kg = g_k + ((size_t)(b * NK + k0)) * HID + h * HD;
        const float* vg = g_v + ((size_t)(b * NK + k0)) * HID + h * HD;
        for (int it = tid; it < 64 * 16; it += 128) {
            int j = it >> 4, d4 = it & 15;
            ((float4*)&ks[j][0])[d4] = ((const float4*)(kg + (size_t)j * HID))[d4];
            ((float4*)&vs[j][0])[d4] = ((const float4*)(vg + (size_t)j * HID))[d4];
        }
        if (tid < 64) {
            kti[tid] = kt_ids[k0 + tid];
            msk[tid] = pad[(size_t)b * NK + k0 + tid] ? 0 : 1;
        }
        __syncthreads();

        #pragma unroll 1
        for (int c = 0; c < 4; c++) {
            float s[16];
            float smax = -1e30f;
            #pragma unroll
            for (int j = 0; j < 16; j++) {
                int jj = c * 16 + j;
                float ds = 0.f;
                #pragma unroll
                for (int d4 = 0; d4 < 16; d4++) {
                    float4 kk = ((const float4*)&ks[jj][0])[d4];
                    ds += qv[4*d4]   * kk.x;
                    ds += qv[4*d4+1] * kk.y;
                    ds += qv[4*d4+2] * kk.z;
                    ds += qv[4*d4+3] * kk.w;
                }
                float sc = ds * 0.125f + tbs[qrowt + kti[jj]];
                if (msk[jj]) sc = -3.0e38f;
                s[j] = sc;
                smax = fmaxf(smax, sc);
            }
            if (smax > m) {
                float corr = __expf(m - smax);
                m = smax;
                l *= corr;
                #pragma unroll
                for (int d = 0; d < 64; d++) acc[d] *= corr;
            }
            #pragma unroll
            for (int j = 0; j < 16; j++) {
                float p = __expf(s[j] - m);
                l += p;
                int jj = c * 16 + j;
                #pragma unroll
                for (int d4 = 0; d4 < 16; d4++) {
                    float4 vv = ((const float4*)&vs[jj][0])[d4];
                    acc[4*d4]   += p * vv.x;
                    acc[4*d4+1] += p * vv.y;
                    acc[4*d4+2] += p * vv.z;
                    acc[4*d4+3] += p * vv.w;
                }
            }
        }
    }

    float inv = 1.f / l;
    float* op = g_ctx + ((size_t)(b * NQ + q)) * HID + h * HD;
    #pragma unroll
    for (int d4 = 0; d4 < 16; d4++) {
        float4 o = make_float4(acc[4*d4] * inv, acc[4*d4+1] * inv,
                               acc[4*d4+2] * inv, acc[4*d4+3] * inv);
        ((float4*)op)[d4] = o;
    }
}

// ---------------- launch ----------------------------------------------------
extern "C" void kernel_launch(void* const* d_in, const int* in_sizes, int n_in,
                              void* d_out, int out_size) {
    const float* queries = (const float*)d_in[0];
    const float* kv      = (const float*)d_in[1];
    const int*   qt_ids  = (const int*)d_in[2];
    const int*   kt_ids  = (const int*)d_in[3];
    const int*   pad     = (const int*)d_in[4];
    const float* Wq   = (const float*)d_in[5];
    const float* Wk   = (const float*)d_in[6];
    const float* Wv   = (const float*)d_in[7];
    const float* Wo   = (const float*)d_in[8];
    const float* qn_w = (const float*)d_in[9];
    const float* qn_b = (const float*)d_in[10];
    const float* kvn_w = (const float*)d_in[11];
    const float* kvn_b = (const float*)d_in[12];
    const float* on_w = (const float*)d_in[13];
    const float* on_b = (const float*)d_in[14];
    const float* tb   = (const float*)d_in[15];
    float* out = (float*)d_out;

    float *p_q, *p_k, *p_v, *p_ctx, *p_o;
    __nv_bfloat16 *p_qn_h, *p_qn_l, *p_kvn_h, *p_kvn_l, *p_ctx_h, *p_ctx_l;
    __nv_bfloat16 *p_wq_h, *p_wq_l, *p_wk_h, *p_wk_l, *p_wv_h, *p_wv_l, *p_wo_h, *p_wo_l;
    cudaGetSymbolAddress((void**)&p_q,   g_q);
    cudaGetSymbolAddress((void**)&p_k,   g_k);
    cudaGetSymbolAddress((void**)&p_v,   g_v);
    cudaGetSymbolAddress((void**)&p_ctx, g_ctx);
    cudaGetSymbolAddress((void**)&p_o,   g_o);
    cudaGetSymbolAddress((void**)&p_qn_h,  g_qn_h);
    cudaGetSymbolAddress((void**)&p_qn_l,  g_qn_l);
    cudaGetSymbolAddress((void**)&p_kvn_h, g_kvn_h);
    cudaGetSymbolAddress((void**)&p_kvn_l, g_kvn_l);
    cudaGetSymbolAddress((void**)&p_ctx_h, g_ctx_h);
    cudaGetSymbolAddress((void**)&p_ctx_l, g_ctx_l);
    cudaGetSymbolAddress((void**)&p_wq_h, g_wq_h);
    cudaGetSymbolAddress((void**)&p_wq_l, g_wq_l);
    cudaGetSymbolAddress((void**)&p_wk_h, g_wk_h);
    cudaGetSymbolAddress((void**)&p_wk_l, g_wk_l);
    cudaGetSymbolAddress((void**)&p_wv_h, g_wv_h);
    cudaGetSymbolAddress((void**)&p_wv_l, g_wv_l);
    cudaGetSymbolAddress((void**)&p_wo_h, g_wo_h);
    cudaGetSymbolAddress((void**)&p_wo_l, g_wo_l);

    static int smem_set = 0;
    if (!smem_set) {
        cudaFuncSetAttribute(gemm_hmma, cudaFuncAttributeMaxDynamicSharedMemorySize, GT_SMEM);
        smem_set = 1;
    }

    // 1. LN -> bf16 splits
    ln_split_kernel<<<MQ, 256>>>(queries, qn_w, qn_b, p_qn_h, p_qn_l);
    ln_split_kernel<<<MK, 256>>>(kv, kvn_w, kvn_b, p_kvn_h, p_kvn_l);

    // 2. weight splits
    split_kernel<<<512, 256>>>(Wq, p_wq_h, p_wq_l, HID * HID / 4);
    split_kernel<<<512, 256>>>(Wk, p_wk_h, p_wk_l, HID * HID / 4);
    split_kernel<<<512, 256>>>(Wv, p_wv_h, p_wv_l, HID * HID / 4);
    split_kernel<<<512, 256>>>(Wo, p_wo_h, p_wo_l, HID * HID / 4);

    // 3. projections via HMMA bf16-split GEMM
    {
        dim3 gq(HID / 64, MQ / 128);
        dim3 gk(HID / 64, MK / 128);
        gemm_hmma<<<gq, 256, GT_SMEM>>>(p_qn_h, p_qn_l, p_wq_h, p_wq_l, p_q);
        gemm_hmma<<<gk, 256, GT_SMEM>>>(p_kvn_h, p_kvn_l, p_wk_h, p_wk_l, p_k);
        gemm_hmma<<<gk, 256, GT_SMEM>>>(p_kvn_h, p_kvn_l, p_wv_h, p_wv_l, p_v);
    }

    // 4. attention (fp32)
    {
        dim3 ga(NQ / 128, HEADS, BATCH);
        attn_kernel<<<ga, 128>>>(qt_ids, kt_ids, pad, tb);
    }

    // 5. ctx split + output projection
    split_kernel<<<512, 256>>>(p_ctx, p_ctx_h, p_ctx_l, MQ * HID / 4);
    {
        dim3 go(HID / 64, MQ / 128);
        gemm_hmma<<<go, 256, GT_SMEM>>>(p_ctx_h, p_ctx_l, p_wo_h, p_wo_l, p_o);
    }

    // 6. residual + LN -> d_out
    res_ln_kernel<<<MQ, 256>>>(queries, p_o, on_w, on_b, out);
}

// round 6
// speedup vs baseline: 4.0792x; 2.3841x over previous
#include <cuda_runtime.h>
#include <cuda_bf16.h>
#include <math.h>
#include <float.h>
#include <stdint.h>

#define BATCH 2
#define NQ    1024
#define NK    4096
#define HID   1024
#define HEADS 16
#define HD    64
#define LN_EPS 1e-5f
#define LOG2E 1.4426950408889634f
#define QKSCALE (0.125f * LOG2E)

#define MQ (BATCH*NQ)   // 2048
#define MK (BATCH*NK)   // 8192

// ---------------- scratch (__device__ globals; no allocations allowed) ------
__device__ float g_q  [MQ*HID];
__device__ float g_k  [MK*HID];
__device__ float g_v  [MK*HID];
__device__ float g_ctx[MQ*HID];
__device__ float g_o  [MQ*HID];
__device__ float g_bias[BATCH*3*NK];

__device__ __nv_bfloat16 g_qn_h [MQ*HID];
__device__ __nv_bfloat16 g_qn_l [MQ*HID];
__device__ __nv_bfloat16 g_kvn_h[MK*HID];
__device__ __nv_bfloat16 g_kvn_l[MK*HID];
__device__ __nv_bfloat16 g_ctx_h[MQ*HID];
__device__ __nv_bfloat16 g_ctx_l[MQ*HID];
__device__ __nv_bfloat16 g_wq_h[HID*HID], g_wq_l[HID*HID];
__device__ __nv_bfloat16 g_wk_h[HID*HID], g_wk_l[HID*HID];
__device__ __nv_bfloat16 g_wv_h[HID*HID], g_wv_l[HID*HID];
__device__ __nv_bfloat16 g_wo_h[HID*HID], g_wo_l[HID*HID];
__device__ __nv_bfloat16 g_qs_h[MQ*HID], g_qs_l[MQ*HID];
__device__ __nv_bfloat16 g_ks_h[MK*HID], g_ks_l[MK*HID];
__device__ __nv_bfloat16 g_vt  [MK*HID];   // [(b*H+h)*64 + d][key]

// ---------------- small helpers ---------------------------------------------
__device__ __forceinline__ uint32_t smem_u32(const void* p) {
    uint32_t a;
    asm("{ .reg .u64 t; cvta.to.shared.u64 t, %1; cvt.u32.u64 %0, t; }" : "=r"(a) : "l"(p));
    return a;
}

__device__ __forceinline__ void split_bf16(float x, __nv_bfloat16& h, __nv_bfloat16& l) {
    h = __float2bfloat16(x);
    l = __float2bfloat16(x - __bfloat162float(h));
}

__device__ __forceinline__ float2 block_reduce2(float a, float b, float* sh) {
    #pragma unroll
    for (int o = 16; o; o >>= 1) {
        a += __shfl_xor_sync(0xffffffffu, a, o);
        b += __shfl_xor_sync(0xffffffffu, b, o);
    }
    int w = threadIdx.x >> 5;
    if ((threadIdx.x & 31) == 0) { sh[w] = a; sh[8 + w] = b; }
    __syncthreads();
    if (threadIdx.x == 0) {
        float sa = 0.f, sb = 0.f;
        #pragma unroll
        for (int i = 0; i < 8; i++) { sa += sh[i]; sb += sh[8 + i]; }
        sh[0] = sa; sh[8] = sb;
    }
    __syncthreads();
    return make_float2(sh[0], sh[8]);
}

#define CP_ASYNC16(dst, src) \
    asm volatile("cp.async.cg.shared.global [%0], [%1], 16;" :: "r"(dst), "l"(src))
#define CP_COMMIT() asm volatile("cp.async.commit_group;" ::: "memory")
#define CP_WAIT0()  asm volatile("cp.async.wait_group 0;" ::: "memory")
#define CP_WAIT1()  asm volatile("cp.async.wait_group 1;" ::: "memory")

__device__ __forceinline__ void ldsm4(uint32_t* r, uint32_t addr) {
    asm volatile("ldmatrix.sync.aligned.m8n8.x4.shared.b16 {%0,%1,%2,%3}, [%4];"
                 : "=r"(r[0]), "=r"(r[1]), "=r"(r[2]), "=r"(r[3]) : "r"(addr));
}
__device__ __forceinline__ void ldsm2(uint32_t* r, uint32_t addr) {
    asm volatile("ldmatrix.sync.aligned.m8n8.x2.shared.b16 {%0,%1}, [%2];"
                 : "=r"(r[0]), "=r"(r[1]) : "r"(addr));
}

__device__ __forceinline__ void mma16816(float* c, const uint32_t* a, const uint32_t* b) {
    asm volatile(
        "mma.sync.aligned.m16n8k16.row.col.f32.bf16.bf16.f32 "
        "{%0,%1,%2,%3}, {%4,%5,%6,%7}, {%8,%9}, {%0,%1,%2,%3};"
        : "+f"(c[0]), "+f"(c[1]), "+f"(c[2]), "+f"(c[3])
        : "r"(a[0]), "r"(a[1]), "r"(a[2]), "r"(a[3]), "r"(b[0]), "r"(b[1]));
}

// fast 2^x for x <= 0 (clamped at -60), ~1e-6 rel err, FMA-pipe only
__device__ __forceinline__ float exp2m(float x) {
    x = fmaxf(x, -60.f);
    float fl = floorf(x);
    float f = x - fl;
    float p = 1.5400290440989764e-4f;
    p = fmaf(p, f, 1.3333558146428443e-3f);
    p = fmaf(p, f, 9.6181291076284772e-3f);
    p = fmaf(p, f, 5.5504108664821580e-2f);
    p = fmaf(p, f, 2.4022650695910072e-1f);
    p = fmaf(p, f, 6.9314718055994531e-1f);
    p = fmaf(p, f, 1.0f);
    return __int_as_float(((int)fl + 127) << 23) * p;
}

// ---------------- LayerNorm -> bf16 hi/lo split ------------------------------
__global__ void ln_split_kernel(const float* __restrict__ x,
                                const float* __restrict__ w,
                                const float* __restrict__ b,
                                __nv_bfloat16* __restrict__ oh,
                                __nv_bfloat16* __restrict__ ol) {
    __shared__ float sh[16];
    size_t row = blockIdx.x;
    float4 v = ((const float4*)(x + row * HID))[threadIdx.x];
    float s  = v.x + v.y + v.z + v.w;
    float s2 = v.x*v.x + v.y*v.y + v.z*v.z + v.w*v.w;
    float2 r = block_reduce2(s, s2, sh);
    float mean = r.x * (1.f / HID);
    float var  = r.y * (1.f / HID) - mean * mean;
    float rstd = rsqrtf(var + LN_EPS);
    float4 wv = ((const float4*)w)[threadIdx.x];
    float4 bv = ((const float4*)b)[threadIdx.x];
    float o0 = (v.x - mean) * rstd * wv.x + bv.x;
    float o1 = (v.y - mean) * rstd * wv.y + bv.y;
    float o2 = (v.z - mean) * rstd * wv.z + bv.z;
    float o3 = (v.w - mean) * rstd * wv.w + bv.w;
    __nv_bfloat16 h0,h1,h2,h3,l0,l1,l2,l3;
    split_bf16(o0,h0,l0); split_bf16(o1,h1,l1);
    split_bf16(o2,h2,l2); split_bf16(o3,h3,l3);
    __nv_bfloat162* ph = (__nv_bfloat162*)(oh + row * HID + threadIdx.x * 4);
    __nv_bfloat162* pl = (__nv_bfloat162*)(ol + row * HID + threadIdx.x * 4);
    ph[0] = __nv_bfloat162(h0, h1); ph[1] = __nv_bfloat162(h2, h3);
    pl[0] = __nv_bfloat162(l0, l1); pl[1] = __nv_bfloat162(l2, l3);
}

// ---------------- generic fp32 -> bf16 hi/lo split (with scale) --------------
__global__ void split_kernel(const float* __restrict__ x,
                             __nv_bfloat16* __restrict__ oh,
                             __nv_bfloat16* __restrict__ ol, int n4, float sc) {
    for (int i = blockIdx.x * blockDim.x + threadIdx.x; i < n4; i += gridDim.x * blockDim.x) {
        float4 v = ((const float4*)x)[i];
        v.x *= sc; v.y *= sc; v.z *= sc; v.w *= sc;
        __nv_bfloat16 h0,h1,h2,h3,l0,l1,l2,l3;
        split_bf16(v.x,h0,l0); split_bf16(v.y,h1,l1);
        split_bf16(v.z,h2,l2); split_bf16(v.w,h3,l3);
        __nv_bfloat162* ph = (__nv_bfloat162*)(oh + (size_t)i * 4);
        __nv_bfloat162* pl = (__nv_bfloat162*)(ol + (size_t)i * 4);
        ph[0] = __nv_bfloat162(h0, h1); ph[1] = __nv_bfloat162(h2, h3);
        pl[0] = __nv_bfloat162(l0, l1); pl[1] = __nv_bfloat162(l2, l3);
    }
}

// ---------------- V transpose: g_v fp32 -> g_vt bf16 [(b,h,d)][key] ----------
__global__ void vt_kernel(const float* __restrict__ v, __nv_bfloat16* __restrict__ vt) {
    __shared__ float tile[32][33];
    int b = blockIdx.z;
    int k0 = blockIdx.x * 32, d0 = blockIdx.y * 32;
    for (int i = threadIdx.y; i < 32; i += 8)
        tile[i][threadIdx.x] = v[(size_t)(b * NK + k0 + i) * HID + d0 + threadIdx.x];
    __syncthreads();
    for (int i = threadIdx.y; i < 32; i += 8) {
        int d = d0 + i;
        int h = d >> 6, dd = d & 63;
        vt[(size_t)((b * HEADS + h) * 64 + dd) * NK + k0 + threadIdx.x] =
            __float2bfloat16(tile[threadIdx.x][i]);
    }
}

// ---------------- bias precompute: [b][qt][key], log2 domain, mask fused -----
__global__ void bias_kernel(const int* __restrict__ kt, const int* __restrict__ pad,
                            const float* __restrict__ tb, float* __restrict__ out) {
    int i = blockIdx.x * blockDim.x + threadIdx.x;
    if (i >= BATCH * NK) return;
    int b = i / NK, k = i % NK;
    float t0, t1, t2;
    if (pad[i]) {
        int c = kt[k];
        t0 = tb[c] * LOG2E; t1 = tb[3 + c] * LOG2E; t2 = tb[6 + c] * LOG2E;
    } else {
        t0 = t1 = t2 = -1e30f;
    }
    out[(size_t)(b * 3 + 0) * NK + k] = t0;
    out[(size_t)(b * 3 + 1) * NK + k] = t1;
    out[(size_t)(b * 3 + 2) * NK + k] = t2;
}

// -------- residual + LayerNorm: out = LN(x + y) -----------------------------
__global__ void res_ln_kernel(const float* __restrict__ x,
                              const float* __restrict__ y,
                              const float* __restrict__ w,
                              const float* __restrict__ b,
                              float* __restrict__ out) {
    __shared__ float sh[16];
    size_t row = blockIdx.x;
    float4 v  = ((const float4*)(x + row * HID))[threadIdx.x];
    float4 yv = ((const float4*)(y + row * HID))[threadIdx.x];
    v.x += yv.x; v.y += yv.y; v.z += yv.z; v.w += yv.w;
    float s  = v.x + v.y + v.z + v.w;
    float s2 = v.x*v.x + v.y*v.y + v.z*v.z + v.w*v.w;
    float2 r = block_reduce2(s, s2, sh);
    float mean = r.x * (1.f / HID);
    float var  = r.y * (1.f / HID) - mean * mean;
    float rstd = rsqrtf(var + LN_EPS);
    float4 wv = ((const float4*)w)[threadIdx.x];
    float4 bv = ((const float4*)b)[threadIdx.x];
    float4 o;
    o.x = (v.x - mean) * rstd * wv.x + bv.x;
    o.y = (v.y - mean) * rstd * wv.y + bv.y;
    o.z = (v.z - mean) * rstd * wv.z + bv.z;
    o.w = (v.w - mean) * rstd * wv.w + bv.w;
    ((float4*)(out + row * HID))[threadIdx.x] = o;
}

// ================= HMMA bf16 split GEMM (proven in R5) ======================
#define STG_AH 0
#define STG_AL 16384
#define STG_BH 32768
#define STG_BL 40960
#define STAGE_SZ 49152
#define GT_SMEM (2*STAGE_SZ)

__global__ void __launch_bounds__(256, 2) gemm_hmma(
    const __nv_bfloat16* __restrict__ Ah, const __nv_bfloat16* __restrict__ Al,
    const __nv_bfloat16* __restrict__ Bh, const __nv_bfloat16* __restrict__ Bl,
    float* __restrict__ C) {
    extern __shared__ char sm[];
    uint32_t sb = smem_u32(sm);
    int tid = threadIdx.x;
    int wid = tid >> 5, lane = tid & 31;
    int wm = wid >> 1, wn = wid & 1;
    int rowBase = blockIdx.y * 128;
    int colBase = blockIdx.x * 64;
    int q = lane >> 3, ln8 = lane & 7;

    float acc[2][4][4];
    #pragma unroll
    for (int i = 0; i < 2; i++)
        #pragma unroll
        for (int j = 0; j < 4; j++)
            #pragma unroll
            for (int r = 0; r < 4; r++) acc[i][j][r] = 0.f;

    auto load_chunk = [&](int c, int st) {
        int k0 = c * 64;
        uint32_t so = sb + st * STAGE_SZ;
        #pragma unroll
        for (int s = 0; s < 4; s++) {
            int idx = tid + s * 256;
            int row = idx >> 3, ch = idx & 7;
            uint32_t off = (uint32_t)row * 128 + (uint32_t)((ch ^ (row & 7)) * 16);
            CP_ASYNC16(so + STG_AH + off, Ah + (size_t)(rowBase + row) * HID + k0 + ch * 8);
            CP_ASYNC16(so + STG_AL + off, Al + (size_t)(rowBase + row) * HID + k0 + ch * 8);
        }
        #pragma unroll
        for (int s = 0; s < 2; s++) {
            int idx = tid + s * 256;
            int row = idx >> 3, ch = idx & 7;
            uint32_t off = (uint32_t)row * 128 + (uint32_t)((ch ^ (row & 7)) * 16);
            CP_ASYNC16(so + STG_BH + off, Bh + (size_t)(colBase + row) * HID + k0 + ch * 8);
            CP_ASYNC16(so + STG_BL + off, Bl + (size_t)(colBase + row) * HID + k0 + ch * 8);
        }
        CP_COMMIT();
    };

    load_chunk(0, 0);

    for (int c = 0; c < 16; c++) {
        if (c < 15) { load_chunk(c + 1, (c + 1) & 1); CP_WAIT1(); }
        else        { CP_WAIT0(); }
        __syncthreads();

        uint32_t stBase = sb + (c & 1) * STAGE_SZ;
        #pragma unroll
        for (int pass = 0; pass < 3; pass++) {
            uint32_t Ab = stBase + ((pass < 2) ? STG_AH : STG_AL);
            uint32_t Bb = stBase + ((pass == 1) ? STG_BL : STG_BH);
            #pragma unroll
            for (int ti = 0; ti < 4; ti++) {
                uint32_t af[2][4];
                #pragma unroll
                for (int mi = 0; mi < 2; mi++) {
                    int row = wm * 32 + mi * 16 + (q & 1) * 8 + ln8;
                    int ch = ti * 2 + (q >> 1);
                    ldsm4(af[mi], Ab + row * 128 + ((ch ^ (row & 7)) * 16));
                }
                uint32_t bf[2][4];
                #pragma unroll
                for (int g = 0; g < 2; g++) {
                    int row = wn * 32 + g * 16 + (q >> 1) * 8 + ln8;
                    int ch = ti * 2 + (q & 1);
                    ldsm4(bf[g], Bb + row * 128 + ((ch ^ (row & 7)) * 16));
                }
                #pragma unroll
                for (int mi = 0; mi < 2; mi++) {
                    mma16816(acc[mi][0], af[mi], &bf[0][0]);
                    mma16816(acc[mi][1], af[mi], &bf[0][2]);
                    mma16816(acc[mi][2], af[mi], &bf[1][0]);
                    mma16816(acc[mi][3], af[mi], &bf[1][2]);
                }
            }
        }
        __syncthreads();
    }

    int r0 = rowBase + wm * 32 + (lane >> 2);
    int c0 = colBase + wn * 32 + (lane & 3) * 2;
    #pragma unroll
    for (int mi = 0; mi < 2; mi++) {
        #pragma unroll
        for (int ni = 0; ni < 4; ni++) {
            int rr = r0 + mi * 16;
            int cc = c0 + ni * 8;
            *(float2*)&C[(size_t)rr * HID + cc] = make_float2(acc[mi][ni][0], acc[mi][ni][1]);
            *(float2*)&C[(size_t)(rr + 8) * HID + cc] = make_float2(acc[mi][ni][2], acc[mi][ni][3]);
        }
    }
}

// ================= HMMA flash attention =====================================
// grid (NQ/64, HEADS, BATCH), 128 threads (4 warps, warp = 16 q-rows).
// smem: Qh 8K | Ql 8K | 2 stages x (Kh 8K | Kl 8K | VT 8K | bias 1K)
#define AS_QH 0
#define AS_QL 8192
#define AS_STG 16384
#define AS_KH 0
#define AS_KL 8192
#define AS_VT 16384
#define AS_BIAS 24576
#define AS_STGSZ 25600
#define AT_SMEM (AS_STG + 2*AS_STGSZ)   // 67584

__global__ void __launch_bounds__(128) attn_hmma(
    const int* __restrict__ qt_ids,
    const __nv_bfloat16* __restrict__ Qh, const __nv_bfloat16* __restrict__ Ql,
    const __nv_bfloat16* __restrict__ Kh, const __nv_bfloat16* __restrict__ Kl,
    const __nv_bfloat16* __restrict__ Vt,
    const float* __restrict__ biasg,
    float* __restrict__ ctx) {
    extern __shared__ char sm[];
    uint32_t sb = smem_u32(sm);
    int tid = threadIdx.x, w = tid >> 5, lane = tid & 31;
    int q0 = blockIdx.x * 64, h = blockIdx.y, b = blockIdx.z;
    int group = lane >> 2, qp = lane & 3;

    // load Q tile (hi/lo) into swizzled smem
    #pragma unroll
    for (int s = 0; s < 4; s++) {
        int idx = tid + s * 128;
        int r = idx >> 3, ch = idx & 7;
        size_t go = (size_t)(b * NQ + q0 + r) * HID + h * 64 + ch * 8;
        uint32_t off = (uint32_t)r * 128 + (uint32_t)((ch ^ (r & 7)) * 16);
        *(uint4*)(sm + AS_QH + off) = *(const uint4*)(Qh + go);
        *(uint4*)(sm + AS_QL + off) = *(const uint4*)(Ql + go);
    }

    auto load_stage = [&](int t, int st) {
        int k0 = t * 64;
        uint32_t so = sb + AS_STG + st * AS_STGSZ;
        #pragma unroll
        for (int s = 0; s < 12; s++) {
            int idx = tid + s * 128;
            int m = idx >> 9;
            int rc = idx & 511;
            int r = rc >> 3, ch = rc & 7;
            uint32_t off = so + m * 8192 + (uint32_t)r * 128 + (uint32_t)((ch ^ (r & 7)) * 16);
            const __nv_bfloat16* src;
            if (m == 0)      src = Kh + (size_t)(b * NK + k0 + r) * HID + h * 64 + ch * 8;
            else if (m == 1) src = Kl + (size_t)(b * NK + k0 + r) * HID + h * 64 + ch * 8;
            else             src = Vt + (size_t)((b * HEADS + h) * 64 + r) * NK + k0 + ch * 8;
            CP_ASYNC16(off, src);
        }
        if (tid < 48) {
            int qt = tid >> 4, j = tid & 15;
            CP_ASYNC16(so + AS_BIAS + qt * 256 + j * 16,
                       biasg + (size_t)(b * 3 + qt) * NK + k0 + j * 4);
        }
        CP_COMMIT();
    };

    load_stage(0, 0);
    __syncthreads();

    // Q fragments (held in registers for whole kernel)
    uint32_t QHf[4][4], QLf[4][4];
    #pragma unroll
    for (int c2 = 0; c2 < 4; c2++) {
        int r = w * 16 + (lane & 15);
        int ch = c2 * 2 + (lane >> 4);
        uint32_t off = (uint32_t)r * 128 + (uint32_t)((ch ^ (r & 7)) * 16);
        ldsm4(QHf[c2], sb + AS_QH + off);
        ldsm4(QLf[c2], sb + AS_QL + off);
    }
    int qtA = qt_ids[q0 + w * 16 + group];
    int qtB = qt_ids[q0 + w * 16 + group + 8];

    float acc[8][4];
    #pragma unroll
    for (int i = 0; i < 8; i++)
        #pragma unroll
        for (int j = 0; j < 4; j++) acc[i][j] = 0.f;
    float mA = -1e30f, mB = -1e30f, lA = 0.f, lB = 0.f;

    for (int t = 0; t < NK / 64; t++) {
        if (t < NK / 64 - 1) { load_stage(t + 1, (t + 1) & 1); CP_WAIT1(); }
        else                 { CP_WAIT0(); }
        __syncthreads();
        uint32_t st = sb + AS_STG + (t & 1) * AS_STGSZ;
        char*    stc = sm + AS_STG + (t & 1) * AS_STGSZ;

        // ---- S = Q K^T (3-term split, log2 domain) ----
        float S[8][4];
        #pragma unroll
        for (int nt = 0; nt < 8; nt++) {
            S[nt][0] = S[nt][1] = S[nt][2] = S[nt][3] = 0.f;
            uint32_t bh[4][2], bl[4][2];
            int krow = nt * 8 + (lane & 7);
            int khalf = (lane >> 3) & 1;
            #pragma unroll
            for (int c2 = 0; c2 < 4; c2++) {
                int ch = c2 * 2 + khalf;
                uint32_t off = (uint32_t)krow * 128 + (uint32_t)((ch ^ (krow & 7)) * 16);
                ldsm2(bh[c2], st + AS_KH + off);
                ldsm2(bl[c2], st + AS_KL + off);
            }
            #pragma unroll
            for (int c2 = 0; c2 < 4; c2++) {
                mma16816(S[nt], QHf[c2], bh[c2]);
                mma16816(S[nt], QLf[c2], bh[c2]);
                mma16816(S[nt], QHf[c2], bl[c2]);
            }
        }

        // ---- bias + row max ----
        const float* bA = (const float*)(stc + AS_BIAS) + qtA * 64;
        const float* bB = (const float*)(stc + AS_BIAS) + qtB * 64;
        float mxA = -1e30f, mxB = -1e30f;
        #pragma unroll
        for (int nt = 0; nt < 8; nt++) {
            float2 vA = *(const float2*)(bA + nt * 8 + qp * 2);
            float2 vB = *(const float2*)(bB + nt * 8 + qp * 2);
            S[nt][0] += vA.x; S[nt][1] += vA.y;
            S[nt][2] += vB.x; S[nt][3] += vB.y;
            mxA = fmaxf(mxA, fmaxf(S[nt][0], S[nt][1]));
            mxB = fmaxf(mxB, fmaxf(S[nt][2], S[nt][3]));
        }
        mxA = fmaxf(mxA, __shfl_xor_sync(0xffffffffu, mxA, 1));
        mxA = fmaxf(mxA, __shfl_xor_sync(0xffffffffu, mxA, 2));
        mxB = fmaxf(mxB, __shfl_xor_sync(0xffffffffu, mxB, 1));
        mxB = fmaxf(mxB, __shfl_xor_sync(0xffffffffu, mxB, 2));

        float mnA = fmaxf(mA, mxA), mnB = fmaxf(mB, mxB);
        float cA = exp2m(mA - mnA), cB = exp2m(mB - mnB);
        mA = mnA; mB = mnB;

        // ---- p = 2^(s-m), pack to bf16 A-frags ----
        float psA = 0.f, psB = 0.f;
        uint32_t P[4][4];
        #pragma unroll
        for (int kc = 0; kc < 4; kc++) {
            int t0 = kc * 2, t1 = kc * 2 + 1;
            float p00 = exp2m(S[t0][0] - mnA), p01 = exp2m(S[t0][1] - mnA);
            float p02 = exp2m(S[t0][2] - mnB), p03 = exp2m(S[t0][3] - mnB);
            float p10 = exp2m(S[t1][0] - mnA), p11 = exp2m(S[t1][1] - mnA);
            float p12 = exp2m(S[t1][2] - mnB), p13 = exp2m(S[t1][3] - mnB);
            psA += p00 + p01 + p10 + p11;
            psB += p02 + p03 + p12 + p13;
            __nv_bfloat162 t;
            t = __floats2bfloat162_rn(p00, p01); P[kc][0] = *(uint32_t*)&t;
            t = __floats2bfloat162_rn(p02, p03); P[kc][1] = *(uint32_t*)&t;
            t = __floats2bfloat162_rn(p10, p11); P[kc][2] = *(uint32_t*)&t;
            t = __floats2bfloat162_rn(p12, p13); P[kc][3] = *(uint32_t*)&t;
        }
        psA += __shfl_xor_sync(0xffffffffu, psA, 1);
        psA += __shfl_xor_sync(0xffffffffu, psA, 2);
        psB += __shfl_xor_sync(0xffffffffu, psB, 1);
        psB += __shfl_xor_sync(0xffffffffu, psB, 2);
        lA = lA * cA + psA;
        lB = lB * cB + psB;

        #pragma unroll
        for (int td = 0; td < 8; td++) {
            acc[td][0] *= cA; acc[td][1] *= cA;
            acc[td][2] *= cB; acc[td][3] *= cB;
        }

        // ---- acc += P @ V  (V^T tiles, same ldmatrix pattern) ----
        #pragma unroll
        for (int kc = 0; kc < 4; kc++) {
            #pragma unroll
            for (int td = 0; td < 8; td++) {
                uint32_t bv[2];
                int drow = td * 8 + (lane & 7);
                int ch = kc * 2 + ((lane >> 3) & 1);
                uint32_t off = (uint32_t)drow * 128 + (uint32_t)((ch ^ (drow & 7)) * 16);
                ldsm2(bv, st + AS_VT + off);
                mma16816(acc[td], P[kc], bv);
            }
        }
        __syncthreads();
    }

    float iA = 1.f / lA, iB = 1.f / lB;
    int rowA = q0 + w * 16 + group, rowB = rowA + 8;
    #pragma unroll
    for (int td = 0; td < 8; td++) {
        int col = h * 64 + td * 8 + qp * 2;
        *(float2*)&ctx[(size_t)(b * NQ + rowA) * HID + col] =
            make_float2(acc[td][0] * iA, acc[td][1] * iA);
        *(float2*)&ctx[(size_t)(b * NQ + rowB) * HID + col] =
            make_float2(acc[td][2] * iB, acc[td][3] * iB);
    }
}

// ---------------- launch ----------------------------------------------------
extern "C" void kernel_launch(void* const* d_in, const int* in_sizes, int n_in,
                              void* d_out, int out_size) {
    const float* queries = (const float*)d_in[0];
    const float* kv      = (const float*)d_in[1];
    const int*   qt_ids  = (const int*)d_in[2];
    const int*   kt_ids  = (const int*)d_in[3];
    const int*   pad     = (const int*)d_in[4];
    const float* Wq   = (const float*)d_in[5];
    const float* Wk   = (const float*)d_in[6];
    const float* Wv   = (const float*)d_in[7];
    const float* Wo   = (const float*)d_in[8];
    const float* qn_w = (const float*)d_in[9];
    const float* qn_b = (const float*)d_in[10];
    const float* kvn_w = (const float*)d_in[11];
    const float* kvn_b = (const float*)d_in[12];
    const float* on_w = (const float*)d_in[13];
    const float* on_b = (const float*)d_in[14];
    const float* tb   = (const float*)d_in[15];
    float* out = (float*)d_out;

    float *p_q, *p_k, *p_v, *p_ctx, *p_o, *p_bias;
    __nv_bfloat16 *p_qn_h, *p_qn_l, *p_kvn_h, *p_kvn_l, *p_ctx_h, *p_ctx_l;
    __nv_bfloat16 *p_wq_h, *p_wq_l, *p_wk_h, *p_wk_l, *p_wv_h, *p_wv_l, *p_wo_h, *p_wo_l;
    __nv_bfloat16 *p_qs_h, *p_qs_l, *p_ks_h, *p_ks_l, *p_vt;
    cudaGetSymbolAddress((void**)&p_q,   g_q);
    cudaGetSymbolAddress((void**)&p_k,   g_k);
    cudaGetSymbolAddress((void**)&p_v,   g_v);
    cudaGetSymbolAddress((void**)&p_ctx, g_ctx);
    cudaGetSymbolAddress((void**)&p_o,   g_o);
    cudaGetSymbolAddress((void**)&p_bias, g_bias);
    cudaGetSymbolAddress((void**)&p_qn_h,  g_qn_h);
    cudaGetSymbolAddress((void**)&p_qn_l,  g_qn_l);
    cudaGetSymbolAddress((void**)&p_kvn_h, g_kvn_h);
    cudaGetSymbolAddress((void**)&p_kvn_l, g_kvn_l);
    cudaGetSymbolAddress((void**)&p_ctx_h, g_ctx_h);
    cudaGetSymbolAddress((void**)&p_ctx_l, g_ctx_l);
    cudaGetSymbolAddress((void**)&p_wq_h, g_wq_h);
    cudaGetSymbolAddress((void**)&p_wq_l, g_wq_l);
    cudaGetSymbolAddress((void**)&p_wk_h, g_wk_h);
    cudaGetSymbolAddress((void**)&p_wk_l, g_wk_l);
    cudaGetSymbolAddress((void**)&p_wv_h, g_wv_h);
    cudaGetSymbolAddress((void**)&p_wv_l, g_wv_l);
    cudaGetSymbolAddress((void**)&p_wo_h, g_wo_h);
    cudaGetSymbolAddress((void**)&p_wo_l, g_wo_l);
    cudaGetSymbolAddress((void**)&p_qs_h, g_qs_h);
    cudaGetSymbolAddress((void**)&p_qs_l, g_qs_l);
    cudaGetSymbolAddress((void**)&p_ks_h, g_ks_h);
    cudaGetSymbolAddress((void**)&p_ks_l, g_ks_l);
    cudaGetSymbolAddress((void**)&p_vt,   g_vt);

    static int attr_set = 0;
    if (!attr_set) {
        cudaFuncSetAttribute(gemm_hmma, cudaFuncAttributeMaxDynamicSharedMemorySize, GT_SMEM);
        cudaFuncSetAttribute(attn_hmma, cudaFuncAttributeMaxDynamicSharedMemorySize, AT_SMEM);
        attr_set = 1;
    }

    // 1. LN -> bf16 splits
    ln_split_kernel<<<MQ, 256>>>(queries, qn_w, qn_b, p_qn_h, p_qn_l);
    ln_split_kernel<<<MK, 256>>>(kv, kvn_w, kvn_b, p_kvn_h, p_kvn_l);

    // 2. weight splits
    split_kernel<<<512, 256>>>(Wq, p_wq_h, p_wq_l, HID * HID / 4, 1.f);
    split_kernel<<<512, 256>>>(Wk, p_wk_h, p_wk_l, HID * HID / 4, 1.f);
    split_kernel<<<512, 256>>>(Wv, p_wv_h, p_wv_l, HID * HID / 4, 1.f);
    split_kernel<<<512, 256>>>(Wo, p_wo_h, p_wo_l, HID * HID / 4, 1.f);

    // 3. projections
    {
        dim3 gq(HID / 64, MQ / 128);
        dim3 gk(HID / 64, MK / 128);
        gemm_hmma<<<gq, 256, GT_SMEM>>>(p_qn_h, p_qn_l, p_wq_h, p_wq_l, p_q);
        gemm_hmma<<<gk, 256, GT_SMEM>>>(p_kvn_h, p_kvn_l, p_wk_h, p_wk_l, p_k);
        gemm_hmma<<<gk, 256, GT_SMEM>>>(p_kvn_h, p_kvn_l, p_wv_h, p_wv_l, p_v);
    }

    // 4. attention precompute: Q scaled split, K split, V transpose, bias table
    split_kernel<<<512, 256>>>(p_q, p_qs_h, p_qs_l, MQ * HID / 4, QKSCALE);
    split_kernel<<<512, 256>>>(p_k, p_ks_h, p_ks_l, MK * HID / 4, 1.f);
    {
        dim3 gv(NK / 32, HID / 32, BATCH);
        vt_kernel<<<gv, dim3(32, 8)>>>(p_v, p_vt);
    }
    bias_kernel<<<(BATCH * NK + 255) / 256, 256>>>(kt_ids, pad, tb, p_bias);

    // 5. flash attention (HMMA)
    {
        dim3 ga(NQ / 64, HEADS, BATCH);
        attn_hmma<<<ga, 128, AT_SMEM>>>(qt_ids, p_qs_h, p_qs_l, p_ks_h, p_ks_l,
                                        p_vt, p_bias, p_ctx);
    }

    // 6. ctx split + output projection
    split_kernel<<<512, 256>>>(p_ctx, p_ctx_h, p_ctx_l, MQ * HID / 4, 1.f);
    {
        dim3 go(HID / 64, MQ / 128);
        gemm_hmma<<<go, 256, GT_SMEM>>>(p_ctx_h, p_ctx_l, p_wo_h, p_wo_l, p_o);
    }

    // 7. residual + LN -> d_out
    res_ln_kernel<<<MQ, 256>>>(queries, p_o, on_w, on_b, out);
}

// round 7
// speedup vs baseline: 6.3954x; 1.5678x over previous
#include <cuda_runtime.h>
#include <cuda_bf16.h>
#include <math.h>
#include <float.h>
#include <stdint.h>

#define BATCH 2
#define NQ    1024
#define NK    4096
#define HID   1024
#define HEADS 16
#define HD    64
#define LN_EPS 1e-5f
#define LOG2E 1.4426950408889634f
#define QKSCALE (0.125f * LOG2E)
#define M0    32.0f

#define MQ (BATCH*NQ)   // 2048
#define MK (BATCH*NK)   // 8192

// ---------------- scratch (__device__ globals; no allocations allowed) ------
__device__ float g_q  [MQ*HID];
__device__ float g_k  [MK*HID];
__device__ float g_v  [MK*HID];
__device__ float g_ctx[MQ*HID];
__device__ float g_o  [MQ*HID];
__device__ float g_bias[BATCH*3*NK];
__device__ int   g_nv[BATCH];
__device__ int   g_cidx[BATCH*NK];

__device__ __nv_bfloat16 g_qn_h [MQ*HID];
__device__ __nv_bfloat16 g_qn_l [MQ*HID];
__device__ __nv_bfloat16 g_kvn_h[MK*HID];
__device__ __nv_bfloat16 g_kvn_l[MK*HID];
__device__ __nv_bfloat16 g_ctx_h[MQ*HID];
__device__ __nv_bfloat16 g_ctx_l[MQ*HID];
__device__ __nv_bfloat16 g_wq_h[HID*HID], g_wq_l[HID*HID];
__device__ __nv_bfloat16 g_wk_h[HID*HID], g_wk_l[HID*HID];
__device__ __nv_bfloat16 g_wv_h[HID*HID], g_wv_l[HID*HID];
__device__ __nv_bfloat16 g_wo_h[HID*HID], g_wo_l[HID*HID];
__device__ __nv_bfloat16 g_qs_h[MQ*HID], g_qs_l[MQ*HID];
__device__ __nv_bfloat16 g_ks_h[MK*HID], g_ks_l[MK*HID];
__device__ __nv_bfloat16 g_vt  [MK*HID];   // [(b*H+h)*64 + d][slot]

// ---------------- small helpers ---------------------------------------------
__device__ __forceinline__ uint32_t smem_u32(const void* p) {
    uint32_t a;
    asm("{ .reg .u64 t; cvta.to.shared.u64 t, %1; cvt.u32.u64 %0, t; }" : "=r"(a) : "l"(p));
    return a;
}

__device__ __forceinline__ void split_bf16(float x, __nv_bfloat16& h, __nv_bfloat16& l) {
    h = __float2bfloat16(x);
    l = __float2bfloat16(x - __bfloat162float(h));
}

__device__ __forceinline__ float2 block_reduce2(float a, float b, float* sh) {
    #pragma unroll
    for (int o = 16; o; o >>= 1) {
        a += __shfl_xor_sync(0xffffffffu, a, o);
        b += __shfl_xor_sync(0xffffffffu, b, o);
    }
    int w = threadIdx.x >> 5;
    if ((threadIdx.x & 31) == 0) { sh[w] = a; sh[8 + w] = b; }
    __syncthreads();
    if (threadIdx.x == 0) {
        float sa = 0.f, sb = 0.f;
        #pragma unroll
        for (int i = 0; i < 8; i++) { sa += sh[i]; sb += sh[8 + i]; }
        sh[0] = sa; sh[8] = sb;
    }
    __syncthreads();
    return make_float2(sh[0], sh[8]);
}

#define CP_ASYNC16(dst, src) \
    asm volatile("cp.async.cg.shared.global [%0], [%1], 16;" :: "r"(dst), "l"(src))
#define CP_COMMIT() asm volatile("cp.async.commit_group;" ::: "memory")
#define CP_WAIT0()  asm volatile("cp.async.wait_group 0;" ::: "memory")
#define CP_WAIT1()  asm volatile("cp.async.wait_group 1;" ::: "memory")

__device__ __forceinline__ void ldsm4(uint32_t* r, uint32_t addr) {
    asm volatile("ldmatrix.sync.aligned.m8n8.x4.shared.b16 {%0,%1,%2,%3}, [%4];"
                 : "=r"(r[0]), "=r"(r[1]), "=r"(r[2]), "=r"(r[3]) : "r"(addr));
}

__device__ __forceinline__ void mma16816(float* c, const uint32_t* a, const uint32_t* b) {
    asm volatile(
        "mma.sync.aligned.m16n8k16.row.col.f32.bf16.bf16.f32 "
        "{%0,%1,%2,%3}, {%4,%5,%6,%7}, {%8,%9}, {%0,%1,%2,%3};"
        : "+f"(c[0]), "+f"(c[1]), "+f"(c[2]), "+f"(c[3])
        : "r"(a[0]), "r"(a[1]), "r"(a[2]), "r"(a[3]), "r"(b[0]), "r"(b[1]));
}

// fast 2^x for x <= 0 (clamped at -80), FMA-pipe only
__device__ __forceinline__ float exp2m(float x) {
    x = fmaxf(x, -80.f);
    float fl = floorf(x);
    float f = x - fl;
    float p = 1.5400290440989764e-4f;
    p = fmaf(p, f, 1.3333558146428443e-3f);
    p = fmaf(p, f, 9.6181291076284772e-3f);
    p = fmaf(p, f, 5.5504108664821580e-2f);
    p = fmaf(p, f, 2.4022650695910072e-1f);
    p = fmaf(p, f, 6.9314718055994531e-1f);
    p = fmaf(p, f, 1.0f);
    return __int_as_float(((int)fl + 127) << 23) * p;
}

// ---------------- deterministic key compaction (block scan, no atomics) -----
__global__ void compact_kernel(const int* __restrict__ pad,
                               int* __restrict__ nv, int* __restrict__ cidx) {
    __shared__ int wsum[32];
    int b = blockIdx.x, tid = threadIdx.x;
    int lane = tid & 31, w = tid >> 5;
    int base = b * NK;
    int k0 = tid * 4;
    int f0 = pad[base + k0 + 0] != 0;
    int f1 = pad[base + k0 + 1] != 0;
    int f2 = pad[base + k0 + 2] != 0;
    int f3 = pad[base + k0 + 3] != 0;
    int c = f0 + f1 + f2 + f3;
    int inc = c;
    #pragma unroll
    for (int o = 1; o < 32; o <<= 1) {
        int t = __shfl_up_sync(0xffffffffu, inc, o);
        if (lane >= o) inc += t;
    }
    if (lane == 31) wsum[w] = inc;
    __syncthreads();
    if (w == 0) {
        int v = wsum[lane];
        #pragma unroll
        for (int o = 1; o < 32; o <<= 1) {
            int t = __shfl_up_sync(0xffffffffu, v, o);
            if (lane >= o) v += t;
        }
        wsum[lane] = v;
    }
    __syncthreads();
    int pos = inc - c + (w ? wsum[w - 1] : 0);
    if (f0) cidx[base + pos++] = k0 + 0;
    if (f1) cidx[base + pos++] = k0 + 1;
    if (f2) cidx[base + pos++] = k0 + 2;
    if (f3) cidx[base + pos++] = k0 + 3;
    int total = wsum[31];
    if (tid == 0) nv[b] = total;
    for (int s = total + tid; s < NK; s += 1024) cidx[base + s] = 0;
}

// ---------------- LayerNorm -> bf16 hi/lo split ------------------------------
__global__ void ln_split_kernel(const float* __restrict__ x,
                                const float* __restrict__ w,
                                const float* __restrict__ b,
                                __nv_bfloat16* __restrict__ oh,
                                __nv_bfloat16* __restrict__ ol) {
    __shared__ float sh[16];
    size_t row = blockIdx.x;
    float4 v = ((const float4*)(x + row * HID))[threadIdx.x];
    float s  = v.x + v.y + v.z + v.w;
    float s2 = v.x*v.x + v.y*v.y + v.z*v.z + v.w*v.w;
    float2 r = block_reduce2(s, s2, sh);
    float mean = r.x * (1.f / HID);
    float var  = r.y * (1.f / HID) - mean * mean;
    float rstd = rsqrtf(var + LN_EPS);
    float4 wv = ((const float4*)w)[threadIdx.x];
    float4 bv = ((const float4*)b)[threadIdx.x];
    float o0 = (v.x - mean) * rstd * wv.x + bv.x;
    float o1 = (v.y - mean) * rstd * wv.y + bv.y;
    float o2 = (v.z - mean) * rstd * wv.z + bv.z;
    float o3 = (v.w - mean) * rstd * wv.w + bv.w;
    __nv_bfloat16 h0,h1,h2,h3,l0,l1,l2,l3;
    split_bf16(o0,h0,l0); split_bf16(o1,h1,l1);
    split_bf16(o2,h2,l2); split_bf16(o3,h3,l3);
    __nv_bfloat162* ph = (__nv_bfloat162*)(oh + row * HID + threadIdx.x * 4);
    __nv_bfloat162* pl = (__nv_bfloat162*)(ol + row * HID + threadIdx.x * 4);
    ph[0] = __nv_bfloat162(h0, h1); ph[1] = __nv_bfloat162(h2, h3);
    pl[0] = __nv_bfloat162(l0, l1); pl[1] = __nv_bfloat162(l2, l3);
}

// ---------------- generic fp32 -> bf16 hi/lo split (with scale) --------------
__global__ void split_kernel(const float* __restrict__ x,
                             __nv_bfloat16* __restrict__ oh,
                             __nv_bfloat16* __restrict__ ol, int n4, float sc) {
    for (int i = blockIdx.x * blockDim.x + threadIdx.x; i < n4; i += gridDim.x * blockDim.x) {
        float4 v = ((const float4*)x)[i];
        v.x *= sc; v.y *= sc; v.z *= sc; v.w *= sc;
        __nv_bfloat16 h0,h1,h2,h3,l0,l1,l2,l3;
        split_bf16(v.x,h0,l0); split_bf16(v.y,h1,l1);
        split_bf16(v.z,h2,l2); split_bf16(v.w,h3,l3);
        __nv_bfloat162* ph = (__nv_bfloat162*)(oh + (size_t)i * 4);
        __nv_bfloat162* pl = (__nv_bfloat162*)(ol + (size_t)i * 4);
        ph[0] = __nv_bfloat162(h0, h1); ph[1] = __nv_bfloat162(h2, h3);
        pl[0] = __nv_bfloat162(l0, l1); pl[1] = __nv_bfloat162(l2, l3);
    }
}

// ---------------- V transpose (guarded to valid slots) -----------------------
__global__ void vt_kernel(const float* __restrict__ v, __nv_bfloat16* __restrict__ vt,
                          const int* __restrict__ nv) {
    __shared__ float tile[32][33];
    int b = blockIdx.z;
    int k0 = blockIdx.x * 32, d0 = blockIdx.y * 32;
    if (k0 >= ((nv[b] + 63) & ~63)) return;
    for (int i = threadIdx.y; i < 32; i += 8)
        tile[i][threadIdx.x] = v[(size_t)(b * NK + k0 + i) * HID + d0 + threadIdx.x];
    __syncthreads();
    for (int i = threadIdx.y; i < 32; i += 8) {
        int d = d0 + i;
        int h = d >> 6, dd = d & 63;
        vt[(size_t)((b * HEADS + h) * 64 + dd) * NK + k0 + threadIdx.x] =
            __float2bfloat16(tile[threadIdx.x][i]);
    }
}

// ---------------- bias (compacted order, log2 domain, -M0 folded) ------------
__global__ void bias_kernel(const int* __restrict__ kt, const int* __restrict__ nv,
                            const int* __restrict__ cidx,
                            const float* __restrict__ tb, float* __restrict__ out) {
    int i = blockIdx.x * blockDim.x + threadIdx.x;
    if (i >= BATCH * NK) return;
    int b = i / NK, s = i % NK;
    float t0, t1, t2;
    if (s < nv[b]) {
        int c = kt[cidx[i]];
        t0 = tb[c] * LOG2E - M0; t1 = tb[3 + c] * LOG2E - M0; t2 = tb[6 + c] * LOG2E - M0;
    } else {
        t0 = t1 = t2 = -1e30f;
    }
    out[(size_t)(b * 3 + 0) * NK + s] = t0;
    out[(size_t)(b * 3 + 1) * NK + s] = t1;
    out[(size_t)(b * 3 + 2) * NK + s] = t2;
}

// -------- residual + LayerNorm: out = LN(x + y) -----------------------------
__global__ void res_ln_kernel(const float* __restrict__ x,
                              const float* __restrict__ y,
                              const float* __restrict__ w,
                              const float* __restrict__ b,
                              float* __restrict__ out) {
    __shared__ float sh[16];
    size_t row = blockIdx.x;
    float4 v  = ((const float4*)(x + row * HID))[threadIdx.x];
    float4 yv = ((const float4*)(y + row * HID))[threadIdx.x];
    v.x += yv.x; v.y += yv.y; v.z += yv.z; v.w += yv.w;
    float s  = v.x + v.y + v.z + v.w;
    float s2 = v.x*v.x + v.y*v.y + v.z*v.z + v.w*v.w;
    float2 r = block_reduce2(s, s2, sh);
    float mean = r.x * (1.f / HID);
    float var  = r.y * (1.f / HID) - mean * mean;
    float rstd = rsqrtf(var + LN_EPS);
    float4 wv = ((const float4*)w)[threadIdx.x];
    float4 bv = ((const float4*)b)[threadIdx.x];
    float4 o;
    o.x = (v.x - mean) * rstd * wv.x + bv.x;
    o.y = (v.y - mean) * rstd * wv.y + bv.y;
    o.z = (v.z - mean) * rstd * wv.z + bv.z;
    o.w = (v.w - mean) * rstd * wv.w + bv.w;
    ((float4*)(out + row * HID))[threadIdx.x] = o;
}

// ================= HMMA bf16 split GEMM (proven R5/R6) ======================
#define STG_AH 0
#define STG_AL 16384
#define STG_BH 32768
#define STG_BL 40960
#define STAGE_SZ 49152
#define GT_SMEM (2*STAGE_SZ)

__global__ void __launch_bounds__(256, 2) gemm_hmma(
    const __nv_bfloat16* __restrict__ Ah, const __nv_bfloat16* __restrict__ Al,
    const __nv_bfloat16* __restrict__ Bh, const __nv_bfloat16* __restrict__ Bl,
    float* __restrict__ C) {
    extern __shared__ char sm[];
    uint32_t sb = smem_u32(sm);
    int tid = threadIdx.x;
    int wid = tid >> 5, lane = tid & 31;
    int wm = wid >> 1, wn = wid & 1;
    int rowBase = blockIdx.y * 128;
    int colBase = blockIdx.x * 64;
    int q = lane >> 3, ln8 = lane & 7;

    float acc[2][4][4];
    #pragma unroll
    for (int i = 0; i < 2; i++)
        #pragma unroll
        for (int j = 0; j < 4; j++)
            #pragma unroll
            for (int r = 0; r < 4; r++) acc[i][j][r] = 0.f;

    auto load_chunk = [&](int c, int st) {
        int k0 = c * 64;
        uint32_t so = sb + st * STAGE_SZ;
        #pragma unroll
        for (int s = 0; s < 4; s++) {
            int idx = tid + s * 256;
            int row = idx >> 3, ch = idx & 7;
            uint32_t off = (uint32_t)row * 128 + (uint32_t)((ch ^ (row & 7)) * 16);
            CP_ASYNC16(so + STG_AH + off, Ah + (size_t)(rowBase + row) * HID + k0 + ch * 8);
            CP_ASYNC16(so + STG_AL + off, Al + (size_t)(rowBase + row) * HID + k0 + ch * 8);
        }
        #pragma unroll
        for (int s = 0; s < 2; s++) {
            int idx = tid + s * 256;
            int row = idx >> 3, ch = idx & 7;
            uint32_t off = (uint32_t)row * 128 + (uint32_t)((ch ^ (row & 7)) * 16);
            CP_ASYNC16(so + STG_BH + off, Bh + (size_t)(colBase + row) * HID + k0 + ch * 8);
            CP_ASYNC16(so + STG_BL + off, Bl + (size_t)(colBase + row) * HID + k0 + ch * 8);
        }
        CP_COMMIT();
    };

    load_chunk(0, 0);

    for (int c = 0; c < 16; c++) {
        if (c < 15) { load_chunk(c + 1, (c + 1) & 1); CP_WAIT1(); }
        else        { CP_WAIT0(); }
        __syncthreads();

        uint32_t stBase = sb + (c & 1) * STAGE_SZ;
        #pragma unroll
        for (int pass = 0; pass < 3; pass++) {
            uint32_t Ab = stBase + ((pass < 2) ? STG_AH : STG_AL);
            uint32_t Bb = stBase + ((pass == 1) ? STG_BL : STG_BH);
            #pragma unroll
            for (int ti = 0; ti < 4; ti++) {
                uint32_t af[2][4];
                #pragma unroll
                for (int mi = 0; mi < 2; mi++) {
                    int row = wm * 32 + mi * 16 + (q & 1) * 8 + ln8;
                    int ch = ti * 2 + (q >> 1);
                    ldsm4(af[mi], Ab + row * 128 + ((ch ^ (row & 7)) * 16));
                }
                uint32_t bf[2][4];
                #pragma unroll
                for (int g = 0; g < 2; g++) {
                    int row = wn * 32 + g * 16 + (q >> 1) * 8 + ln8;
                    int ch = ti * 2 + (q & 1);
                    ldsm4(bf[g], Bb + row * 128 + ((ch ^ (row & 7)) * 16));
                }
                #pragma unroll
                for (int mi = 0; mi < 2; mi++) {
                    mma16816(acc[mi][0], af[mi], &bf[0][0]);
                    mma16816(acc[mi][1], af[mi], &bf[0][2]);
                    mma16816(acc[mi][2], af[mi], &bf[1][0]);
                    mma16816(acc[mi][3], af[mi], &bf[1][2]);
                }
            }
        }
        __syncthreads();
    }

    int r0 = rowBase + wm * 32 + (lane >> 2);
    int c0 = colBase + wn * 32 + (lane & 3) * 2;
    #pragma unroll
    for (int mi = 0; mi < 2; mi++) {
        #pragma unroll
        for (int ni = 0; ni < 4; ni++) {
            int rr = r0 + mi * 16;
            int cc = c0 + ni * 8;
            *(float2*)&C[(size_t)rr * HID + cc] = make_float2(acc[mi][ni][0], acc[mi][ni][1]);
            *(float2*)&C[(size_t)(rr + 8) * HID + cc] = make_float2(acc[mi][ni][2], acc[mi][ni][3]);
        }
    }
}

// ====== gathered-A variant for K/V projections (compacted rows) =============
__global__ void __launch_bounds__(256, 2) gemm_hmma_idx(
    const __nv_bfloat16* __restrict__ Ah, const __nv_bfloat16* __restrict__ Al,
    const __nv_bfloat16* __restrict__ Bh, const __nv_bfloat16* __restrict__ Bl,
    float* __restrict__ C, const int* __restrict__ cidx, const int* __restrict__ nv) {
    extern __shared__ char sm[];
    uint32_t sb = smem_u32(sm);
    int tid = threadIdx.x;
    int wid = tid >> 5, lane = tid & 31;
    int wm = wid >> 1, wn = wid & 1;
    int rowBase = blockIdx.y * 128;
    int colBase = blockIdx.x * 64;
    int b = rowBase / NK;
    int slot0 = rowBase % NK;
    if (slot0 >= ((nv[b] + 63) & ~63)) return;
    int q = lane >> 3, ln8 = lane & 7;

    // per-thread gathered A row pointers (rows fixed across K-chunks)
    const __nv_bfloat16 *pAh[4], *pAl[4];
    #pragma unroll
    for (int s = 0; s < 4; s++) {
        int slot = slot0 + (tid >> 3) + 32 * s;
        int ar = cidx[b * NK + slot];
        size_t o = (size_t)(b * NK + ar) * HID + (tid & 7) * 8;
        pAh[s] = Ah + o; pAl[s] = Al + o;
    }

    float acc[2][4][4];
    #pragma unroll
    for (int i = 0; i < 2; i++)
        #pragma unroll
        for (int j = 0; j < 4; j++)
            #pragma unroll
            for (int r = 0; r < 4; r++) acc[i][j][r] = 0.f;

    auto load_chunk = [&](int c, int st) {
        int k0 = c * 64;
        uint32_t so = sb + st * STAGE_SZ;
        #pragma unroll
        for (int s = 0; s < 4; s++) {
            int row = (tid >> 3) + 32 * s, ch = tid & 7;
            uint32_t off = (uint32_t)row * 128 + (uint32_t)((ch ^ (row & 7)) * 16);
            CP_ASYNC16(so + STG_AH + off, pAh[s] + k0);
            CP_ASYNC16(so + STG_AL + off, pAl[s] + k0);
        }
        #pragma unroll
        for (int s = 0; s < 2; s++) {
            int idx = tid + s * 256;
            int row = idx >> 3, ch = idx & 7;
            uint32_t off = (uint32_t)row * 128 + (uint32_t)((ch ^ (row & 7)) * 16);
            CP_ASYNC16(so + STG_BH + off, Bh + (size_t)(colBase + row) * HID + k0 + ch * 8);
            CP_ASYNC16(so + STG_BL + off, Bl + (size_t)(colBase + row) * HID + k0 + ch * 8);
        }
        CP_COMMIT();
    };

    load_chunk(0, 0);

    for (int c = 0; c < 16; c++) {
        if (c < 15) { load_chunk(c + 1, (c + 1) & 1); CP_WAIT1(); }
        else        { CP_WAIT0(); }
        __syncthreads();

        uint32_t stBase = sb + (c & 1) * STAGE_SZ;
        #pragma unroll
        for (int pass = 0; pass < 3; pass++) {
            uint32_t Ab = stBase + ((pass < 2) ? STG_AH : STG_AL);
            uint32_t Bb = stBase + ((pass == 1) ? STG_BL : STG_BH);
            #pragma unroll
            for (int ti = 0; ti < 4; ti++) {
                uint32_t af[2][4];
                #pragma unroll
                for (int mi = 0; mi < 2; mi++) {
                    int row = wm * 32 + mi * 16 + (q & 1) * 8 + ln8;
                    int ch = ti * 2 + (q >> 1);
                    ldsm4(af[mi], Ab + row * 128 + ((ch ^ (row & 7)) * 16));
                }
                uint32_t bf[2][4];
                #pragma unroll
                for (int g = 0; g < 2; g++) {
                    int row = wn * 32 + g * 16 + (q >> 1) * 8 + ln8;
                    int ch = ti * 2 + (q & 1);
                    ldsm4(bf[g], Bb + row * 128 + ((ch ^ (row & 7)) * 16));
                }
                #pragma unroll
                for (int mi = 0; mi < 2; mi++) {
                    mma16816(acc[mi][0], af[mi], &bf[0][0]);
                    mma16816(acc[mi][1], af[mi], &bf[0][2]);
                    mma16816(acc[mi][2], af[mi], &bf[1][0]);
                    mma16816(acc[mi][3], af[mi], &bf[1][2]);
                }
            }
        }
        __syncthreads();
    }

    int r0 = rowBase + wm * 32 + (lane >> 2);
    int c0 = colBase + wn * 32 + (lane & 3) * 2;
    #pragma unroll
    for (int mi = 0; mi < 2; mi++) {
        #pragma unroll
        for (int ni = 0; ni < 4; ni++) {
            int rr = r0 + mi * 16;
            int cc = c0 + ni * 8;
            *(float2*)&C[(size_t)rr * HID + cc] = make_float2(acc[mi][ni][0], acc[mi][ni][1]);
            *(float2*)&C[(size_t)(rr + 8) * HID + cc] = make_float2(acc[mi][ni][2], acc[mi][ni][3]);
        }
    }
}

// ================= HMMA flash attention (compacted keys, fixed max) =========
#define AS_QH 0
#define AS_QL 8192
#define AS_STG 16384
#define AS_KH 0
#define AS_KL 8192
#define AS_VT 16384
#define AS_BIAS 24576
#define AS_STGSZ 25600
#define AT_SMEM (AS_STG + 2*AS_STGSZ)   // 67584

__global__ void __launch_bounds__(128) attn_hmma(
    const int* __restrict__ qt_ids, const int* __restrict__ nv,
    const __nv_bfloat16* __restrict__ Qh, const __nv_bfloat16* __restrict__ Ql,
    const __nv_bfloat16* __restrict__ Kh, const __nv_bfloat16* __restrict__ Kl,
    const __nv_bfloat16* __restrict__ Vt,
    const float* __restrict__ biasg,
    float* __restrict__ ctx) {
    extern __shared__ char sm[];
    uint32_t sb = smem_u32(sm);
    int tid = threadIdx.x, w = tid >> 5, lane = tid & 31;
    int q0 = blockIdx.x * 64, h = blockIdx.y, b = blockIdx.z;
    int group = lane >> 2, qp = lane & 3;
    int q8 = lane >> 3, ln8 = lane & 7;
    int ntiles = (nv[b] + 63) >> 6;

    // load Q tile (hi/lo) into swizzled smem
    #pragma unroll
    for (int s = 0; s < 4; s++) {
        int idx = tid + s * 128;
        int r = idx >> 3, ch = idx & 7;
        size_t go = (size_t)(b * NQ + q0 + r) * HID + h * 64 + ch * 8;
        uint32_t off = (uint32_t)r * 128 + (uint32_t)((ch ^ (r & 7)) * 16);
        *(uint4*)(sm + AS_QH + off) = *(const uint4*)(Qh + go);
        *(uint4*)(sm + AS_QL + off) = *(const uint4*)(Ql + go);
    }

    auto load_stage = [&](int t, int st) {
        int k0 = t * 64;
        uint32_t so = sb + AS_STG + st * AS_STGSZ;
        #pragma unroll
        for (int s = 0; s < 12; s++) {
            int idx = tid + s * 128;
            int m = idx >> 9;
            int rc = idx & 511;
            int r = rc >> 3, ch = rc & 7;
            uint32_t off = so + m * 8192 + (uint32_t)r * 128 + (uint32_t)((ch ^ (r & 7)) * 16);
            const __nv_bfloat16* src;
            if (m == 0)      src = Kh + (size_t)(b * NK + k0 + r) * HID + h * 64 + ch * 8;
            else if (m == 1) src = Kl + (size_t)(b * NK + k0 + r) * HID + h * 64 + ch * 8;
            else             src = Vt + (size_t)((b * HEADS + h) * 64 + r) * NK + k0 + ch * 8;
            CP_ASYNC16(off, src);
        }
        if (tid < 48) {
            int qt = tid >> 4, j = tid & 15;
            CP_ASYNC16(so + AS_BIAS + qt * 256 + j * 16,
                       biasg + (size_t)(b * 3 + qt) * NK + k0 + j * 4);
        }
        CP_COMMIT();
    };

    load_stage(0, 0);
    __syncthreads();

    // Q fragments (held in registers for whole kernel)
    uint32_t QHf[4][4], QLf[4][4];
    #pragma unroll
    for (int c2 = 0; c2 < 4; c2++) {
        int r = w * 16 + (lane & 15);
        int ch = c2 * 2 + (lane >> 4);
        uint32_t off = (uint32_t)r * 128 + (uint32_t)((ch ^ (r & 7)) * 16);
        ldsm4(QHf[c2], sb + AS_QH + off);
        ldsm4(QLf[c2], sb + AS_QL + off);
    }
    int qtA = qt_ids[q0 + w * 16 + group];
    int qtB = qt_ids[q0 + w * 16 + group + 8];

    float acc[8][4];
    #pragma unroll
    for (int i = 0; i < 8; i++)
        #pragma unroll
        for (int j = 0; j < 4; j++) acc[i][j] = 0.f;
    float lA = 0.f, lB = 0.f;

    for (int t = 0; t < ntiles; t++) {
        if (t + 1 < ntiles) { load_stage(t + 1, (t + 1) & 1); CP_WAIT1(); }
        else                { CP_WAIT0(); }
        __syncthreads();
        uint32_t st = sb + AS_STG + (t & 1) * AS_STGSZ;
        char*    stc = sm + AS_STG + (t & 1) * AS_STGSZ;

        // ---- S = Q K^T (3-term split, log2 domain), merged ldsm4 ----
        float S[8][4];
        #pragma unroll
        for (int np = 0; np < 4; np++) {
            #pragma unroll
            for (int j = 0; j < 4; j++) { S[2*np][j] = 0.f; S[2*np+1][j] = 0.f; }
            #pragma unroll
            for (int c2 = 0; c2 < 4; c2++) {
                int row = np * 16 + (q8 >> 1) * 8 + ln8;
                int ch = c2 * 2 + (q8 & 1);
                uint32_t off = (uint32_t)row * 128 + (uint32_t)((ch ^ (row & 7)) * 16);
                uint32_t kh[4], kl[4];
                ldsm4(kh, st + AS_KH + off);
                ldsm4(kl, st + AS_KL + off);
                mma16816(S[2*np],   QHf[c2], &kh[0]);
                mma16816(S[2*np],   QLf[c2], &kh[0]);
                mma16816(S[2*np],   QHf[c2], &kl[0]);
                mma16816(S[2*np+1], QHf[c2], &kh[2]);
                mma16816(S[2*np+1], QLf[c2], &kh[2]);
                mma16816(S[2*np+1], QHf[c2], &kl[2]);
            }
        }

        // ---- p = 2^(S + bias') (fixed max M0 folded into bias) ----
        const float* bA = (const float*)(stc + AS_BIAS) + qtA * 64;
        const float* bB = (const float*)(stc + AS_BIAS) + qtB * 64;
        uint32_t P[4][4];
        #pragma unroll
        for (int kc = 0; kc < 4; kc++) {
            int t0 = kc * 2, t1 = t0 + 1;
            float2 a0 = *(const float2*)(bA + t0 * 8 + qp * 2);
            float2 b0 = *(const float2*)(bB + t0 * 8 + qp * 2);
            float2 a1 = *(const float2*)(bA + t1 * 8 + qp * 2);
            float2 b1 = *(const float2*)(bB + t1 * 8 + qp * 2);
            float p00 = exp2m(S[t0][0] + a0.x), p01 = exp2m(S[t0][1] + a0.y);
            float p02 = exp2m(S[t0][2] + b0.x), p03 = exp2m(S[t0][3] + b0.y);
            float p10 = exp2m(S[t1][0] + a1.x), p11 = exp2m(S[t1][1] + a1.y);
            float p12 = exp2m(S[t1][2] + b1.x), p13 = exp2m(S[t1][3] + b1.y);
            lA += p00 + p01 + p10 + p11;
            lB += p02 + p03 + p12 + p13;
            __nv_bfloat162 tt;
            tt = __floats2bfloat162_rn(p00, p01); P[kc][0] = *(uint32_t*)&tt;
            tt = __floats2bfloat162_rn(p02, p03); P[kc][1] = *(uint32_t*)&tt;
            tt = __floats2bfloat162_rn(p10, p11); P[kc][2] = *(uint32_t*)&tt;
            tt = __floats2bfloat162_rn(p12, p13); P[kc][3] = *(uint32_t*)&tt;
        }

        // ---- acc += P @ V  (merged ldsm4) ----
        #pragma unroll
        for (int kc = 0; kc < 4; kc++) {
            #pragma unroll
            for (int tdp = 0; tdp < 4; tdp++) {
                int row = tdp * 16 + (q8 >> 1) * 8 + ln8;
                int ch = kc * 2 + (q8 & 1);
                uint32_t off = (uint32_t)row * 128 + (uint32_t)((ch ^ (row & 7)) * 16);
                uint32_t v4[4];
                ldsm4(v4, st + AS_VT + off);
                mma16816(acc[2*tdp],   P[kc], &v4[0]);
                mma16816(acc[2*tdp+1], P[kc], &v4[2]);
            }
        }
        __syncthreads();
    }

    // deferred l reduction over the quad
    lA += __shfl_xor_sync(0xffffffffu, lA, 1);
    lA += __shfl_xor_sync(0xffffffffu, lA, 2);
    lB += __shfl_xor_sync(0xffffffffu, lB, 1);
    lB += __shfl_xor_sync(0xffffffffu, lB, 2);
    float iA = 1.f / lA, iB = 1.f / lB;

    int rowA = q0 + w * 16 + group, rowB = rowA + 8;
    #pragma unroll
    for (int td = 0; td < 8; td++) {
        int col = h * 64 + td * 8 + qp * 2;
        *(float2*)&ctx[(size_t)(b * NQ + rowA) * HID + col] =
            make_float2(acc[td][0] * iA, acc[td][1] * iA);
        *(float2*)&ctx[(size_t)(b * NQ + rowB) * HID + col] =
            make_float2(acc[td][2] * iB, acc[td][3] * iB);
    }
}

// ---------------- launch ----------------------------------------------------
extern "C" void kernel_launch(void* const* d_in, const int* in_sizes, int n_in,
                              void* d_out, int out_size) {
    const float* queries = (const float*)d_in[0];
    const float* kv      = (const float*)d_in[1];
    const int*   qt_ids  = (const int*)d_in[2];
    const int*   kt_ids  = (const int*)d_in[3];
    const int*   pad     = (const int*)d_in[4];
    const float* Wq   = (const float*)d_in[5];
    const float* Wk   = (const float*)d_in[6];
    const float* Wv   = (const float*)d_in[7];
    const float* Wo   = (const float*)d_in[8];
    const float* qn_w = (const float*)d_in[9];
    const float* qn_b = (const float*)d_in[10];
    const float* kvn_w = (const float*)d_in[11];
    const float* kvn_b = (const float*)d_in[12];
    const float* on_w = (const float*)d_in[13];
    const float* on_b = (const float*)d_in[14];
    const float* tb   = (const float*)d_in[15];
    float* out = (float*)d_out;

    float *p_q, *p_k, *p_v, *p_ctx, *p_o, *p_bias;
    int *p_nv, *p_cidx;
    __nv_bfloat16 *p_qn_h, *p_qn_l, *p_kvn_h, *p_kvn_l, *p_ctx_h, *p_ctx_l;
    __nv_bfloat16 *p_wq_h, *p_wq_l, *p_wk_h, *p_wk_l, *p_wv_h, *p_wv_l, *p_wo_h, *p_wo_l;
    __nv_bfloat16 *p_qs_h, *p_qs_l, *p_ks_h, *p_ks_l, *p_vt;
    cudaGetSymbolAddress((void**)&p_q,   g_q);
    cudaGetSymbolAddress((void**)&p_k,   g_k);
    cudaGetSymbolAddress((void**)&p_v,   g_v);
    cudaGetSymbolAddress((void**)&p_ctx, g_ctx);
    cudaGetSymbolAddress((void**)&p_o,   g_o);
    cudaGetSymbolAddress((void**)&p_bias, g_bias);
    cudaGetSymbolAddress((void**)&p_nv,   g_nv);
    cudaGetSymbolAddress((void**)&p_cidx, g_cidx);
    cudaGetSymbolAddress((void**)&p_qn_h,  g_qn_h);
    cudaGetSymbolAddress((void**)&p_qn_l,  g_qn_l);
    cudaGetSymbolAddress((void**)&p_kvn_h, g_kvn_h);
    cudaGetSymbolAddress((void**)&p_kvn_l, g_kvn_l);
    cudaGetSymbolAddress((void**)&p_ctx_h, g_ctx_h);
    cudaGetSymbolAddress((void**)&p_ctx_l, g_ctx_l);
    cudaGetSymbolAddress((void**)&p_wq_h, g_wq_h);
    cudaGetSymbolAddress((void**)&p_wq_l, g_wq_l);
    cudaGetSymbolAddress((void**)&p_wk_h, g_wk_h);
    cudaGetSymbolAddress((void**)&p_wk_l, g_wk_l);
    cudaGetSymbolAddress((void**)&p_wv_h, g_wv_h);
    cudaGetSymbolAddress((void**)&p_wv_l, g_wv_l);
    cudaGetSymbolAddress((void**)&p_wo_h, g_wo_h);
    cudaGetSymbolAddress((void**)&p_wo_l, g_wo_l);
    cudaGetSymbolAddress((void**)&p_qs_h, g_qs_h);
    cudaGetSymbolAddress((void**)&p_qs_l, g_qs_l);
    cudaGetSymbolAddress((void**)&p_ks_h, g_ks_h);
    cudaGetSymbolAddress((void**)&p_ks_l, g_ks_l);
    cudaGetSymbolAddress((void**)&p_vt,   g_vt);

    static int attr_set = 0;
    if (!attr_set) {
        cudaFuncSetAttribute(gemm_hmma, cudaFuncAttributeMaxDynamicSharedMemorySize, GT_SMEM);
        cudaFuncSetAttribute(gemm_hmma_idx, cudaFuncAttributeMaxDynamicSharedMemorySize, GT_SMEM);
        cudaFuncSetAttribute(attn_hmma, cudaFuncAttributeMaxDynamicSharedMemorySize, AT_SMEM);
        attr_set = 1;
    }

    // 0. deterministic key compaction
    compact_kernel<<<BATCH, 1024>>>(pad, p_nv, p_cidx);

    // 1. LN -> bf16 splits
    ln_split_kernel<<<MQ, 256>>>(queries, qn_w, qn_b, p_qn_h, p_qn_l);
    ln_split_kernel<<<MK, 256>>>(kv, kvn_w, kvn_b, p_kvn_h, p_kvn_l);

    // 2. weight splits
    split_kernel<<<512, 256>>>(Wq, p_wq_h, p_wq_l, HID * HID / 4, 1.f);
    split_kernel<<<512, 256>>>(Wk, p_wk_h, p_wk_l, HID * HID / 4, 1.f);
    split_kernel<<<512, 256>>>(Wv, p_wv_h, p_wv_l, HID * HID / 4, 1.f);
    split_kernel<<<512, 256>>>(Wo, p_wo_h, p_wo_l, HID * HID / 4, 1.f);

    // 3. projections (K/V gathered to compacted rows, early-exit past nv)
    {
        dim3 gq(HID / 64, MQ / 128);
        dim3 gk(HID / 64, MK / 128);
        gemm_hmma<<<gq, 256, GT_SMEM>>>(p_qn_h, p_qn_l, p_wq_h, p_wq_l, p_q);
        gemm_hmma_idx<<<gk, 256, GT_SMEM>>>(p_kvn_h, p_kvn_l, p_wk_h, p_wk_l, p_k, p_cidx, p_nv);
        gemm_hmma_idx<<<gk, 256, GT_SMEM>>>(p_kvn_h, p_kvn_l, p_wv_h, p_wv_l, p_v, p_cidx, p_nv);
    }

    // 4. attention precompute
    split_kernel<<<512, 256>>>(p_q, p_qs_h, p_qs_l, MQ * HID / 4, QKSCALE);
    split_kernel<<<512, 256>>>(p_k, p_ks_h, p_ks_l, MK * HID / 4, 1.f);
    {
        dim3 gv(NK / 32, HID / 32, BATCH);
        vt_kernel<<<gv, dim3(32, 8)>>>(p_v, p_vt, p_nv);
    }
    bias_kernel<<<(BATCH * NK + 255) / 256, 256>>>(kt_ids, p_nv, p_cidx, tb, p_bias);

    // 5. flash attention (HMMA, compacted keys)
    {
        dim3 ga(NQ / 64, HEADS, BATCH);
        attn_hmma<<<ga, 128, AT_SMEM>>>(qt_ids, p_nv, p_qs_h, p_qs_l, p_ks_h, p_ks_l,
                                        p_vt, p_bias, p_ctx);
    }

    // 6. ctx split + output projection
    split_kernel<<<512, 256>>>(p_ctx, p_ctx_h, p_ctx_l, MQ * HID / 4, 1.f);
    {
        dim3 go(HID / 64, MQ / 128);
        gemm_hmma<<<go, 256, GT_SMEM>>>(p_ctx_h, p_ctx_l, p_wo_h, p_wo_l, p_o);
    }

    // 7. residual + LN -> d_out
    res_ln_kernel<<<MQ, 256>>>(queries, p_o, on_w, on_b, out);
}

// round 8
// speedup vs baseline: 11.2132x; 1.7533x over previous
#include <cuda_runtime.h>
#include <cuda_bf16.h>
#include <math.h>
#include <float.h>
#include <stdint.h>

#define BATCH 2
#define NQ    1024
#define NK    4096
#define HID   1024
#define HEADS 16
#define HD    64
#define LN_EPS 1e-5f
#define LOG2E 1.4426950408889634f
#define QKSCALE (0.125f * LOG2E)
#define M0    32.0f

#define MQ (BATCH*NQ)   // 2048
#define MK (BATCH*NK)   // 8192

// ---------------- scratch (__device__ globals) ------------------------------
__device__ float g_o   [MQ*HID];
__device__ float g_bias[BATCH*3*NK];
__device__ int   g_nv[BATCH];
__device__ int   g_cidx[BATCH*NK];

__device__ __nv_bfloat16 g_qn [MQ*HID];
__device__ __nv_bfloat16 g_kvn[MK*HID];
__device__ __nv_bfloat16 g_wq_h[HID*HID];
__device__ __nv_bfloat16 g_wk_h[HID*HID];
__device__ __nv_bfloat16 g_wv_h[HID*HID];
__device__ __nv_bfloat16 g_wo_h[HID*HID], g_wo_l[HID*HID];
__device__ __nv_bfloat16 g_qs [MQ*HID];
__device__ __nv_bfloat16 g_ks [MK*HID];
__device__ __nv_bfloat16 g_vt [MK*HID];       // [(b*H+h)*64 + d][slot]
__device__ __nv_bfloat16 g_ctx_h[MQ*HID], g_ctx_l[MQ*HID];

// ---------------- small helpers ---------------------------------------------
__device__ __forceinline__ uint32_t smem_u32(const void* p) {
    uint32_t a;
    asm("{ .reg .u64 t; cvta.to.shared.u64 t, %1; cvt.u32.u64 %0, t; }" : "=r"(a) : "l"(p));
    return a;
}

__device__ __forceinline__ void split_bf16(float x, __nv_bfloat16& h, __nv_bfloat16& l) {
    h = __float2bfloat16(x);
    l = __float2bfloat16(x - __bfloat162float(h));
}

__device__ __forceinline__ float2 block_reduce2(float a, float b, float* sh) {
    #pragma unroll
    for (int o = 16; o; o >>= 1) {
        a += __shfl_xor_sync(0xffffffffu, a, o);
        b += __shfl_xor_sync(0xffffffffu, b, o);
    }
    int w = threadIdx.x >> 5;
    if ((threadIdx.x & 31) == 0) { sh[w] = a; sh[8 + w] = b; }
    __syncthreads();
    if (threadIdx.x == 0) {
        float sa = 0.f, sb = 0.f;
        #pragma unroll
        for (int i = 0; i < 8; i++) { sa += sh[i]; sb += sh[8 + i]; }
        sh[0] = sa; sh[8] = sb;
    }
    __syncthreads();
    return make_float2(sh[0], sh[8]);
}

#define CP_ASYNC16(dst, src) \
    asm volatile("cp.async.cg.shared.global [%0], [%1], 16;" :: "r"(dst), "l"(src))
#define CP_COMMIT() asm volatile("cp.async.commit_group;" ::: "memory")
#define CP_WAIT0()  asm volatile("cp.async.wait_group 0;" ::: "memory")
#define CP_WAIT1()  asm volatile("cp.async.wait_group 1;" ::: "memory")

__device__ __forceinline__ void ldsm4(uint32_t* r, uint32_t addr) {
    asm volatile("ldmatrix.sync.aligned.m8n8.x4.shared.b16 {%0,%1,%2,%3}, [%4];"
                 : "=r"(r[0]), "=r"(r[1]), "=r"(r[2]), "=r"(r[3]) : "r"(addr));
}

__device__ __forceinline__ void mma16816(float* c, const uint32_t* a, const uint32_t* b) {
    asm volatile(
        "mma.sync.aligned.m16n8k16.row.col.f32.bf16.bf16.f32 "
        "{%0,%1,%2,%3}, {%4,%5,%6,%7}, {%8,%9}, {%0,%1,%2,%3};"
        : "+f"(c[0]), "+f"(c[1]), "+f"(c[2]), "+f"(c[3])
        : "r"(a[0]), "r"(a[1]), "r"(a[2]), "r"(a[3]), "r"(b[0]), "r"(b[1]));
}

// fast 2^x for x <= 0 (clamped at -80), magic-rounding + deg-4 poly
__device__ __forceinline__ float exp2m(float x) {
    x = fmaxf(x, -80.f);
    float t = __fadd_rn(x, 12582912.f);            // round to int (magic)
    float r = __fadd_rn(t, -12582912.f);
    float f = x - r;                               // [-0.5, 0.5]
    int   n = __float_as_int(t) - 0x4B400000;
    float p = 9.6181291e-3f;
    p = fmaf(p, f, 5.5504109e-2f);
    p = fmaf(p, f, 2.4022651e-1f);
    p = fmaf(p, f, 6.9314718e-1f);
    p = fmaf(p, f, 1.0f);
    return __int_as_float((n + 127) << 23) * p;
}

// ---------------- deterministic key compaction -------------------------------
__global__ void compact_kernel(const int* __restrict__ pad,
                               int* __restrict__ nv, int* __restrict__ cidx) {
    __shared__ int wsum[32];
    int b = blockIdx.x, tid = threadIdx.x;
    int lane = tid & 31, w = tid >> 5;
    int base = b * NK;
    int k0 = tid * 4;
    int f0 = pad[base + k0 + 0] != 0;
    int f1 = pad[base + k0 + 1] != 0;
    int f2 = pad[base + k0 + 2] != 0;
    int f3 = pad[base + k0 + 3] != 0;
    int c = f0 + f1 + f2 + f3;
    int inc = c;
    #pragma unroll
    for (int o = 1; o < 32; o <<= 1) {
        int t = __shfl_up_sync(0xffffffffu, inc, o);
        if (lane >= o) inc += t;
    }
    if (lane == 31) wsum[w] = inc;
    __syncthreads();
    if (w == 0) {
        int v = wsum[lane];
        #pragma unroll
        for (int o = 1; o < 32; o <<= 1) {
            int t = __shfl_up_sync(0xffffffffu, v, o);
            if (lane >= o) v += t;
        }
        wsum[lane] = v;
    }
    __syncthreads();
    int pos = inc - c + (w ? wsum[w - 1] : 0);
    if (f0) cidx[base + pos++] = k0 + 0;
    if (f1) cidx[base + pos++] = k0 + 1;
    if (f2) cidx[base + pos++] = k0 + 2;
    if (f3) cidx[base + pos++] = k0 + 3;
    int total = wsum[31];
    if (tid == 0) nv[b] = total;
    for (int s = total + tid; s < NK; s += 1024) cidx[base + s] = 0;
}

// ---------------- LayerNorm -> bf16 ------------------------------------------
__global__ void ln_bf16_kernel(const float* __restrict__ x,
                               const float* __restrict__ w,
                               const float* __restrict__ b,
                               __nv_bfloat16* __restrict__ oh) {
    __shared__ float sh[16];
    size_t row = blockIdx.x;
    float4 v = ((const float4*)(x + row * HID))[threadIdx.x];
    float s  = v.x + v.y + v.z + v.w;
    float s2 = v.x*v.x + v.y*v.y + v.z*v.z + v.w*v.w;
    float2 r = block_reduce2(s, s2, sh);
    float mean = r.x * (1.f / HID);
    float var  = r.y * (1.f / HID) - mean * mean;
    float rstd = rsqrtf(var + LN_EPS);
    float4 wv = ((const float4*)w)[threadIdx.x];
    float4 bv = ((const float4*)b)[threadIdx.x];
    float o0 = (v.x - mean) * rstd * wv.x + bv.x;
    float o1 = (v.y - mean) * rstd * wv.y + bv.y;
    float o2 = (v.z - mean) * rstd * wv.z + bv.z;
    float o3 = (v.w - mean) * rstd * wv.w + bv.w;
    __nv_bfloat162* ph = (__nv_bfloat162*)(oh + row * HID + threadIdx.x * 4);
    ph[0] = __floats2bfloat162_rn(o0, o1);
    ph[1] = __floats2bfloat162_rn(o2, o3);
}

// ---------------- merged weight splits: Wq/Wk/Wv hi; Wo hi+lo ----------------
__global__ void wsplit_all(const float* __restrict__ w0, const float* __restrict__ w1,
                           const float* __restrict__ w2, const float* __restrict__ w3,
                           __nv_bfloat16* __restrict__ h0, __nv_bfloat16* __restrict__ h1,
                           __nv_bfloat16* __restrict__ h2, __nv_bfloat16* __restrict__ h3,
                           __nv_bfloat16* __restrict__ l3) {
    int wi = blockIdx.x >> 9;
    int blk = blockIdx.x & 511;
    const float* src = (wi == 0) ? w0 : (wi == 1) ? w1 : (wi == 2) ? w2 : w3;
    __nv_bfloat16* dh = (wi == 0) ? h0 : (wi == 1) ? h1 : (wi == 2) ? h2 : h3;
    const int n4 = HID * HID / 4;
    for (int i = blk * 256 + threadIdx.x; i < n4; i += 512 * 256) {
        float4 v = ((const float4*)src)[i];
        __nv_bfloat16 a0,a1,a2,a3,b0,b1,b2,b3;
        split_bf16(v.x,a0,b0); split_bf16(v.y,a1,b1);
        split_bf16(v.z,a2,b2); split_bf16(v.w,a3,b3);
        __nv_bfloat162* ph = (__nv_bfloat162*)(dh + (size_t)i * 4);
        ph[0] = __nv_bfloat162(a0, a1); ph[1] = __nv_bfloat162(a2, a3);
        if (wi == 3) {
            __nv_bfloat162* pl = (__nv_bfloat162*)(l3 + (size_t)i * 4);
            pl[0] = __nv_bfloat162(b0, b1); pl[1] = __nv_bfloat162(b2, b3);
        }
    }
}

// ---------------- bias (compacted, log2, -M0 folded) -------------------------
__global__ void bias_kernel(const int* __restrict__ kt, const int* __restrict__ nv,
                            const int* __restrict__ cidx,
                            const float* __restrict__ tb, float* __restrict__ out) {
    int i = blockIdx.x * blockDim.x + threadIdx.x;
    if (i >= BATCH * NK) return;
    int b = i / NK, s = i % NK;
    float t0, t1, t2;
    if (s < nv[b]) {
        int c = kt[cidx[i]];
        t0 = tb[c] * LOG2E - M0; t1 = tb[3 + c] * LOG2E - M0; t2 = tb[6 + c] * LOG2E - M0;
    } else {
        t0 = t1 = t2 = -1e30f;
    }
    out[(size_t)(b * 3 + 0) * NK + s] = t0;
    out[(size_t)(b * 3 + 1) * NK + s] = t1;
    out[(size_t)(b * 3 + 2) * NK + s] = t2;
}

// -------- residual + LayerNorm -----------------------------------------------
__global__ void res_ln_kernel(const float* __restrict__ x,
                              const float* __restrict__ y,
                              const float* __restrict__ w,
                              const float* __restrict__ b,
                              float* __restrict__ out) {
    __shared__ float sh[16];
    size_t row = blockIdx.x;
    float4 v  = ((const float4*)(x + row * HID))[threadIdx.x];
    float4 yv = ((const float4*)(y + row * HID))[threadIdx.x];
    v.x += yv.x; v.y += yv.y; v.z += yv.z; v.w += yv.w;
    float s  = v.x + v.y + v.z + v.w;
    float s2 = v.x*v.x + v.y*v.y + v.z*v.z + v.w*v.w;
    float2 r = block_reduce2(s, s2, sh);
    float mean = r.x * (1.f / HID);
    float var  = r.y * (1.f / HID) - mean * mean;
    float rstd = rsqrtf(var + LN_EPS);
    float4 wv = ((const float4*)w)[threadIdx.x];
    float4 bv = ((const float4*)b)[threadIdx.x];
    float4 o;
    o.x = (v.x - mean) * rstd * wv.x + bv.x;
    o.y = (v.y - mean) * rstd * wv.y + bv.y;
    o.z = (v.z - mean) * rstd * wv.z + bv.z;
    o.w = (v.w - mean) * rstd * wv.w + bv.w;
    ((float4*)(out + row * HID))[threadIdx.x] = o;
}

// ================= 1-term bf16 HMMA GEMM with fused epilogues ================
// C = A[M,1024] @ B[64-col tile,1024]^T, bf16 in, fp32 acc.
// EPI: 0 = bf16 out scaled by QKSCALE (Q), 1 = bf16 out (K), 2 = V-transpose.
#define G1_A 0
#define G1_B 16384
#define G1_STG 24576
#define G1_SMEM 49152

template<int EPI, bool IDX>
__global__ void __launch_bounds__(256, 2) gemm1(
    const __nv_bfloat16* __restrict__ A, const __nv_bfloat16* __restrict__ B,
    __nv_bfloat16* __restrict__ Cb,
    const int* __restrict__ cidx, const int* __restrict__ nv) {
    extern __shared__ char sm[];
    uint32_t sb = smem_u32(sm);
    int tid = threadIdx.x;
    int wid = tid >> 5, lane = tid & 31;
    int wm = wid >> 1, wn = wid & 1;
    int rowBase = blockIdx.y * 128;
    int colBase = blockIdx.x * 64;
    int q = lane >> 3, ln8 = lane & 7;

    int bb = 0;
    if (IDX) {
        bb = rowBase / NK;
        int slot0 = rowBase % NK;
        if (slot0 >= ((nv[bb] + 63) & ~63)) return;
    }

    // per-thread A row pointers
    const __nv_bfloat16* pA[4];
    #pragma unroll
    for (int s = 0; s < 4; s++) {
        int row = (tid >> 3) + 32 * s;
        if (IDX) {
            int slot = (rowBase % NK) + row;
            int ar = cidx[bb * NK + slot];
            pA[s] = A + (size_t)(bb * NK + ar) * HID + (tid & 7) * 8;
        } else {
            pA[s] = A + (size_t)(rowBase + row) * HID + (tid & 7) * 8;
        }
    }

    float acc[2][4][4];
    #pragma unroll
    for (int i = 0; i < 2; i++)
        #pragma unroll
        for (int j = 0; j < 4; j++)
            #pragma unroll
            for (int r = 0; r < 4; r++) acc[i][j][r] = 0.f;

    auto load_chunk = [&](int c, int st) {
        int k0 = c * 64;
        uint32_t so = sb + st * G1_STG;
        #pragma unroll
        for (int s = 0; s < 4; s++) {
            int row = (tid >> 3) + 32 * s, ch = tid & 7;
            uint32_t off = (uint32_t)row * 128 + (uint32_t)((ch ^ (row & 7)) * 16);
            CP_ASYNC16(so + G1_A + off, pA[s] + k0);
        }
        #pragma unroll
        for (int s = 0; s < 2; s++) {
            int idx = tid + s * 256;
            int row = idx >> 3, ch = idx & 7;
            uint32_t off = (uint32_t)row * 128 + (uint32_t)((ch ^ (row & 7)) * 16);
            CP_ASYNC16(so + G1_B + off, B + (size_t)(colBase + row) * HID + k0 + ch * 8);
        }
        CP_COMMIT();
    };

    load_chunk(0, 0);

    for (int c = 0; c < 16; c++) {
        if (c < 15) { load_chunk(c + 1, (c + 1) & 1); CP_WAIT1(); }
        else        { CP_WAIT0(); }
        __syncthreads();

        uint32_t Ab = sb + (c & 1) * G1_STG + G1_A;
        uint32_t Bb = sb + (c & 1) * G1_STG + G1_B;
        #pragma unroll
        for (int ti = 0; ti < 4; ti++) {
            uint32_t af[2][4];
            #pragma unroll
            for (int mi = 0; mi < 2; mi++) {
                int row = wm * 32 + mi * 16 + (q & 1) * 8 + ln8;
                int ch = ti * 2 + (q >> 1);
                ldsm4(af[mi], Ab + row * 128 + ((ch ^ (row & 7)) * 16));
            }
            uint32_t bf[2][4];
            #pragma unroll
            for (int g = 0; g < 2; g++) {
                int row = wn * 32 + g * 16 + (q >> 1) * 8 + ln8;
                int ch = ti * 2 + (q & 1);
                ldsm4(bf[g], Bb + row * 128 + ((ch ^ (row & 7)) * 16));
            }
            #pragma unroll
            for (int mi = 0; mi < 2; mi++) {
                mma16816(acc[mi][0], af[mi], &bf[0][0]);
                mma16816(acc[mi][1], af[mi], &bf[0][2]);
                mma16816(acc[mi][2], af[mi], &bf[1][0]);
                mma16816(acc[mi][3], af[mi], &bf[1][2]);
            }
        }
        __syncthreads();
    }

    if (EPI < 2) {
        const float sc = (EPI == 0) ? QKSCALE : 1.0f;
        int r0 = rowBase + wm * 32 + (lane >> 2);
        int c0 = colBase + wn * 32 + (lane & 3) * 2;
        #pragma unroll
        for (int mi = 0; mi < 2; mi++) {
            #pragma unroll
            for (int ni = 0; ni < 4; ni++) {
                int rr = r0 + mi * 16;
                int cc = c0 + ni * 8;
                *(__nv_bfloat162*)&Cb[(size_t)rr * HID + cc] =
                    __floats2bfloat162_rn(acc[mi][ni][0] * sc, acc[mi][ni][1] * sc);
                *(__nv_bfloat162*)&Cb[(size_t)(rr + 8) * HID + cc] =
                    __floats2bfloat162_rn(acc[mi][ni][2] * sc, acc[mi][ni][3] * sc);
            }
        }
    } else {
        // V transpose epilogue: acc -> smem [128 keys][65] -> vt[(b,h,d)][slot]
        float* ts = (float*)sm;
        int r0l = wm * 32 + (lane >> 2);
        int c0l = wn * 32 + (lane & 3) * 2;
        #pragma unroll
        for (int mi = 0; mi < 2; mi++) {
            #pragma unroll
            for (int ni = 0; ni < 4; ni++) {
                int rr = r0l + mi * 16, cc = c0l + ni * 8;
                ts[rr * 65 + cc] = acc[mi][ni][0];
                ts[rr * 65 + cc + 1] = acc[mi][ni][1];
                ts[(rr + 8) * 65 + cc] = acc[mi][ni][2];
                ts[(rr + 8) * 65 + cc + 1] = acc[mi][ni][3];
            }
        }
        __syncthreads();
        int hh = blockIdx.x;                     // head = colBase/64
        int slot0 = rowBase % NK;
        int d = tid >> 2, kb = (tid & 3) * 32;
        __nv_bfloat16* dst = Cb + (size_t)((bb * HEADS + hh) * 64 + d) * NK + slot0 + kb;
        #pragma unroll
        for (int k = 0; k < 32; k += 2) {
            *(__nv_bfloat162*)(dst + k) =
                __floats2bfloat162_rn(ts[(kb + k) * 65 + d], ts[(kb + k + 1) * 65 + d]);
        }
    }
}

// ================= 3-term split GEMM (O projection, fp32 out) ===============
#define STG_AH 0
#define STG_AL 16384
#define STG_BH 32768
#define STG_BL 40960
#define STAGE_SZ 49152
#define GT_SMEM (2*STAGE_SZ)

__global__ void __launch_bounds__(256, 2) gemm3_hmma(
    const __nv_bfloat16* __restrict__ Ah, const __nv_bfloat16* __restrict__ Al,
    const __nv_bfloat16* __restrict__ Bh, const __nv_bfloat16* __restrict__ Bl,
    float* __restrict__ C) {
    extern __shared__ char sm[];
    uint32_t sb = smem_u32(sm);
    int tid = threadIdx.x;
    int wid = tid >> 5, lane = tid & 31;
    int wm = wid >> 1, wn = wid & 1;
    int rowBase = blockIdx.y * 128;
    int colBase = blockIdx.x * 64;
    int q = lane >> 3, ln8 = lane & 7;

    float acc[2][4][4];
    #pragma unroll
    for (int i = 0; i < 2; i++)
        #pragma unroll
        for (int j = 0; j < 4; j++)
            #pragma unroll
            for (int r = 0; r < 4; r++) acc[i][j][r] = 0.f;

    auto load_chunk = [&](int c, int st) {
        int k0 = c * 64;
        uint32_t so = sb + st * STAGE_SZ;
        #pragma unroll
        for (int s = 0; s < 4; s++) {
            int idx = tid + s * 256;
            int row = idx >> 3, ch = idx & 7;
            uint32_t off = (uint32_t)row * 128 + (uint32_t)((ch ^ (row & 7)) * 16);
            CP_ASYNC16(so + STG_AH + off, Ah + (size_t)(rowBase + row) * HID + k0 + ch * 8);
            CP_ASYNC16(so + STG_AL + off, Al + (size_t)(rowBase + row) * HID + k0 + ch * 8);
        }
        #pragma unroll
        for (int s = 0; s < 2; s++) {
            int idx = tid + s * 256;
            int row = idx >> 3, ch = idx & 7;
            uint32_t off = (uint32_t)row * 128 + (uint32_t)((ch ^ (row & 7)) * 16);
            CP_ASYNC16(so + STG_BH + off, Bh + (size_t)(colBase + row) * HID + k0 + ch * 8);
            CP_ASYNC16(so + STG_BL + off, Bl + (size_t)(colBase + row) * HID + k0 + ch * 8);
        }
        CP_COMMIT();
    };

    load_chunk(0, 0);

    for (int c = 0; c < 16; c++) {
        if (c < 15) { load_chunk(c + 1, (c + 1) & 1); CP_WAIT1(); }
        else        { CP_WAIT0(); }
        __syncthreads();

        uint32_t stBase = sb + (c & 1) * STAGE_SZ;
        #pragma unroll
        for (int pass = 0; pass < 3; pass++) {
            uint32_t Ab = stBase + ((pass < 2) ? STG_AH : STG_AL);
            uint32_t Bb = stBase + ((pass == 1) ? STG_BL : STG_BH);
            #pragma unroll
            for (int ti = 0; ti < 4; ti++) {
                uint32_t af[2][4];
                #pragma unroll
                for (int mi = 0; mi < 2; mi++) {
                    int row = wm * 32 + mi * 16 + (q & 1) * 8 + ln8;
                    int ch = ti * 2 + (q >> 1);
                    ldsm4(af[mi], Ab + row * 128 + ((ch ^ (row & 7)) * 16));
                }
                uint32_t bf[2][4];
                #pragma unroll
                for (int g = 0; g < 2; g++) {
                    int row = wn * 32 + g * 16 + (q >> 1) * 8 + ln8;
                    int ch = ti * 2 + (q & 1);
                    ldsm4(bf[g], Bb + row * 128 + ((ch ^ (row & 7)) * 16));
                }
                #pragma unroll
                for (int mi = 0; mi < 2; mi++) {
                    mma16816(acc[mi][0], af[mi], &bf[0][0]);
                    mma16816(acc[mi][1], af[mi], &bf[0][2]);
                    mma16816(acc[mi][2], af[mi], &bf[1][0]);
                    mma16816(acc[mi][3], af[mi], &bf[1][2]);
                }
            }
        }
        __syncthreads();
    }

    int r0 = rowBase + wm * 32 + (lane >> 2);
    int c0 = colBase + wn * 32 + (lane & 3) * 2;
    #pragma unroll
    for (int mi = 0; mi < 2; mi++) {
        #pragma unroll
        for (int ni = 0; ni < 4; ni++) {
            int rr = r0 + mi * 16;
            int cc = c0 + ni * 8;
            *(float2*)&C[(size_t)rr * HID + cc] = make_float2(acc[mi][ni][0], acc[mi][ni][1]);
            *(float2*)&C[(size_t)(rr + 8) * HID + cc] = make_float2(acc[mi][ni][2], acc[mi][ni][3]);
        }
    }
}

// ================= HMMA flash attention (1-term QK, split ctx out) ==========
#define AS_Q 0
#define AS_STG 8192
#define AS_KH 0
#define AS_VT 8192
#define AS_BIAS 16384
#define AS_STGSZ 17408
#define AT_SMEM (AS_STG + 2*AS_STGSZ)   // 43008

__global__ void __launch_bounds__(128) attn_hmma(
    const int* __restrict__ qt_ids, const int* __restrict__ nv,
    const __nv_bfloat16* __restrict__ Qs,
    const __nv_bfloat16* __restrict__ Ks,
    const __nv_bfloat16* __restrict__ Vt,
    const float* __restrict__ biasg,
    __nv_bfloat16* __restrict__ ctxh, __nv_bfloat16* __restrict__ ctxl) {
    extern __shared__ char sm[];
    uint32_t sb = smem_u32(sm);
    int tid = threadIdx.x, w = tid >> 5, lane = tid & 31;
    int q0 = blockIdx.x * 64, h = blockIdx.y, b = blockIdx.z;
    int group = lane >> 2, qp = lane & 3;
    int q8 = lane >> 3, ln8 = lane & 7;
    int ntiles = (nv[b] + 63) >> 6;

    // load Q tile into swizzled smem
    #pragma unroll
    for (int s = 0; s < 4; s++) {
        int idx = tid + s * 128;
        int r = idx >> 3, ch = idx & 7;
        size_t go = (size_t)(b * NQ + q0 + r) * HID + h * 64 + ch * 8;
        uint32_t off = (uint32_t)r * 128 + (uint32_t)((ch ^ (r & 7)) * 16);
        *(uint4*)(sm + AS_Q + off) = *(const uint4*)(Qs + go);
    }

    auto load_stage = [&](int t, int st) {
        int k0 = t * 64;
        uint32_t so = sb + AS_STG + st * AS_STGSZ;
        #pragma unroll
        for (int s = 0; s < 8; s++) {
            int idx = tid + s * 128;
            int m = idx >> 9;
            int rc = idx & 511;
            int r = rc >> 3, ch = rc & 7;
            uint32_t off = so + m * 8192 + (uint32_t)r * 128 + (uint32_t)((ch ^ (r & 7)) * 16);
            const __nv_bfloat16* src;
            if (m == 0) src = Ks + (size_t)(b * NK + k0 + r) * HID + h * 64 + ch * 8;
            else        src = Vt + (size_t)((b * HEADS + h) * 64 + r) * NK + k0 + ch * 8;
            CP_ASYNC16(off, src);
        }
        if (tid < 48) {
            int qt = tid >> 4, j = tid & 15;
            CP_ASYNC16(so + AS_BIAS + qt * 256 + j * 16,
                       biasg + (size_t)(b * 3 + qt) * NK + k0 + j * 4);
        }
        CP_COMMIT();
    };

    load_stage(0, 0);
    __syncthreads();

    uint32_t QHf[4][4];
    #pragma unroll
    for (int c2 = 0; c2 < 4; c2++) {
        int r = w * 16 + (lane & 15);
        int ch = c2 * 2 + (lane >> 4);
        uint32_t off = (uint32_t)r * 128 + (uint32_t)((ch ^ (r & 7)) * 16);
        ldsm4(QHf[c2], sb + AS_Q + off);
    }
    int qtA = qt_ids[q0 + w * 16 + group];
    int qtB = qt_ids[q0 + w * 16 + group + 8];

    float acc[8][4];
    #pragma unroll
    for (int i = 0; i < 8; i++)
        #pragma unroll
        for (int j = 0; j < 4; j++) acc[i][j] = 0.f;
    float lA = 0.f, lB = 0.f;

    for (int t = 0; t < ntiles; t++) {
        if (t + 1 < ntiles) { load_stage(t + 1, (t + 1) & 1); CP_WAIT1(); }
        else                { CP_WAIT0(); }
        __syncthreads();
        uint32_t st = sb + AS_STG + (t & 1) * AS_STGSZ;
        char*    stc = sm + AS_STG + (t & 1) * AS_STGSZ;

        // ---- S = Q K^T (bf16 1-term, log2 domain) ----
        float S[8][4];
        #pragma unroll
        for (int np = 0; np < 4; np++) {
            #pragma unroll
            for (int j = 0; j < 4; j++) { S[2*np][j] = 0.f; S[2*np+1][j] = 0.f; }
            #pragma unroll
            for (int c2 = 0; c2 < 4; c2++) {
                int row = np * 16 + (q8 >> 1) * 8 + ln8;
                int ch = c2 * 2 + (q8 & 1);
                uint32_t off = (uint32_t)row * 128 + (uint32_t)((ch ^ (row & 7)) * 16);
                uint32_t kh[4];
                ldsm4(kh, st + AS_KH + off);
                mma16816(S[2*np],   QHf[c2], &kh[0]);
                mma16816(S[2*np+1], QHf[c2], &kh[2]);
            }
        }

        // ---- p = 2^(S + bias') (fixed max M0 folded into bias) ----
        const float* bA = (const float*)(stc + AS_BIAS) + qtA * 64;
        const float* bB = (const float*)(stc + AS_BIAS) + qtB * 64;
        uint32_t P[4][4];
        #pragma unroll
        for (int kc = 0; kc < 4; kc++) {
            int t0 = kc * 2, t1 = t0 + 1;
            float2 a0 = *(const float2*)(bA + t0 * 8 + qp * 2);
            float2 b0 = *(const float2*)(bB + t0 * 8 + qp * 2);
            float2 a1 = *(const float2*)(bA + t1 * 8 + qp * 2);
            float2 b1 = *(const float2*)(bB + t1 * 8 + qp * 2);
            float p00 = exp2m(S[t0][0] + a0.x), p01 = exp2m(S[t0][1] + a0.y);
            float p02 = exp2m(S[t0][2] + b0.x), p03 = exp2m(S[t0][3] + b0.y);
            float p10 = exp2m(S[t1][0] + a1.x), p11 = exp2m(S[t1][1] + a1.y);
            float p12 = exp2m(S[t1][2] + b1.x), p13 = exp2m(S[t1][3] + b1.y);
            lA += p00 + p01 + p10 + p11;
            lB += p02 + p03 + p12 + p13;
            __nv_bfloat162 tt;
            tt = __floats2bfloat162_rn(p00, p01); P[kc][0] = *(uint32_t*)&tt;
            tt = __floats2bfloat162_rn(p02, p03); P[kc][1] = *(uint32_t*)&tt;
            tt = __floats2bfloat162_rn(p10, p11); P[kc][2] = *(uint32_t*)&tt;
            tt = __floats2bfloat162_rn(p12, p13); P[kc][3] = *(uint32_t*)&tt;
        }

        // ---- acc += P @ V ----
        #pragma unroll
        for (int kc = 0; kc < 4; kc++) {
            #pragma unroll
            for (int tdp = 0; tdp < 4; tdp++) {
                int row = tdp * 16 + (q8 >> 1) * 8 + ln8;
                int ch = kc * 2 + (q8 & 1);
                uint32_t off = (uint32_t)row * 128 + (uint32_t)((ch ^ (row & 7)) * 16);
                uint32_t v4[4];
                ldsm4(v4, st + AS_VT + off);
                mma16816(acc[2*tdp],   P[kc], &v4[0]);
                mma16816(acc[2*tdp+1], P[kc], &v4[2]);
            }
        }
        __syncthreads();
    }

    lA += __shfl_xor_sync(0xffffffffu, lA, 1);
    lA += __shfl_xor_sync(0xffffffffu, lA, 2);
    lB += __shfl_xor_sync(0xffffffffu, lB, 1);
    lB += __shfl_xor_sync(0xffffffffu, lB, 2);
    float iA = 1.f / lA, iB = 1.f / lB;

    int rowA = q0 + w * 16 + group, rowB = rowA + 8;
    #pragma unroll
    for (int td = 0; td < 8; td++) {
        int col = h * 64 + td * 8 + qp * 2;
        float v0 = acc[td][0] * iA, v1 = acc[td][1] * iA;
        float v2 = acc[td][2] * iB, v3 = acc[td][3] * iB;
        __nv_bfloat16 h0,h1,h2,h3,l0,l1,l2,l3;
        split_bf16(v0,h0,l0); split_bf16(v1,h1,l1);
        split_bf16(v2,h2,l2); split_bf16(v3,h3,l3);
        size_t oA = (size_t)(b * NQ + rowA) * HID + col;
        size_t oB = (size_t)(b * NQ + rowB) * HID + col;
        *(__nv_bfloat162*)&ctxh[oA] = __nv_bfloat162(h0, h1);
        *(__nv_bfloat162*)&ctxl[oA] = __nv_bfloat162(l0, l1);
        *(__nv_bfloat162*)&ctxh[oB] = __nv_bfloat162(h2, h3);
        *(__nv_bfloat162*)&ctxl[oB] = __nv_bfloat162(l2, l3);
    }
}

// ---------------- launch ----------------------------------------------------
extern "C" void kernel_launch(void* const* d_in, const int* in_sizes, int n_in,
                              void* d_out, int out_size) {
    const float* queries = (const float*)d_in[0];
    const float* kv      = (const float*)d_in[1];
    const int*   qt_ids  = (const int*)d_in[2];
    const int*   kt_ids  = (const int*)d_in[3];
    const int*   pad     = (const int*)d_in[4];
    const float* Wq   = (const float*)d_in[5];
    const float* Wk   = (const float*)d_in[6];
    const float* Wv   = (const float*)d_in[7];
    const float* Wo   = (const float*)d_in[8];
    const float* qn_w = (const float*)d_in[9];
    const float* qn_b = (const float*)d_in[10];
    const float* kvn_w = (const float*)d_in[11];
    const float* kvn_b = (const float*)d_in[12];
    const float* on_w = (const float*)d_in[13];
    const float* on_b = (const float*)d_in[14];
    const float* tb   = (const float*)d_in[15];
    float* out = (float*)d_out;

    float *p_o, *p_bias;
    int *p_nv, *p_cidx;
    __nv_bfloat16 *p_qn, *p_kvn, *p_wq, *p_wk, *p_wv, *p_wo_h, *p_wo_l;
    __nv_bfloat16 *p_qs, *p_ks, *p_vt, *p_ctx_h, *p_ctx_l;
    cudaGetSymbolAddress((void**)&p_o,    g_o);
    cudaGetSymbolAddress((void**)&p_bias, g_bias);
    cudaGetSymbolAddress((void**)&p_nv,   g_nv);
    cudaGetSymbolAddress((void**)&p_cidx, g_cidx);
    cudaGetSymbolAddress((void**)&p_qn,   g_qn);
    cudaGetSymbolAddress((void**)&p_kvn,  g_kvn);
    cudaGetSymbolAddress((void**)&p_wq,   g_wq_h);
    cudaGetSymbolAddress((void**)&p_wk,   g_wk_h);
    cudaGetSymbolAddress((void**)&p_wv,   g_wv_h);
    cudaGetSymbolAddress((void**)&p_wo_h, g_wo_h);
    cudaGetSymbolAddress((void**)&p_wo_l, g_wo_l);
    cudaGetSymbolAddress((void**)&p_qs,   g_qs);
    cudaGetSymbolAddress((void**)&p_ks,   g_ks);
    cudaGetSymbolAddress((void**)&p_vt,   g_vt);
    cudaGetSymbolAddress((void**)&p_ctx_h, g_ctx_h);
    cudaGetSymbolAddress((void**)&p_ctx_l, g_ctx_l);

    static int attr_set = 0;
    if (!attr_set) {
        cudaFuncSetAttribute(gemm1<0,false>, cudaFuncAttributeMaxDynamicSharedMemorySize, G1_SMEM);
        cudaFuncSetAttribute(gemm1<1,true>,  cudaFuncAttributeMaxDynamicSharedMemorySize, G1_SMEM);
        cudaFuncSetAttribute(gemm1<2,true>,  cudaFuncAttributeMaxDynamicSharedMemorySize, G1_SMEM);
        cudaFuncSetAttribute(gemm3_hmma, cudaFuncAttributeMaxDynamicSharedMemorySize, GT_SMEM);
        cudaFuncSetAttribute(attn_hmma, cudaFuncAttributeMaxDynamicSharedMemorySize, AT_SMEM);
        attr_set = 1;
    }

    // 0. key compaction
    compact_kernel<<<BATCH, 1024>>>(pad, p_nv, p_cidx);

    // 1. LN -> bf16
    ln_bf16_kernel<<<MQ, 256>>>(queries, qn_w, qn_b, p_qn);
    ln_bf16_kernel<<<MK, 256>>>(kv, kvn_w, kvn_b, p_kvn);

    // 2. weight prep (one launch)
    wsplit_all<<<2048, 256>>>(Wq, Wk, Wv, Wo, p_wq, p_wk, p_wv, p_wo_h, p_wo_l);

    // 3. projections with fused epilogues
    {
        dim3 gq(HID / 64, MQ / 128);
        dim3 gk(HID / 64, MK / 128);
        gemm1<0,false><<<gq, 256, G1_SMEM>>>(p_qn, p_wq, p_qs, nullptr, nullptr);
        gemm1<1,true ><<<gk, 256, G1_SMEM>>>(p_kvn, p_wk, p_ks, p_cidx, p_nv);
        gemm1<2,true ><<<gk, 256, G1_SMEM>>>(p_kvn, p_wv, p_vt, p_cidx, p_nv);
    }

    // 4. bias table
    bias_kernel<<<(BATCH * NK + 255) / 256, 256>>>(kt_ids, p_nv, p_cidx, tb, p_bias);

    // 5. flash attention -> ctx hi/lo
    {
        dim3 ga(NQ / 64, HEADS, BATCH);
        attn_hmma<<<ga, 128, AT_SMEM>>>(qt_ids, p_nv, p_qs, p_ks, p_vt, p_bias,
                                        p_ctx_h, p_ctx_l);
    }

    // 6. output projection (3-term)
    {
        dim3 go(HID / 64, MQ / 128);
        gemm3_hmma<<<go, 256, GT_SMEM>>>(p_ctx_h, p_ctx_l, p_wo_h, p_wo_l, p_o);
    }

    // 7. residual + LN -> d_out
    res_ln_kernel<<<MQ, 256>>>(queries, p_o, on_w, on_b, out);
}

// round 11
// speedup vs baseline: 11.5012x; 1.0257x over previous
#include <cuda_runtime.h>
#include <cuda_bf16.h>
#include <math.h>
#include <float.h>
#include <stdint.h>

#define BATCH 2
#define NQ    1024
#define NK    4096
#define HID   1024
#define HEADS 16
#define HD    64
#define LN_EPS 1e-5f
#define LOG2E 1.4426950408889634f
#define QKSCALE (0.125f * LOG2E)
#define M0    32.0f

#define MQ (BATCH*NQ)   // 2048
#define MK (BATCH*NK)   // 8192

// ---------------- scratch (__device__ globals) ------------------------------
__device__ float g_o   [MQ*HID];
__device__ float g_bias[BATCH*3*NK];
__device__ int   g_nv[BATCH];
__device__ int   g_cidx[BATCH*NK];

__device__ __nv_bfloat16 g_qn [MQ*HID];
__device__ __nv_bfloat16 g_kvn[MK*HID];
__device__ __nv_bfloat16 g_wq_h[HID*HID];
__device__ __nv_bfloat16 g_wk_h[HID*HID];
__device__ __nv_bfloat16 g_wv_h[HID*HID];
__device__ __nv_bfloat16 g_wo_h[HID*HID], g_wo_l[HID*HID];
__device__ __nv_bfloat16 g_qs [MQ*HID];
__device__ __nv_bfloat16 g_ks [MK*HID];
__device__ __nv_bfloat16 g_vt [MK*HID];       // [(b*H+h)*64 + d][slot]
__device__ __nv_bfloat16 g_ctx_h[MQ*HID], g_ctx_l[MQ*HID];

// ---------------- small helpers ---------------------------------------------
__device__ __forceinline__ uint32_t smem_u32(const void* p) {
    uint32_t a;
    asm("{ .reg .u64 t; cvta.to.shared.u64 t, %1; cvt.u32.u64 %0, t; }" : "=r"(a) : "l"(p));
    return a;
}

__device__ __forceinline__ void split_bf16(float x, __nv_bfloat16& h, __nv_bfloat16& l) {
    h = __float2bfloat16(x);
    l = __float2bfloat16(x - __bfloat162float(h));
}

__device__ __forceinline__ float2 block_reduce2(float a, float b, float* sh) {
    #pragma unroll
    for (int o = 16; o; o >>= 1) {
        a += __shfl_xor_sync(0xffffffffu, a, o);
        b += __shfl_xor_sync(0xffffffffu, b, o);
    }
    int w = threadIdx.x >> 5;
    if ((threadIdx.x & 31) == 0) { sh[w] = a; sh[8 + w] = b; }
    __syncthreads();
    if (threadIdx.x == 0) {
        float sa = 0.f, sb = 0.f;
        #pragma unroll
        for (int i = 0; i < 8; i++) { sa += sh[i]; sb += sh[8 + i]; }
        sh[0] = sa; sh[8] = sb;
    }
    __syncthreads();
    return make_float2(sh[0], sh[8]);
}

#define CP_ASYNC16(dst, src) \
    asm volatile("cp.async.cg.shared.global [%0], [%1], 16;" :: "r"(dst), "l"(src))
#define CP_COMMIT() asm volatile("cp.async.commit_group;" ::: "memory")
#define CP_WAIT0()  asm volatile("cp.async.wait_group 0;" ::: "memory")
#define CP_WAIT1()  asm volatile("cp.async.wait_group 1;" ::: "memory")

__device__ __forceinline__ void ldsm4(uint32_t* r, uint32_t addr) {
    asm volatile("ldmatrix.sync.aligned.m8n8.x4.shared.b16 {%0,%1,%2,%3}, [%4];"
                 : "=r"(r[0]), "=r"(r[1]), "=r"(r[2]), "=r"(r[3]) : "r"(addr));
}

__device__ __forceinline__ void mma16816(float* c, const uint32_t* a, const uint32_t* b) {
    asm volatile(
        "mma.sync.aligned.m16n8k16.row.col.f32.bf16.bf16.f32 "
        "{%0,%1,%2,%3}, {%4,%5,%6,%7}, {%8,%9}, {%0,%1,%2,%3};"
        : "+f"(c[0]), "+f"(c[1]), "+f"(c[2]), "+f"(c[3])
        : "r"(a[0]), "r"(a[1]), "r"(a[2]), "r"(a[3]), "r"(b[0]), "r"(b[1]));
}

// fast 2^x for x <= 0 (clamped at -80), magic-rounding + deg-4 poly
__device__ __forceinline__ float exp2m(float x) {
    x = fmaxf(x, -80.f);
    float t = __fadd_rn(x, 12582912.f);
    float r = __fadd_rn(t, -12582912.f);
    float f = x - r;
    int   n = __float_as_int(t) - 0x4B400000;
    float p = 9.6181291e-3f;
    p = fmaf(p, f, 5.5504109e-2f);
    p = fmaf(p, f, 2.4022651e-1f);
    p = fmaf(p, f, 6.9314718e-1f);
    p = fmaf(p, f, 1.0f);
    return __int_as_float((n + 127) << 23) * p;
}

// ------------- key compaction + fused bias table (one block per batch) -------
__global__ void compact_bias_kernel(const int* __restrict__ pad,
                                    const int* __restrict__ kt,
                                    const float* __restrict__ tb,
                                    int* __restrict__ nv, int* __restrict__ cidx,
                                    float* __restrict__ bias) {
    __shared__ int wsum[32];
    __shared__ float tbl[9];
    int b = blockIdx.x, tid = threadIdx.x;
    int lane = tid & 31, w = tid >> 5;
    int base = b * NK;
    if (tid < 9) tbl[tid] = tb[tid] * LOG2E - M0;
    int k0 = tid * 4;
    int f0 = pad[base + k0 + 0] != 0;
    int f1 = pad[base + k0 + 1] != 0;
    int f2 = pad[base + k0 + 2] != 0;
    int f3 = pad[base + k0 + 3] != 0;
    int c = f0 + f1 + f2 + f3;
    int inc = c;
    #pragma unroll
    for (int o = 1; o < 32; o <<= 1) {
        int t = __shfl_up_sync(0xffffffffu, inc, o);
        if (lane >= o) inc += t;
    }
    if (lane == 31) wsum[w] = inc;
    __syncthreads();
    if (w == 0) {
        int v = wsum[lane];
        #pragma unroll
        for (int o = 1; o < 32; o <<= 1) {
            int t = __shfl_up_sync(0xffffffffu, v, o);
            if (lane >= o) v += t;
        }
        wsum[lane] = v;
    }
    __syncthreads();
    int pos = inc - c + (w ? wsum[w - 1] : 0);
    if (f0) cidx[base + pos++] = k0 + 0;
    if (f1) cidx[base + pos++] = k0 + 1;
    if (f2) cidx[base + pos++] = k0 + 2;
    if (f3) cidx[base + pos++] = k0 + 3;
    int total = wsum[31];
    if (tid == 0) nv[b] = total;
    for (int s = total + tid; s < NK; s += 1024) cidx[base + s] = 0;
    __syncthreads();
    // fused bias table in compacted order
    for (int s = tid; s < NK; s += 1024) {
        float t0, t1, t2;
        if (s < total) {
            int cc = kt[cidx[base + s]];
            t0 = tbl[cc]; t1 = tbl[3 + cc]; t2 = tbl[6 + cc];
        } else {
            t0 = t1 = t2 = -1e30f;
        }
        bias[(size_t)(b * 3 + 0) * NK + s] = t0;
        bias[(size_t)(b * 3 + 1) * NK + s] = t1;
        bias[(size_t)(b * 3 + 2) * NK + s] = t2;
    }
}

// ---------------- merged LayerNorm (queries + kv) -> bf16 --------------------
__global__ void ln_bf16_all(const float* __restrict__ xq, const float* __restrict__ xk,
                            const float* __restrict__ qw, const float* __restrict__ qb,
                            const float* __restrict__ kw, const float* __restrict__ kb,
                            __nv_bfloat16* __restrict__ oq, __nv_bfloat16* __restrict__ ok) {
    __shared__ float sh[16];
    size_t row = blockIdx.x;
    const float* x; const float* w; const float* b; __nv_bfloat16* oh;
    if (row < MQ) { x = xq + row * HID; w = qw; b = qb; oh = oq + row * HID; }
    else { size_t r2 = row - MQ; x = xk + r2 * HID; w = kw; b = kb; oh = ok + r2 * HID; }
    float4 v = ((const float4*)x)[threadIdx.x];
    float s  = v.x + v.y + v.z + v.w;
    float s2 = v.x*v.x + v.y*v.y + v.z*v.z + v.w*v.w;
    float2 r = block_reduce2(s, s2, sh);
    float mean = r.x * (1.f / HID);
    float var  = r.y * (1.f / HID) - mean * mean;
    float rstd = rsqrtf(var + LN_EPS);
    float4 wv = ((const float4*)w)[threadIdx.x];
    float4 bv = ((const float4*)b)[threadIdx.x];
    float o0 = (v.x - mean) * rstd * wv.x + bv.x;
    float o1 = (v.y - mean) * rstd * wv.y + bv.y;
    float o2 = (v.z - mean) * rstd * wv.z + bv.z;
    float o3 = (v.w - mean) * rstd * wv.w + bv.w;
    __nv_bfloat162* ph = (__nv_bfloat162*)(oh + threadIdx.x * 4);
    ph[0] = __floats2bfloat162_rn(o0, o1);
    ph[1] = __floats2bfloat162_rn(o2, o3);
}

// ---------------- merged weight splits: Wq/Wk/Wv hi; Wo hi+lo ----------------
__global__ void wsplit_all(const float* __restrict__ w0, const float* __restrict__ w1,
                           const float* __restrict__ w2, const float* __restrict__ w3,
                           __nv_bfloat16* __restrict__ h0, __nv_bfloat16* __restrict__ h1,
                           __nv_bfloat16* __restrict__ h2, __nv_bfloat16* __restrict__ h3,
                           __nv_bfloat16* __restrict__ l3) {
    int wi = blockIdx.x >> 9;
    int blk = blockIdx.x & 511;
    const float* src = (wi == 0) ? w0 : (wi == 1) ? w1 : (wi == 2) ? w2 : w3;
    __nv_bfloat16* dh = (wi == 0) ? h0 : (wi == 1) ? h1 : (wi == 2) ? h2 : h3;
    const int n4 = HID * HID / 4;
    for (int i = blk * 256 + threadIdx.x; i < n4; i += 512 * 256) {
        float4 v = ((const float4*)src)[i];
        __nv_bfloat16 a0,a1,a2,a3,b0,b1,b2,b3;
        split_bf16(v.x,a0,b0); split_bf16(v.y,a1,b1);
        split_bf16(v.z,a2,b2); split_bf16(v.w,a3,b3);
        __nv_bfloat162* ph = (__nv_bfloat162*)(dh + (size_t)i * 4);
        ph[0] = __nv_bfloat162(a0, a1); ph[1] = __nv_bfloat162(a2, a3);
        if (wi == 3) {
            __nv_bfloat162* pl = (__nv_bfloat162*)(l3 + (size_t)i * 4);
            pl[0] = __nv_bfloat162(b0, b1); pl[1] = __nv_bfloat162(b2, b3);
        }
    }
}

// -------- residual + LayerNorm -----------------------------------------------
__global__ void res_ln_kernel(const float* __restrict__ x,
                              const float* __restrict__ y,
                              const float* __restrict__ w,
                              const float* __restrict__ b,
                              float* __restrict__ out) {
    __shared__ float sh[16];
    size_t row = blockIdx.x;
    float4 v  = ((const float4*)(x + row * HID))[threadIdx.x];
    float4 yv = ((const float4*)(y + row * HID))[threadIdx.x];
    v.x += yv.x; v.y += yv.y; v.z += yv.z; v.w += yv.w;
    float s  = v.x + v.y + v.z + v.w;
    float s2 = v.x*v.x + v.y*v.y + v.z*v.z + v.w*v.w;
    float2 r = block_reduce2(s, s2, sh);
    float mean = r.x * (1.f / HID);
    float var  = r.y * (1.f / HID) - mean * mean;
    float rstd = rsqrtf(var + LN_EPS);
    float4 wv = ((const float4*)w)[threadIdx.x];
    float4 bv = ((const float4*)b)[threadIdx.x];
    float4 o;
    o.x = (v.x - mean) * rstd * wv.x + bv.x;
    o.y = (v.y - mean) * rstd * wv.y + bv.y;
    o.z = (v.z - mean) * rstd * wv.z + bv.z;
    o.w = (v.w - mean) * rstd * wv.w + bv.w;
    ((float4*)(out + row * HID))[threadIdx.x] = o;
}

// ================= 1-term bf16 HMMA GEMM with fused epilogues ================
#define G1_A 0
#define G1_B 16384
#define G1_STG 24576
#define G1_SMEM 49152

template<int EPI, bool IDX>
__global__ void __launch_bounds__(256, 2) gemm1(
    const __nv_bfloat16* __restrict__ A, const __nv_bfloat16* __restrict__ B,
    __nv_bfloat16* __restrict__ Cb,
    const int* __restrict__ cidx, const int* __restrict__ nv) {
    extern __shared__ char sm[];
    uint32_t sb = smem_u32(sm);
    int tid = threadIdx.x;
    int wid = tid >> 5, lane = tid & 31;
    int wm = wid >> 1, wn = wid & 1;
    int rowBase = blockIdx.y * 128;
    int colBase = blockIdx.x * 64;
    int q = lane >> 3, ln8 = lane & 7;

    int bb = 0;
    if (IDX) {
        bb = rowBase / NK;
        int slot0 = rowBase % NK;
        if (slot0 >= ((nv[bb] + 63) & ~63)) return;
    }

    const __nv_bfloat16* pA[4];
    #pragma unroll
    for (int s = 0; s < 4; s++) {
        int row = (tid >> 3) + 32 * s;
        if (IDX) {
            int slot = (rowBase % NK) + row;
            int ar = cidx[bb * NK + slot];
            pA[s] = A + (size_t)(bb * NK + ar) * HID + (tid & 7) * 8;
        } else {
            pA[s] = A + (size_t)(rowBase + row) * HID + (tid & 7) * 8;
        }
    }

    float acc[2][4][4];
    #pragma unroll
    for (int i = 0; i < 2; i++)
        #pragma unroll
        for (int j = 0; j < 4; j++)
            #pragma unroll
            for (int r = 0; r < 4; r++) acc[i][j][r] = 0.f;

    auto load_chunk = [&](int c, int st) {
        int k0 = c * 64;
        uint32_t so = sb + st * G1_STG;
        #pragma unroll
        for (int s = 0; s < 4; s++) {
            int row = (tid >> 3) + 32 * s, ch = tid & 7;
            uint32_t off = (uint32_t)row * 128 + (uint32_t)((ch ^ (row & 7)) * 16);
            CP_ASYNC16(so + G1_A + off, pA[s] + k0);
        }
        #pragma unroll
        for (int s = 0; s < 2; s++) {
            int idx = tid + s * 256;
            int row = idx >> 3, ch = idx & 7;
            uint32_t off = (uint32_t)row * 128 + (uint32_t)((ch ^ (row & 7)) * 16);
            CP_ASYNC16(so + G1_B + off, B + (size_t)(colBase + row) * HID + k0 + ch * 8);
        }
        CP_COMMIT();
    };

    load_chunk(0, 0);

    for (int c = 0; c < 16; c++) {
        if (c < 15) { load_chunk(c + 1, (c + 1) & 1); CP_WAIT1(); }
        else        { CP_WAIT0(); }
        __syncthreads();

        uint32_t Ab = sb + (c & 1) * G1_STG + G1_A;
        uint32_t Bb = sb + (c & 1) * G1_STG + G1_B;
        #pragma unroll
        for (int ti = 0; ti < 4; ti++) {
            uint32_t af[2][4];
            #pragma unroll
            for (int mi = 0; mi < 2; mi++) {
                int row = wm * 32 + mi * 16 + (q & 1) * 8 + ln8;
                int ch = ti * 2 + (q >> 1);
                ldsm4(af[mi], Ab + row * 128 + ((ch ^ (row & 7)) * 16));
            }
            uint32_t bf[2][4];
            #pragma unroll
            for (int g = 0; g < 2; g++) {
                int row = wn * 32 + g * 16 + (q >> 1) * 8 + ln8;
                int ch = ti * 2 + (q & 1);
                ldsm4(bf[g], Bb + row * 128 + ((ch ^ (row & 7)) * 16));
            }
            #pragma unroll
            for (int mi = 0; mi < 2; mi++) {
                mma16816(acc[mi][0], af[mi], &bf[0][0]);
                mma16816(acc[mi][1], af[mi], &bf[0][2]);
                mma16816(acc[mi][2], af[mi], &bf[1][0]);
                mma16816(acc[mi][3], af[mi], &bf[1][2]);
            }
        }
        __syncthreads();
    }

    if (EPI < 2) {
        const float sc = (EPI == 0) ? QKSCALE : 1.0f;
        int r0 = rowBase + wm * 32 + (lane >> 2);
        int c0 = colBase + wn * 32 + (lane & 3) * 2;
        #pragma unroll
        for (int mi = 0; mi < 2; mi++) {
            #pragma unroll
            for (int ni = 0; ni < 4; ni++) {
                int rr = r0 + mi * 16;
                int cc = c0 + ni * 8;
                *(__nv_bfloat162*)&Cb[(size_t)rr * HID + cc] =
                    __floats2bfloat162_rn(acc[mi][ni][0] * sc, acc[mi][ni][1] * sc);
                *(__nv_bfloat162*)&Cb[(size_t)(rr + 8) * HID + cc] =
                    __floats2bfloat162_rn(acc[mi][ni][2] * sc, acc[mi][ni][3] * sc);
            }
        }
    } else {
        float* ts = (float*)sm;
        int r0l = wm * 32 + (lane >> 2);
        int c0l = wn * 32 + (lane & 3) * 2;
        #pragma unroll
        for (int mi = 0; mi < 2; mi++) {
            #pragma unroll
            for (int ni = 0; ni < 4; ni++) {
                int rr = r0l + mi * 16, cc = c0l + ni * 8;
                ts[rr * 65 + cc] = acc[mi][ni][0];
                ts[rr * 65 + cc + 1] = acc[mi][ni][1];
                ts[(rr + 8) * 65 + cc] = acc[mi][ni][2];
                ts[(rr + 8) * 65 + cc + 1] = acc[mi][ni][3];
            }
        }
        __syncthreads();
        int hh = blockIdx.x;
        int slot0 = rowBase % NK;
        int d = tid >> 2, kb = (tid & 3) * 32;
        __nv_bfloat16* dst = Cb + (size_t)((bb * HEADS + hh) * 64 + d) * NK + slot0 + kb;
        #pragma unroll
        for (int k = 0; k < 32; k += 2) {
            *(__nv_bfloat162*)(dst + k) =
                __floats2bfloat162_rn(ts[(kb + k) * 65 + d], ts[(kb + k + 1) * 65 + d]);
        }
    }
}

// ================= 3-term split GEMM (O projection, fp32 out) ===============
#define STG_AH 0
#define STG_AL 16384
#define STG_BH 32768
#define STG_BL 40960
#define STAGE_SZ 49152
#define GT_SMEM (2*STAGE_SZ)

__global__ void __launch_bounds__(256, 2) gemm3_hmma(
    const __nv_bfloat16* __restrict__ Ah, const __nv_bfloat16* __restrict__ Al,
    const __nv_bfloat16* __restrict__ Bh, const __nv_bfloat16* __restrict__ Bl,
    float* __restrict__ C) {
    extern __shared__ char sm[];
    uint32_t sb = smem_u32(sm);
    int tid = threadIdx.x;
    int wid = tid >> 5, lane = tid & 31;
    int wm = wid >> 1, wn = wid & 1;
    int rowBase = blockIdx.y * 128;
    int colBase = blockIdx.x * 64;
    int q = lane >> 3, ln8 = lane & 7;

    float acc[2][4][4];
    #pragma unroll
    for (int i = 0; i < 2; i++)
        #pragma unroll
        for (int j = 0; j < 4; j++)
            #pragma unroll
            for (int r = 0; r < 4; r++) acc[i][j][r] = 0.f;

    auto load_chunk = [&](int c, int st) {
        int k0 = c * 64;
        uint32_t so = sb + st * STAGE_SZ;
        #pragma unroll
        for (int s = 0; s < 4; s++) {
            int idx = tid + s * 256;
            int row = idx >> 3, ch = idx & 7;
            uint32_t off = (uint32_t)row * 128 + (uint32_t)((ch ^ (row & 7)) * 16);
            CP_ASYNC16(so + STG_AH + off, Ah + (size_t)(rowBase + row) * HID + k0 + ch * 8);
            CP_ASYNC16(so + STG_AL + off, Al + (size_t)(rowBase + row) * HID + k0 + ch * 8);
        }
        #pragma unroll
        for (int s = 0; s < 2; s++) {
            int idx = tid + s * 256;
            int row = idx >> 3, ch = idx & 7;
            uint32_t off = (uint32_t)row * 128 + (uint32_t)((ch ^ (row & 7)) * 16);
            CP_ASYNC16(so + STG_BH + off, Bh + (size_t)(colBase + row) * HID + k0 + ch * 8);
            CP_ASYNC16(so + STG_BL + off, Bl + (size_t)(colBase + row) * HID + k0 + ch * 8);
        }
        CP_COMMIT();
    };

    load_chunk(0, 0);

    for (int c = 0; c < 16; c++) {
        if (c < 15) { load_chunk(c + 1, (c + 1) & 1); CP_WAIT1(); }
        else        { CP_WAIT0(); }
        __syncthreads();

        uint32_t stBase = sb + (c & 1) * STAGE_SZ;
        #pragma unroll
        for (int pass = 0; pass < 3; pass++) {
            uint32_t Ab = stBase + ((pass < 2) ? STG_AH : STG_AL);
            uint32_t Bb = stBase + ((pass == 1) ? STG_BL : STG_BH);
            #pragma unroll
            for (int ti = 0; ti < 4; ti++) {
                uint32_t af[2][4];
                #pragma unroll
                for (int mi = 0; mi < 2; mi++) {
                    int row = wm * 32 + mi * 16 + (q & 1) * 8 + ln8;
                    int ch = ti * 2 + (q >> 1);
                    ldsm4(af[mi], Ab + row * 128 + ((ch ^ (row & 7)) * 16));
                }
                uint32_t bf[2][4];
                #pragma unroll
                for (int g = 0; g < 2; g++) {
                    int row = wn * 32 + g * 16 + (q >> 1) * 8 + ln8;
                    int ch = ti * 2 + (q & 1);
                    ldsm4(bf[g], Bb + row * 128 + ((ch ^ (row & 7)) * 16));
                }
                #pragma unroll
                for (int mi = 0; mi < 2; mi++) {
                    mma16816(acc[mi][0], af[mi], &bf[0][0]);
                    mma16816(acc[mi][1], af[mi], &bf[0][2]);
                    mma16816(acc[mi][2], af[mi], &bf[1][0]);
                    mma16816(acc[mi][3], af[mi], &bf[1][2]);
                }
            }
        }
        __syncthreads();
    }

    int r0 = rowBase + wm * 32 + (lane >> 2);
    int c0 = colBase + wn * 32 + (lane & 3) * 2;
    #pragma unroll
    for (int mi = 0; mi < 2; mi++) {
        #pragma unroll
        for (int ni = 0; ni < 4; ni++) {
            int rr = r0 + mi * 16;
            int cc = c0 + ni * 8;
            *(float2*)&C[(size_t)rr * HID + cc] = make_float2(acc[mi][ni][0], acc[mi][ni][1]);
            *(float2*)&C[(size_t)(rr + 8) * HID + cc] = make_float2(acc[mi][ni][2], acc[mi][ni][3]);
        }
    }
}

// ================= HMMA flash attention: 128 queries/CTA, 256 threads =======
#define AS_Q 0
#define AS_STG 16384
#define AS_KH 0
#define AS_VT 8192
#define AS_BIAS 16384
#define AS_STGSZ 17408
#define AT_SMEM (AS_STG + 2*AS_STGSZ)   // 51200

__global__ void __launch_bounds__(256) attn_hmma(
    const int* __restrict__ qt_ids, const int* __restrict__ nv,
    const __nv_bfloat16* __restrict__ Qs,
    const __nv_bfloat16* __restrict__ Ks,
    const __nv_bfloat16* __restrict__ Vt,
    const float* __restrict__ biasg,
    __nv_bfloat16* __restrict__ ctxh, __nv_bfloat16* __restrict__ ctxl) {
    extern __shared__ char sm[];
    uint32_t sb = smem_u32(sm);
    int tid = threadIdx.x, w = tid >> 5, lane = tid & 31;
    int q0 = blockIdx.x * 128, h = blockIdx.y, b = blockIdx.z;
    int group = lane >> 2, qp = lane & 3;
    int q8 = lane >> 3, ln8 = lane & 7;
    int ntiles = (nv[b] + 63) >> 6;

    // load 128-row Q tile into swizzled smem (1024 uint4 / 256 threads)
    #pragma unroll
    for (int s = 0; s < 4; s++) {
        int idx = tid + s * 256;
        int r = idx >> 3, ch = idx & 7;
        size_t go = (size_t)(b * NQ + q0 + r) * HID + h * 64 + ch * 8;
        uint32_t off = (uint32_t)r * 128 + (uint32_t)((ch ^ (r & 7)) * 16);
        *(uint4*)(sm + AS_Q + off) = *(const uint4*)(Qs + go);
    }

    auto load_stage = [&](int t, int st) {
        int k0 = t * 64;
        uint32_t so = sb + AS_STG + st * AS_STGSZ;
        #pragma unroll
        for (int s = 0; s < 4; s++) {
            int idx = tid + s * 256;
            int m = idx >> 9;
            int rc = idx & 511;
            int r = rc >> 3, ch = rc & 7;
            uint32_t off = so + m * 8192 + (uint32_t)r * 128 + (uint32_t)((ch ^ (r & 7)) * 16);
            const __nv_bfloat16* src;
            if (m == 0) src = Ks + (size_t)(b * NK + k0 + r) * HID + h * 64 + ch * 8;
            else        src = Vt + (size_t)((b * HEADS + h) * 64 + r) * NK + k0 + ch * 8;
            CP_ASYNC16(off, src);
        }
        if (tid < 48) {
            int qt = tid >> 4, j = tid & 15;
            CP_ASYNC16(so + AS_BIAS + qt * 256 + j * 16,
                       biasg + (size_t)(b * 3 + qt) * NK + k0 + j * 4);
        }
        CP_COMMIT();
    };

    load_stage(0, 0);
    __syncthreads();

    uint32_t QHf[4][4];
    #pragma unroll
    for (int c2 = 0; c2 < 4; c2++) {
        int r = w * 16 + (lane & 15);
        int ch = c2 * 2 + (lane >> 4);
        uint32_t off = (uint32_t)r * 128 + (uint32_t)((ch ^ (r & 7)) * 16);
        ldsm4(QHf[c2], sb + AS_Q + off);
    }
    int qtA = qt_ids[q0 + w * 16 + group];
    int qtB = qt_ids[q0 + w * 16 + group + 8];

    float acc[8][4];
    #pragma unroll
    for (int i = 0; i < 8; i++)
        #pragma unroll
        for (int j = 0; j < 4; j++) acc[i][j] = 0.f;
    float lA = 0.f, lB = 0.f;

    for (int t = 0; t < ntiles; t++) {
        if (t + 1 < ntiles) { load_stage(t + 1, (t + 1) & 1); CP_WAIT1(); }
        else                { CP_WAIT0(); }
        __syncthreads();
        uint32_t st = sb + AS_STG + (t & 1) * AS_STGSZ;
        char*    stc = sm + AS_STG + (t & 1) * AS_STGSZ;

        // ---- S = Q K^T (bf16, log2 domain) ----
        float S[8][4];
        #pragma unroll
        for (int np = 0; np < 4; np++) {
            #pragma unroll
            for (int j = 0; j < 4; j++) { S[2*np][j] = 0.f; S[2*np+1][j] = 0.f; }
            #pragma unroll
            for (int c2 = 0; c2 < 4; c2++) {
                int row = np * 16 + (q8 >> 1) * 8 + ln8;
                int ch = c2 * 2 + (q8 & 1);
                uint32_t off = (uint32_t)row * 128 + (uint32_t)((ch ^ (row & 7)) * 16);
                uint32_t kh[4];
                ldsm4(kh, st + AS_KH + off);
                mma16816(S[2*np],   QHf[c2], &kh[0]);
                mma16816(S[2*np+1], QHf[c2], &kh[2]);
            }
        }

        // ---- p = 2^(S + bias') ----
        const float* bA = (const float*)(stc + AS_BIAS) + qtA * 64;
        const float* bB = (const float*)(stc + AS_BIAS) + qtB * 64;
        uint32_t P[4][4];
        #pragma unroll
        for (int kc = 0; kc < 4; kc++) {
            int t0 = kc * 2, t1 = t0 + 1;
            float2 a0 = *(const float2*)(bA + t0 * 8 + qp * 2);
            float2 b0 = *(const float2*)(bB + t0 * 8 + qp * 2);
            float2 a1 = *(const float2*)(bA + t1 * 8 + qp * 2);
            float2 b1 = *(const float2*)(bB + t1 * 8 + qp * 2);
            float p00 = exp2m(S[t0][0] + a0.x), p01 = exp2m(S[t0][1] + a0.y);
            float p02 = exp2m(S[t0][2] + b0.x), p03 = exp2m(S[t0][3] + b0.y);
            float p10 = exp2m(S[t1][0] + a1.x), p11 = exp2m(S[t1][1] + a1.y);
            float p12 = exp2m(S[t1][2] + b1.x), p13 = exp2m(S[t1][3] + b1.y);
            lA += p00 + p01 + p10 + p11;
            lB += p02 + p03 + p12 + p13;
            __nv_bfloat162 tt;
            tt = __floats2bfloat162_rn(p00, p01); P[kc][0] = *(uint32_t*)&tt;
            tt = __floats2bfloat162_rn(p02, p03); P[kc][1] = *(uint32_t*)&tt;
            tt = __floats2bfloat162_rn(p10, p11); P[kc][2] = *(uint32_t*)&tt;
            tt = __floats2bfloat162_rn(p12, p13); P[kc][3] = *(uint32_t*)&tt;
        }

        // ---- acc += P @ V ----
        #pragma unroll
        for (int kc = 0; kc < 4; kc++) {
            #pragma unroll
            for (int tdp = 0; tdp < 4; tdp++) {
                int row = tdp * 16 + (q8 >> 1) * 8 + ln8;
                int ch = kc * 2 + (q8 & 1);
                uint32_t off = (uint32_t)row * 128 + (uint32_t)((ch ^ (row & 7)) * 16);
                uint32_t v4[4];
                ldsm4(v4, st + AS_VT + off);
                mma16816(acc[2*tdp],   P[kc], &v4[0]);
                mma16816(acc[2*tdp+1], P[kc], &v4[2]);
            }
        }
        __syncthreads();
    }

    lA += __shfl_xor_sync(0xffffffffu, lA, 1);
    lA += __shfl_xor_sync(0xffffffffu, lA, 2);
    lB += __shfl_xor_sync(0xffffffffu, lB, 1);
    lB += __shfl_xor_sync(0xffffffffu, lB, 2);
    float iA = 1.f / lA, iB = 1.f / lB;

    int rowA = q0 + w * 16 + group, rowB = rowA + 8;
    #pragma unroll
    for (int td = 0; td < 8; td++) {
        int col = h * 64 + td * 8 + qp * 2;
        float v0 = acc[td][0] * iA, v1 = acc[td][1] * iA;
        float v2 = acc[td][2] * iB, v3 = acc[td][3] * iB;
        __nv_bfloat16 h0,h1,h2,h3,l0,l1,l2,l3;
        split_bf16(v0,h0,l0); split_bf16(v1,h1,l1);
        split_bf16(v2,h2,l2); split_bf16(v3,h3,l3);
        size_t oA = (size_t)(b * NQ + rowA) * HID + col;
        size_t oB = (size_t)(b * NQ + rowB) * HID + col;
        *(__nv_bfloat162*)&ctxh[oA] = __nv_bfloat162(h0, h1);
        *(__nv_bfloat162*)&ctxl[oA] = __nv_bfloat162(l0, l1);
        *(__nv_bfloat162*)&ctxh[oB] = __nv_bfloat162(h2, h3);
        *(__nv_bfloat162*)&ctxl[oB] = __nv_bfloat162(l2, l3);
    }
}

// ---------------- launch ----------------------------------------------------
extern "C" void kernel_launch(void* const* d_in, const int* in_sizes, int n_in,
                              void* d_out, int out_size) {
    const float* queries = (const float*)d_in[0];
    const float* kv      = (const float*)d_in[1];
    const int*   qt_ids  = (const int*)d_in[2];
    const int*   kt_ids  = (const int*)d_in[3];
    const int*   pad     = (const int*)d_in[4];
    const float* Wq   = (const float*)d_in[5];
    const float* Wk   = (const float*)d_in[6];
    const float* Wv   = (const float*)d_in[7];
    const float* Wo   = (const float*)d_in[8];
    const float* qn_w = (const float*)d_in[9];
    const float* qn_b = (const float*)d_in[10];
    const float* kvn_w = (const float*)d_in[11];
    const float* kvn_b = (const float*)d_in[12];
    const float* on_w = (const float*)d_in[13];
    const float* on_b = (const float*)d_in[14];
    const float* tb   = (const float*)d_in[15];
    float* out = (float*)d_out;

    float *p_o, *p_bias;
    int *p_nv, *p_cidx;
    __nv_bfloat16 *p_qn, *p_kvn, *p_wq, *p_wk, *p_wv, *p_wo_h, *p_wo_l;
    __nv_bfloat16 *p_qs, *p_ks, *p_vt, *p_ctx_h, *p_ctx_l;
    cudaGetSymbolAddress((void**)&p_o,    g_o);
    cudaGetSymbolAddress((void**)&p_bias, g_bias);
    cudaGetSymbolAddress((void**)&p_nv,   g_nv);
    cudaGetSymbolAddress((void**)&p_cidx, g_cidx);
    cudaGetSymbolAddress((void**)&p_qn,   g_qn);
    cudaGetSymbolAddress((void**)&p_kvn,  g_kvn);
    cudaGetSymbolAddress((void**)&p_wq,   g_wq_h);
    cudaGetSymbolAddress((void**)&p_wk,   g_wk_h);
    cudaGetSymbolAddress((void**)&p_wv,   g_wv_h);
    cudaGetSymbolAddress((void**)&p_wo_h, g_wo_h);
    cudaGetSymbolAddress((void**)&p_wo_l, g_wo_l);
    cudaGetSymbolAddress((void**)&p_qs,   g_qs);
    cudaGetSymbolAddress((void**)&p_ks,   g_ks);
    cudaGetSymbolAddress((void**)&p_vt,   g_vt);
    cudaGetSymbolAddress((void**)&p_ctx_h, g_ctx_h);
    cudaGetSymbolAddress((void**)&p_ctx_l, g_ctx_l);

    static int attr_set = 0;
    if (!attr_set) {
        cudaFuncSetAttribute(gemm1<0,false>, cudaFuncAttributeMaxDynamicSharedMemorySize, G1_SMEM);
        cudaFuncSetAttribute(gemm1<1,true>,  cudaFuncAttributeMaxDynamicSharedMemorySize, G1_SMEM);
        cudaFuncSetAttribute(gemm1<2,true>,  cudaFuncAttributeMaxDynamicSharedMemorySize, G1_SMEM);
        cudaFuncSetAttribute(gemm3_hmma, cudaFuncAttributeMaxDynamicSharedMemorySize, GT_SMEM);
        cudaFuncSetAttribute(attn_hmma, cudaFuncAttributeMaxDynamicSharedMemorySize, AT_SMEM);
        attr_set = 1;
    }

    // 0. key compaction + bias table (fused)
    compact_bias_kernel<<<BATCH, 1024>>>(pad, kt_ids, tb, p_nv, p_cidx, p_bias);

    // 1. LN -> bf16 (merged)
    ln_bf16_all<<<MQ + MK, 256>>>(queries, kv, qn_w, qn_b, kvn_w, kvn_b, p_qn, p_kvn);

    // 2. weight prep (one launch)
    wsplit_all<<<2048, 256>>>(Wq, Wk, Wv, Wo, p_wq, p_wk, p_wv, p_wo_h, p_wo_l);

    // 3. projections with fused epilogues
    {
        dim3 gq(HID / 64, MQ / 128);
        dim3 gk(HID / 64, MK / 128);
        gemm1<0,false><<<gq, 256, G1_SMEM>>>(p_qn, p_wq, p_qs, nullptr, nullptr);
        gemm1<1,true ><<<gk, 256, G1_SMEM>>>(p_kvn, p_wk, p_ks, p_cidx, p_nv);
        gemm1<2,true ><<<gk, 256, G1_SMEM>>>(p_kvn, p_wv, p_vt, p_cidx, p_nv);
    }

    // 4. flash attention (128 q/CTA) -> ctx hi/lo
    {
        dim3 ga(NQ / 128, HEADS, BATCH);
        attn_hmma<<<ga, 256, AT_SMEM>>>(qt_ids, p_nv, p_qs, p_ks, p_vt, p_bias,
                                        p_ctx_h, p_ctx_l);
    }

    // 5. output projection (3-term)
    {
        dim3 go(HID / 64, MQ / 128);
        gemm3_hmma<<<go, 256, GT_SMEM>>>(p_ctx_h, p_ctx_l, p_wo_h, p_wo_l, p_o);
    }

    // 6. residual + LN -> d_out
    res_ln_kernel<<<MQ, 256>>>(queries, p_o, on_w, on_b, out);
}

// round 12
// speedup vs baseline: 13.0194x; 1.1320x over previous
#include <cuda_runtime.h>
#include <cuda_bf16.h>
#include <math.h>
#include <float.h>
#include <stdint.h>

#define BATCH 2
#define NQ    1024
#define NK    4096
#define HID   1024
#define HEADS 16
#define HD    64
#define LN_EPS 1e-5f
#define LOG2E 1.4426950408889634f
#define QKSCALE (0.125f * LOG2E)
#define M0    32.0f

#define MQ (BATCH*NQ)   // 2048
#define MK (BATCH*NK)   // 8192

// ---------------- scratch (__device__ globals) ------------------------------
__device__ float g_o   [MQ*HID];
__device__ float g_bias[BATCH*3*NK];
__device__ int   g_nv[BATCH];
__device__ int   g_cidx[BATCH*NK];

__device__ __nv_bfloat16 g_qn [MQ*HID];
__device__ __nv_bfloat16 g_kvn[MK*HID];
__device__ __nv_bfloat16 g_wq_h[HID*HID];
__device__ __nv_bfloat16 g_wk_h[HID*HID];
__device__ __nv_bfloat16 g_wv_h[HID*HID];
__device__ __nv_bfloat16 g_wo_h[HID*HID];
__device__ __nv_bfloat16 g_qs [MQ*HID];
__device__ __nv_bfloat16 g_ks [MK*HID];
__device__ __nv_bfloat16 g_vt [MK*HID];       // [(b*H+h)*64 + d][slot]
__device__ __nv_bfloat16 g_ctx_h[MQ*HID], g_ctx_l[MQ*HID];

// ---------------- small helpers ---------------------------------------------
__device__ __forceinline__ uint32_t smem_u32(const void* p) {
    uint32_t a;
    asm("{ .reg .u64 t; cvta.to.shared.u64 t, %1; cvt.u32.u64 %0, t; }" : "=r"(a) : "l"(p));
    return a;
}

__device__ __forceinline__ void split_bf16(float x, __nv_bfloat16& h, __nv_bfloat16& l) {
    h = __float2bfloat16(x);
    l = __float2bfloat16(x - __bfloat162float(h));
}

__device__ __forceinline__ float2 block_reduce2(float a, float b, float* sh) {
    #pragma unroll
    for (int o = 16; o; o >>= 1) {
        a += __shfl_xor_sync(0xffffffffu, a, o);
        b += __shfl_xor_sync(0xffffffffu, b, o);
    }
    int w = threadIdx.x >> 5;
    if ((threadIdx.x & 31) == 0) { sh[w] = a; sh[8 + w] = b; }
    __syncthreads();
    if (threadIdx.x == 0) {
        float sa = 0.f, sb = 0.f;
        #pragma unroll
        for (int i = 0; i < 8; i++) { sa += sh[i]; sb += sh[8 + i]; }
        sh[0] = sa; sh[8] = sb;
    }
    __syncthreads();
    return make_float2(sh[0], sh[8]);
}

#define CP_ASYNC16(dst, src) \
    asm volatile("cp.async.cg.shared.global [%0], [%1], 16;" :: "r"(dst), "l"(src))
#define CP_COMMIT() asm volatile("cp.async.commit_group;" ::: "memory")
#define CP_WAIT0()  asm volatile("cp.async.wait_group 0;" ::: "memory")
#define CP_WAIT1()  asm volatile("cp.async.wait_group 1;" ::: "memory")

__device__ __forceinline__ void ldsm4(uint32_t* r, uint32_t addr) {
    asm volatile("ldmatrix.sync.aligned.m8n8.x4.shared.b16 {%0,%1,%2,%3}, [%4];"
                 : "=r"(r[0]), "=r"(r[1]), "=r"(r[2]), "=r"(r[3]) : "r"(addr));
}

__device__ __forceinline__ void mma16816(float* c, const uint32_t* a, const uint32_t* b) {
    asm volatile(
        "mma.sync.aligned.m16n8k16.row.col.f32.bf16.bf16.f32 "
        "{%0,%1,%2,%3}, {%4,%5,%6,%7}, {%8,%9}, {%0,%1,%2,%3};"
        : "+f"(c[0]), "+f"(c[1]), "+f"(c[2]), "+f"(c[3])
        : "r"(a[0]), "r"(a[1]), "r"(a[2]), "r"(a[3]), "r"(b[0]), "r"(b[1]));
}

// fast 2^x for x <= 0 (clamped at -80), magic-rounding + deg-4 poly
__device__ __forceinline__ float exp2m(float x) {
    x = fmaxf(x, -80.f);
    float t = __fadd_rn(x, 12582912.f);
    float r = __fadd_rn(t, -12582912.f);
    float f = x - r;
    int   n = __float_as_int(t) - 0x4B400000;
    float p = 9.6181291e-3f;
    p = fmaf(p, f, 5.5504109e-2f);
    p = fmaf(p, f, 2.4022651e-1f);
    p = fmaf(p, f, 6.9314718e-1f);
    p = fmaf(p, f, 1.0f);
    return __int_as_float((n + 127) << 23) * p;
}

// ------------- key compaction + fused bias table (one block per batch) -------
__global__ void compact_bias_kernel(const int* __restrict__ pad,
                                    const int* __restrict__ kt,
                                    const float* __restrict__ tb,
                                    int* __restrict__ nv, int* __restrict__ cidx,
                                    float* __restrict__ bias) {
    __shared__ int wsum[32];
    __shared__ float tbl[9];
    int b = blockIdx.x, tid = threadIdx.x;
    int lane = tid & 31, w = tid >> 5;
    int base = b * NK;
    if (tid < 9) tbl[tid] = tb[tid] * LOG2E - M0;
    int k0 = tid * 4;
    int f0 = pad[base + k0 + 0] != 0;
    int f1 = pad[base + k0 + 1] != 0;
    int f2 = pad[base + k0 + 2] != 0;
    int f3 = pad[base + k0 + 3] != 0;
    int c = f0 + f1 + f2 + f3;
    int inc = c;
    #pragma unroll
    for (int o = 1; o < 32; o <<= 1) {
        int t = __shfl_up_sync(0xffffffffu, inc, o);
        if (lane >= o) inc += t;
    }
    if (lane == 31) wsum[w] = inc;
    __syncthreads();
    if (w == 0) {
        int v = wsum[lane];
        #pragma unroll
        for (int o = 1; o < 32; o <<= 1) {
            int t = __shfl_up_sync(0xffffffffu, v, o);
            if (lane >= o) v += t;
        }
        wsum[lane] = v;
    }
    __syncthreads();
    int pos = inc - c + (w ? wsum[w - 1] : 0);
    if (f0) cidx[base + pos++] = k0 + 0;
    if (f1) cidx[base + pos++] = k0 + 1;
    if (f2) cidx[base + pos++] = k0 + 2;
    if (f3) cidx[base + pos++] = k0 + 3;
    int total = wsum[31];
    if (tid == 0) nv[b] = total;
    for (int s = total + tid; s < NK; s += 1024) cidx[base + s] = 0;
    __syncthreads();
    for (int s = tid; s < NK; s += 1024) {
        float t0, t1, t2;
        if (s < total) {
            int cc = kt[cidx[base + s]];
            t0 = tbl[cc]; t1 = tbl[3 + cc]; t2 = tbl[6 + cc];
        } else {
            t0 = t1 = t2 = -1e30f;
        }
        bias[(size_t)(b * 3 + 0) * NK + s] = t0;
        bias[(size_t)(b * 3 + 1) * NK + s] = t1;
        bias[(size_t)(b * 3 + 2) * NK + s] = t2;
    }
}

// ---- merged prep: LN (queries + kv) -> bf16, then 4x weight -> bf16 hi ------
__global__ void prep_all(const float* __restrict__ xq, const float* __restrict__ xk,
                         const float* __restrict__ qw, const float* __restrict__ qb,
                         const float* __restrict__ kw, const float* __restrict__ kb,
                         const float* __restrict__ w0, const float* __restrict__ w1,
                         const float* __restrict__ w2, const float* __restrict__ w3,
                         __nv_bfloat16* __restrict__ oq, __nv_bfloat16* __restrict__ ok,
                         __nv_bfloat16* __restrict__ h0, __nv_bfloat16* __restrict__ h1,
                         __nv_bfloat16* __restrict__ h2, __nv_bfloat16* __restrict__ h3) {
    __shared__ float sh[16];
    int bid = blockIdx.x;
    if (bid < MQ + MK) {
        size_t row = bid;
        const float* x; const float* w; const float* b; __nv_bfloat16* oh;
        if (row < MQ) { x = xq + row * HID; w = qw; b = qb; oh = oq + row * HID; }
        else { size_t r2 = row - MQ; x = xk + r2 * HID; w = kw; b = kb; oh = ok + r2 * HID; }
        float4 v = ((const float4*)x)[threadIdx.x];
        float s  = v.x + v.y + v.z + v.w;
        float s2 = v.x*v.x + v.y*v.y + v.z*v.z + v.w*v.w;
        float2 r = block_reduce2(s, s2, sh);
        float mean = r.x * (1.f / HID);
        float var  = r.y * (1.f / HID) - mean * mean;
        float rstd = rsqrtf(var + LN_EPS);
        float4 wv = ((const float4*)w)[threadIdx.x];
        float4 bv = ((const float4*)b)[threadIdx.x];
        float o0 = (v.x - mean) * rstd * wv.x + bv.x;
        float o1 = (v.y - mean) * rstd * wv.y + bv.y;
        float o2 = (v.z - mean) * rstd * wv.z + bv.z;
        float o3 = (v.w - mean) * rstd * wv.w + bv.w;
        __nv_bfloat162* ph = (__nv_bfloat162*)(oh + threadIdx.x * 4);
        ph[0] = __floats2bfloat162_rn(o0, o1);
        ph[1] = __floats2bfloat162_rn(o2, o3);
    } else {
        int blk = bid - (MQ + MK);
        int wi = blk >> 9, ib = blk & 511;
        const float* src = (wi == 0) ? w0 : (wi == 1) ? w1 : (wi == 2) ? w2 : w3;
        __nv_bfloat16* dh = (wi == 0) ? h0 : (wi == 1) ? h1 : (wi == 2) ? h2 : h3;
        const int n4 = HID * HID / 4;
        for (int i = ib * 256 + threadIdx.x; i < n4; i += 512 * 256) {
            float4 v = ((const float4*)src)[i];
            __nv_bfloat162* ph = (__nv_bfloat162*)(dh + (size_t)i * 4);
            ph[0] = __floats2bfloat162_rn(v.x, v.y);
            ph[1] = __floats2bfloat162_rn(v.z, v.w);
        }
    }
}

// -------- residual + LayerNorm -----------------------------------------------
__global__ void res_ln_kernel(const float* __restrict__ x,
                              const float* __restrict__ y,
                              const float* __restrict__ w,
                              const float* __restrict__ b,
                              float* __restrict__ out) {
    __shared__ float sh[16];
    size_t row = blockIdx.x;
    float4 v  = ((const float4*)(x + row * HID))[threadIdx.x];
    float4 yv = ((const float4*)(y + row * HID))[threadIdx.x];
    v.x += yv.x; v.y += yv.y; v.z += yv.z; v.w += yv.w;
    float s  = v.x + v.y + v.z + v.w;
    float s2 = v.x*v.x + v.y*v.y + v.z*v.z + v.w*v.w;
    float2 r = block_reduce2(s, s2, sh);
    float mean = r.x * (1.f / HID);
    float var  = r.y * (1.f / HID) - mean * mean;
    float rstd = rsqrtf(var + LN_EPS);
    float4 wv = ((const float4*)w)[threadIdx.x];
    float4 bv = ((const float4*)b)[threadIdx.x];
    float4 o;
    o.x = (v.x - mean) * rstd * wv.x + bv.x;
    o.y = (v.y - mean) * rstd * wv.y + bv.y;
    o.z = (v.z - mean) * rstd * wv.z + bv.z;
    o.w = (v.w - mean) * rstd * wv.w + bv.w;
    ((float4*)(out + row * HID))[threadIdx.x] = o;
}

// ================= Q projection: 1-term bf16 GEMM, scaled bf16 out ==========
#define G1_A 0
#define G1_B 16384
#define G1_STG 24576
#define G1_SMEM 49152

__global__ void __launch_bounds__(256, 2) gemm_q(
    const __nv_bfloat16* __restrict__ A, const __nv_bfloat16* __restrict__ B,
    __nv_bfloat16* __restrict__ Cb) {
    extern __shared__ char sm[];
    uint32_t sb = smem_u32(sm);
    int tid = threadIdx.x;
    int wid = tid >> 5, lane = tid & 31;
    int wm = wid >> 1, wn = wid & 1;
    int rowBase = blockIdx.y * 128;
    int colBase = blockIdx.x * 64;
    int q = lane >> 3, ln8 = lane & 7;

    float acc[2][4][4];
    #pragma unroll
    for (int i = 0; i < 2; i++)
        #pragma unroll
        for (int j = 0; j < 4; j++)
            #pragma unroll
            for (int r = 0; r < 4; r++) acc[i][j][r] = 0.f;

    auto load_chunk = [&](int c, int st) {
        int k0 = c * 64;
        uint32_t so = sb + st * G1_STG;
        #pragma unroll
        for (int s = 0; s < 4; s++) {
            int row = (tid >> 3) + 32 * s, ch = tid & 7;
            uint32_t off = (uint32_t)row * 128 + (uint32_t)((ch ^ (row & 7)) * 16);
            CP_ASYNC16(so + G1_A + off, A + (size_t)(rowBase + row) * HID + k0 + ch * 8);
        }
        #pragma unroll
        for (int s = 0; s < 2; s++) {
            int idx = tid + s * 256;
            int row = idx >> 3, ch = idx & 7;
            uint32_t off = (uint32_t)row * 128 + (uint32_t)((ch ^ (row & 7)) * 16);
            CP_ASYNC16(so + G1_B + off, B + (size_t)(colBase + row) * HID + k0 + ch * 8);
        }
        CP_COMMIT();
    };

    load_chunk(0, 0);

    for (int c = 0; c < 16; c++) {
        if (c < 15) { load_chunk(c + 1, (c + 1) & 1); CP_WAIT1(); }
        else        { CP_WAIT0(); }
        __syncthreads();
        uint32_t Ab = sb + (c & 1) * G1_STG + G1_A;
        uint32_t Bb = sb + (c & 1) * G1_STG + G1_B;
        #pragma unroll
        for (int ti = 0; ti < 4; ti++) {
            uint32_t af[2][4];
            #pragma unroll
            for (int mi = 0; mi < 2; mi++) {
                int row = wm * 32 + mi * 16 + (q & 1) * 8 + ln8;
                int ch = ti * 2 + (q >> 1);
                ldsm4(af[mi], Ab + row * 128 + ((ch ^ (row & 7)) * 16));
            }
            uint32_t bf[2][4];
            #pragma unroll
            for (int g = 0; g < 2; g++) {
                int row = wn * 32 + g * 16 + (q >> 1) * 8 + ln8;
                int ch = ti * 2 + (q & 1);
                ldsm4(bf[g], Bb + row * 128 + ((ch ^ (row & 7)) * 16));
            }
            #pragma unroll
            for (int mi = 0; mi < 2; mi++) {
                mma16816(acc[mi][0], af[mi], &bf[0][0]);
                mma16816(acc[mi][1], af[mi], &bf[0][2]);
                mma16816(acc[mi][2], af[mi], &bf[1][0]);
                mma16816(acc[mi][3], af[mi], &bf[1][2]);
            }
        }
        __syncthreads();
    }

    int r0 = rowBase + wm * 32 + (lane >> 2);
    int c0 = colBase + wn * 32 + (lane & 3) * 2;
    #pragma unroll
    for (int mi = 0; mi < 2; mi++) {
        #pragma unroll
        for (int ni = 0; ni < 4; ni++) {
            int rr = r0 + mi * 16;
            int cc = c0 + ni * 8;
            *(__nv_bfloat162*)&Cb[(size_t)rr * HID + cc] =
                __floats2bfloat162_rn(acc[mi][ni][0] * QKSCALE, acc[mi][ni][1] * QKSCALE);
            *(__nv_bfloat162*)&Cb[(size_t)(rr + 8) * HID + cc] =
                __floats2bfloat162_rn(acc[mi][ni][2] * QKSCALE, acc[mi][ni][3] * QKSCALE);
        }
    }
}

// ======== fused K+V projection: shared gathered A, dual B, dual epilogue =====
#define KV_A 0
#define KV_BK 16384
#define KV_BV 24576
#define KV_STG 32768
#define KV_SMEM 65536

__global__ void __launch_bounds__(256) gemm_kv(
    const __nv_bfloat16* __restrict__ A,
    const __nv_bfloat16* __restrict__ Bk, const __nv_bfloat16* __restrict__ Bv,
    __nv_bfloat16* __restrict__ Ks, __nv_bfloat16* __restrict__ Vt,
    const int* __restrict__ cidx, const int* __restrict__ nv) {
    extern __shared__ char sm[];
    uint32_t sb = smem_u32(sm);
    int tid = threadIdx.x;
    int wid = tid >> 5, lane = tid & 31;
    int wm = wid >> 1, wn = wid & 1;
    int rowBase = blockIdx.y * 128;
    int colBase = blockIdx.x * 64;
    int q = lane >> 3, ln8 = lane & 7;

    int bb = rowBase / NK;
    int slot0 = rowBase % NK;
    if (slot0 >= ((nv[bb] + 63) & ~63)) return;

    const __nv_bfloat16* pA[4];
    #pragma unroll
    for (int s = 0; s < 4; s++) {
        int slot = slot0 + (tid >> 3) + 32 * s;
        int ar = cidx[bb * NK + slot];
        pA[s] = A + (size_t)(bb * NK + ar) * HID + (tid & 7) * 8;
    }

    float acck[2][4][4], accv[2][4][4];
    #pragma unroll
    for (int i = 0; i < 2; i++)
        #pragma unroll
        for (int j = 0; j < 4; j++)
            #pragma unroll
            for (int r = 0; r < 4; r++) { acck[i][j][r] = 0.f; accv[i][j][r] = 0.f; }

    auto load_chunk = [&](int c, int st) {
        int k0 = c * 64;
        uint32_t so = sb + st * KV_STG;
        #pragma unroll
        for (int s = 0; s < 4; s++) {
            int row = (tid >> 3) + 32 * s, ch = tid & 7;
            uint32_t off = (uint32_t)row * 128 + (uint32_t)((ch ^ (row & 7)) * 16);
            CP_ASYNC16(so + KV_A + off, pA[s] + k0);
        }
        #pragma unroll
        for (int s = 0; s < 2; s++) {
            int idx = tid + s * 256;
            int row = idx >> 3, ch = idx & 7;
            uint32_t off = (uint32_t)row * 128 + (uint32_t)((ch ^ (row & 7)) * 16);
            CP_ASYNC16(so + KV_BK + off, Bk + (size_t)(colBase + row) * HID + k0 + ch * 8);
            CP_ASYNC16(so + KV_BV + off, Bv + (size_t)(colBase + row) * HID + k0 + ch * 8);
        }
        CP_COMMIT();
    };

    load_chunk(0, 0);

    for (int c = 0; c < 16; c++) {
        if (c < 15) { load_chunk(c + 1, (c + 1) & 1); CP_WAIT1(); }
        else        { CP_WAIT0(); }
        __syncthreads();
        uint32_t Ab  = sb + (c & 1) * KV_STG + KV_A;
        uint32_t Bkb = sb + (c & 1) * KV_STG + KV_BK;
        uint32_t Bvb = sb + (c & 1) * KV_STG + KV_BV;
        #pragma unroll
        for (int ti = 0; ti < 4; ti++) {
            uint32_t af[2][4];
            #pragma unroll
            for (int mi = 0; mi < 2; mi++) {
                int row = wm * 32 + mi * 16 + (q & 1) * 8 + ln8;
                int ch = ti * 2 + (q >> 1);
                ldsm4(af[mi], Ab + row * 128 + ((ch ^ (row & 7)) * 16));
            }
            uint32_t bk[2][4], bv[2][4];
            #pragma unroll
            for (int g = 0; g < 2; g++) {
                int row = wn * 32 + g * 16 + (q >> 1) * 8 + ln8;
                int ch = ti * 2 + (q & 1);
                uint32_t off = row * 128 + ((ch ^ (row & 7)) * 16);
                ldsm4(bk[g], Bkb + off);
                ldsm4(bv[g], Bvb + off);
            }
            #pragma unroll
            for (int mi = 0; mi < 2; mi++) {
                mma16816(acck[mi][0], af[mi], &bk[0][0]);
                mma16816(acck[mi][1], af[mi], &bk[0][2]);
                mma16816(acck[mi][2], af[mi], &bk[1][0]);
                mma16816(acck[mi][3], af[mi], &bk[1][2]);
                mma16816(accv[mi][0], af[mi], &bv[0][0]);
                mma16816(accv[mi][1], af[mi], &bv[0][2]);
                mma16816(accv[mi][2], af[mi], &bv[1][0]);
                mma16816(accv[mi][3], af[mi], &bv[1][2]);
            }
        }
        __syncthreads();
    }

    // --- K epilogue: bf16 writes (row-major) ---
    {
        int r0 = rowBase + wm * 32 + (lane >> 2);
        int c0 = colBase + wn * 32 + (lane & 3) * 2;
        #pragma unroll
        for (int mi = 0; mi < 2; mi++) {
            #pragma unroll
            for (int ni = 0; ni < 4; ni++) {
                int rr = r0 + mi * 16;
                int cc = c0 + ni * 8;
                *(__nv_bfloat162*)&Ks[(size_t)rr * HID + cc] =
                    __floats2bfloat162_rn(acck[mi][ni][0], acck[mi][ni][1]);
                *(__nv_bfloat162*)&Ks[(size_t)(rr + 8) * HID + cc] =
                    __floats2bfloat162_rn(acck[mi][ni][2], acck[mi][ni][3]);
            }
        }
    }

    // --- V epilogue: transpose through smem -> Vt[(b,h,d)][slot] ---
    {
        float* ts = (float*)sm;
        int r0l = wm * 32 + (lane >> 2);
        int c0l = wn * 32 + (lane & 3) * 2;
        #pragma unroll
        for (int mi = 0; mi < 2; mi++) {
            #pragma unroll
            for (int ni = 0; ni < 4; ni++) {
                int rr = r0l + mi * 16, cc = c0l + ni * 8;
                ts[rr * 65 + cc] = accv[mi][ni][0];
                ts[rr * 65 + cc + 1] = accv[mi][ni][1];
                ts[(rr + 8) * 65 + cc] = accv[mi][ni][2];
                ts[(rr + 8) * 65 + cc + 1] = accv[mi][ni][3];
            }
        }
        __syncthreads();
        int hh = blockIdx.x;
        int d = tid >> 2, kb = (tid & 3) * 32;
        __nv_bfloat16* dst = Vt + (size_t)((bb * HEADS + hh) * 64 + d) * NK + slot0 + kb;
        #pragma unroll
        for (int k = 0; k < 32; k += 2) {
            *(__nv_bfloat162*)(dst + k) =
                __floats2bfloat162_rn(ts[(kb + k) * 65 + d], ts[(kb + k + 1) * 65 + d]);
        }
    }
}

// ================= 2-term O projection: (ctx_h + ctx_l) @ Wo_h^T ============
#define O_AH 0
#define O_AL 16384
#define O_BH 32768
#define O_STG 40960
#define O_SMEM (2*O_STG)   // 81920

__global__ void __launch_bounds__(256, 2) gemm_o(
    const __nv_bfloat16* __restrict__ Ah, const __nv_bfloat16* __restrict__ Al,
    const __nv_bfloat16* __restrict__ Bh,
    float* __restrict__ C) {
    extern __shared__ char sm[];
    uint32_t sb = smem_u32(sm);
    int tid = threadIdx.x;
    int wid = tid >> 5, lane = tid & 31;
    int wm = wid >> 1, wn = wid & 1;
    int rowBase = blockIdx.y * 128;
    int colBase = blockIdx.x * 64;
    int q = lane >> 3, ln8 = lane & 7;

    float acc[2][4][4];
    #pragma unroll
    for (int i = 0; i < 2; i++)
        #pragma unroll
        for (int j = 0; j < 4; j++)
            #pragma unroll
            for (int r = 0; r < 4; r++) acc[i][j][r] = 0.f;

    auto load_chunk = [&](int c, int st) {
        int k0 = c * 64;
        uint32_t so = sb + st * O_STG;
        #pragma unroll
        for (int s = 0; s < 4; s++) {
            int idx = tid + s * 256;
            int row = idx >> 3, ch = idx & 7;
            uint32_t off = (uint32_t)row * 128 + (uint32_t)((ch ^ (row & 7)) * 16);
            CP_ASYNC16(so + O_AH + off, Ah + (size_t)(rowBase + row) * HID + k0 + ch * 8);
            CP_ASYNC16(so + O_AL + off, Al + (size_t)(rowBase + row) * HID + k0 + ch * 8);
        }
        #pragma unroll
        for (int s = 0; s < 2; s++) {
            int idx = tid + s * 256;
            int row = idx >> 3, ch = idx & 7;
            uint32_t off = (uint32_t)row * 128 + (uint32_t)((ch ^ (row & 7)) * 16);
            CP_ASYNC16(so + O_BH + off, Bh + (size_t)(colBase + row) * HID + k0 + ch * 8);
        }
        CP_COMMIT();
    };

    load_chunk(0, 0);

    for (int c = 0; c < 16; c++) {
        if (c < 15) { load_chunk(c + 1, (c + 1) & 1); CP_WAIT1(); }
        else        { CP_WAIT0(); }
        __syncthreads();
        uint32_t stBase = sb + (c & 1) * O_STG;
        #pragma unroll
        for (int pass = 0; pass < 2; pass++) {
            uint32_t Ab = stBase + ((pass == 0) ? O_AH : O_AL);
            uint32_t Bb = stBase + O_BH;
            #pragma unroll
            for (int ti = 0; ti < 4; ti++) {
                uint32_t af[2][4];
                #pragma unroll
                for (int mi = 0; mi < 2; mi++) {
                    int row = wm * 32 + mi * 16 + (q & 1) * 8 + ln8;
                    int ch = ti * 2 + (q >> 1);
                    ldsm4(af[mi], Ab + row * 128 + ((ch ^ (row & 7)) * 16));
                }
                uint32_t bf[2][4];
                #pragma unroll
                for (int g = 0; g < 2; g++) {
                    int row = wn * 32 + g * 16 + (q >> 1) * 8 + ln8;
                    int ch = ti * 2 + (q & 1);
                    ldsm4(bf[g], Bb + row * 128 + ((ch ^ (row & 7)) * 16));
                }
                #pragma unroll
                for (int mi = 0; mi < 2; mi++) {
                    mma16816(acc[mi][0], af[mi], &bf[0][0]);
                    mma16816(acc[mi][1], af[mi], &bf[0][2]);
                    mma16816(acc[mi][2], af[mi], &bf[1][0]);
                    mma16816(acc[mi][3], af[mi], &bf[1][2]);
                }
            }
        }
        __syncthreads();
    }

    int r0 = rowBase + wm * 32 + (lane >> 2);
    int c0 = colBase + wn * 32 + (lane & 3) * 2;
    #pragma unroll
    for (int mi = 0; mi < 2; mi++) {
        #pragma unroll
        for (int ni = 0; ni < 4; ni++) {
            int rr = r0 + mi * 16;
            int cc = c0 + ni * 8;
            *(float2*)&C[(size_t)rr * HID + cc] = make_float2(acc[mi][ni][0], acc[mi][ni][1]);
            *(float2*)&C[(size_t)(rr + 8) * HID + cc] = make_float2(acc[mi][ni][2], acc[mi][ni][3]);
        }
    }
}

// ================= HMMA flash attention: 128 queries/CTA, 256 threads =======
#define AS_Q 0
#define AS_STG 16384
#define AS_KH 0
#define AS_VT 8192
#define AS_BIAS 16384
#define AS_STGSZ 17408
#define AT_SMEM (AS_STG + 2*AS_STGSZ)   // 51200

__global__ void __launch_bounds__(256) attn_hmma(
    const int* __restrict__ qt_ids, const int* __restrict__ nv,
    const __nv_bfloat16* __restrict__ Qs,
    const __nv_bfloat16* __restrict__ Ks,
    const __nv_bfloat16* __restrict__ Vt,
    const float* __restrict__ biasg,
    __nv_bfloat16* __restrict__ ctxh, __nv_bfloat16* __restrict__ ctxl) {
    extern __shared__ char sm[];
    uint32_t sb = smem_u32(sm);
    int tid = threadIdx.x, w = tid >> 5, lane = tid & 31;
    int q0 = blockIdx.x * 128, h = blockIdx.y, b = blockIdx.z;
    int group = lane >> 2, qp = lane & 3;
    int q8 = lane >> 3, ln8 = lane & 7;
    int ntiles = (nv[b] + 63) >> 6;

    #pragma unroll
    for (int s = 0; s < 4; s++) {
        int idx = tid + s * 256;
        int r = idx >> 3, ch = idx & 7;
        size_t go = (size_t)(b * NQ + q0 + r) * HID + h * 64 + ch * 8;
        uint32_t off = (uint32_t)r * 128 + (uint32_t)((ch ^ (r & 7)) * 16);
        *(uint4*)(sm + AS_Q + off) = *(const uint4*)(Qs + go);
    }

    auto load_stage = [&](int t, int st) {
        int k0 = t * 64;
        uint32_t so = sb + AS_STG + st * AS_STGSZ;
        #pragma unroll
        for (int s = 0; s < 4; s++) {
            int idx = tid + s * 256;
            int m = idx >> 9;
            int rc = idx & 511;
            int r = rc >> 3, ch = rc & 7;
            uint32_t off = so + m * 8192 + (uint32_t)r * 128 + (uint32_t)((ch ^ (r & 7)) * 16);
            const __nv_bfloat16* src;
            if (m == 0) src = Ks + (size_t)(b * NK + k0 + r) * HID + h * 64 + ch * 8;
            else        src = Vt + (size_t)((b * HEADS + h) * 64 + r) * NK + k0 + ch * 8;
            CP_ASYNC16(off, src);
        }
        if (tid < 48) {
            int qt = tid >> 4, j = tid & 15;
            CP_ASYNC16(so + AS_BIAS + qt * 256 + j * 16,
                       biasg + (size_t)(b * 3 + qt) * NK + k0 + j * 4);
        }
        CP_COMMIT();
    };

    load_stage(0, 0);
    __syncthreads();

    uint32_t QHf[4][4];
    #pragma unroll
    for (int c2 = 0; c2 < 4; c2++) {
        int r = w * 16 + (lane & 15);
        int ch = c2 * 2 + (lane >> 4);
        uint32_t off = (uint32_t)r * 128 + (uint32_t)((ch ^ (r & 7)) * 16);
        ldsm4(QHf[c2], sb + AS_Q + off);
    }
    int qtA = qt_ids[q0 + w * 16 + group];
    int qtB = qt_ids[q0 + w * 16 + group + 8];

    float acc[8][4];
    #pragma unroll
    for (int i = 0; i < 8; i++)
        #pragma unroll
        for (int j = 0; j < 4; j++) acc[i][j] = 0.f;
    float lA = 0.f, lB = 0.f;

    for (int t = 0; t < ntiles; t++) {
        if (t + 1 < ntiles) { load_stage(t + 1, (t + 1) & 1); CP_WAIT1(); }
        else                { CP_WAIT0(); }
        __syncthreads();
        uint32_t st = sb + AS_STG + (t & 1) * AS_STGSZ;
        char*    stc = sm + AS_STG + (t & 1) * AS_STGSZ;

        float S[8][4];
        #pragma unroll
        for (int np = 0; np < 4; np++) {
            #pragma unroll
            for (int j = 0; j < 4; j++) { S[2*np][j] = 0.f; S[2*np+1][j] = 0.f; }
            #pragma unroll
            for (int c2 = 0; c2 < 4; c2++) {
                int row = np * 16 + (q8 >> 1) * 8 + ln8;
                int ch = c2 * 2 + (q8 & 1);
                uint32_t off = (uint32_t)row * 128 + (uint32_t)((ch ^ (row & 7)) * 16);
                uint32_t kh[4];
                ldsm4(kh, st + AS_KH + off);
                mma16816(S[2*np],   QHf[c2], &kh[0]);
                mma16816(S[2*np+1], QHf[c2], &kh[2]);
            }
        }

        const float* bA = (const float*)(stc + AS_BIAS) + qtA * 64;
        const float* bB = (const float*)(stc + AS_BIAS) + qtB * 64;
        uint32_t P[4][4];
        #pragma unroll
        for (int kc = 0; kc < 4; kc++) {
            int t0 = kc * 2, t1 = t0 + 1;
            float2 a0 = *(const float2*)(bA + t0 * 8 + qp * 2);
            float2 b0 = *(const float2*)(bB + t0 * 8 + qp * 2);
            float2 a1 = *(const float2*)(bA + t1 * 8 + qp * 2);
            float2 b1 = *(const float2*)(bB + t1 * 8 + qp * 2);
            float p00 = exp2m(S[t0][0] + a0.x), p01 = exp2m(S[t0][1] + a0.y);
            float p02 = exp2m(S[t0][2] + b0.x), p03 = exp2m(S[t0][3] + b0.y);
            float p10 = exp2m(S[t1][0] + a1.x), p11 = exp2m(S[t1][1] + a1.y);
            float p12 = exp2m(S[t1][2] + b1.x), p13 = exp2m(S[t1][3] + b1.y);
            lA += p00 + p01 + p10 + p11;
            lB += p02 + p03 + p12 + p13;
            __nv_bfloat162 tt;
            tt = __floats2bfloat162_rn(p00, p01); P[kc][0] = *(uint32_t*)&tt;
            tt = __floats2bfloat162_rn(p02, p03); P[kc][1] = *(uint32_t*)&tt;
            tt = __floats2bfloat162_rn(p10, p11); P[kc][2] = *(uint32_t*)&tt;
            tt = __floats2bfloat162_rn(p12, p13); P[kc][3] = *(uint32_t*)&tt;
        }

        #pragma unroll
        for (int kc = 0; kc < 4; kc++) {
            #pragma unroll
            for (int tdp = 0; tdp < 4; tdp++) {
                int row = tdp * 16 + (q8 >> 1) * 8 + ln8;
                int ch = kc * 2 + (q8 & 1);
                uint32_t off = (uint32_t)row * 128 + (uint32_t)((ch ^ (row & 7)) * 16);
                uint32_t v4[4];
                ldsm4(v4, st + AS_VT + off);
                mma16816(acc[2*tdp],   P[kc], &v4[0]);
                mma16816(acc[2*tdp+1], P[kc], &v4[2]);
            }
        }
        __syncthreads();
    }

    lA += __shfl_xor_sync(0xffffffffu, lA, 1);
    lA += __shfl_xor_sync(0xffffffffu, lA, 2);
    lB += __shfl_xor_sync(0xffffffffu, lB, 1);
    lB += __shfl_xor_sync(0xffffffffu, lB, 2);
    float iA = 1.f / lA, iB = 1.f / lB;

    int rowA = q0 + w * 16 + group, rowB = rowA + 8;
    #pragma unroll
    for (int td = 0; td < 8; td++) {
        int col = h * 64 + td * 8 + qp * 2;
        float v0 = acc[td][0] * iA, v1 = acc[td][1] * iA;
        float v2 = acc[td][2] * iB, v3 = acc[td][3] * iB;
        __nv_bfloat16 h0,h1,h2,h3,l0,l1,l2,l3;
        split_bf16(v0,h0,l0); split_bf16(v1,h1,l1);
        split_bf16(v2,h2,l2); split_bf16(v3,h3,l3);
        size_t oA = (size_t)(b * NQ + rowA) * HID + col;
        size_t oB = (size_t)(b * NQ + rowB) * HID + col;
        *(__nv_bfloat162*)&ctxh[oA] = __nv_bfloat162(h0, h1);
        *(__nv_bfloat162*)&ctxl[oA] = __nv_bfloat162(l0, l1);
        *(__nv_bfloat162*)&ctxh[oB] = __nv_bfloat162(h2, h3);
        *(__nv_bfloat162*)&ctxl[oB] = __nv_bfloat162(l2, l3);
    }
}

// ---------------- launch ----------------------------------------------------
extern "C" void kernel_launch(void* const* d_in, const int* in_sizes, int n_in,
                              void* d_out, int out_size) {
    const float* queries = (const float*)d_in[0];
    const float* kv      = (const float*)d_in[1];
    const int*   qt_ids  = (const int*)d_in[2];
    const int*   kt_ids  = (const int*)d_in[3];
    const int*   pad     = (const int*)d_in[4];
    const float* Wq   = (const float*)d_in[5];
    const float* Wk   = (const float*)d_in[6];
    const float* Wv   = (const float*)d_in[7];
    const float* Wo   = (const float*)d_in[8];
    const float* qn_w = (const float*)d_in[9];
    const float* qn_b = (const float*)d_in[10];
    const float* kvn_w = (const float*)d_in[11];
    const float* kvn_b = (const float*)d_in[12];
    const float* on_w = (const float*)d_in[13];
    const float* on_b = (const float*)d_in[14];
    const float* tb   = (const float*)d_in[15];
    float* out = (float*)d_out;

    float *p_o, *p_bias;
    int *p_nv, *p_cidx;
    __nv_bfloat16 *p_qn, *p_kvn, *p_wq, *p_wk, *p_wv, *p_wo_h;
    __nv_bfloat16 *p_qs, *p_ks, *p_vt, *p_ctx_h, *p_ctx_l;
    cudaGetSymbolAddress((void**)&p_o,    g_o);
    cudaGetSymbolAddress((void**)&p_bias, g_bias);
    cudaGetSymbolAddress((void**)&p_nv,   g_nv);
    cudaGetSymbolAddress((void**)&p_cidx, g_cidx);
    cudaGetSymbolAddress((void**)&p_qn,   g_qn);
    cudaGetSymbolAddress((void**)&p_kvn,  g_kvn);
    cudaGetSymbolAddress((void**)&p_wq,   g_wq_h);
    cudaGetSymbolAddress((void**)&p_wk,   g_wk_h);
    cudaGetSymbolAddress((void**)&p_wv,   g_wv_h);
    cudaGetSymbolAddress((void**)&p_wo_h, g_wo_h);
    cudaGetSymbolAddress((void**)&p_qs,   g_qs);
    cudaGetSymbolAddress((void**)&p_ks,   g_ks);
    cudaGetSymbolAddress((void**)&p_vt,   g_vt);
    cudaGetSymbolAddress((void**)&p_ctx_h, g_ctx_h);
    cudaGetSymbolAddress((void**)&p_ctx_l, g_ctx_l);

    static int attr_set = 0;
    if (!attr_set) {
        cudaFuncSetAttribute(gemm_q,  cudaFuncAttributeMaxDynamicSharedMemorySize, G1_SMEM);
        cudaFuncSetAttribute(gemm_kv, cudaFuncAttributeMaxDynamicSharedMemorySize, KV_SMEM);
        cudaFuncSetAttribute(gemm_o,  cudaFuncAttributeMaxDynamicSharedMemorySize, O_SMEM);
        cudaFuncSetAttribute(attn_hmma, cudaFuncAttributeMaxDynamicSharedMemorySize, AT_SMEM);
        attr_set = 1;
    }

    // 0. key compaction + bias table (fused)
    compact_bias_kernel<<<BATCH, 1024>>>(pad, kt_ids, tb, p_nv, p_cidx, p_bias);

    // 1. LN + weight prep (one launch, block-range dispatch)
    prep_all<<<MQ + MK + 2048, 256>>>(queries, kv, qn_w, qn_b, kvn_w, kvn_b,
                                      Wq, Wk, Wv, Wo,
                                      p_qn, p_kvn, p_wq, p_wk, p_wv, p_wo_h);

    // 2. projections
    {
        dim3 gq(HID / 64, MQ / 128);
        dim3 gk(HID / 64, MK / 128);
        gemm_q<<<gq, 256, G1_SMEM>>>(p_qn, p_wq, p_qs);
        gemm_kv<<<gk, 256, KV_SMEM>>>(p_kvn, p_wk, p_wv, p_ks, p_vt, p_cidx, p_nv);
    }

    // 3. flash attention -> ctx hi/lo
    {
        dim3 ga(NQ / 128, HEADS, BATCH);
        attn_hmma<<<ga, 256, AT_SMEM>>>(qt_ids, p_nv, p_qs, p_ks, p_vt, p_bias,
                                        p_ctx_h, p_ctx_l);
    }

    // 4. output projection (2-term)
    {
        dim3 go(HID / 64, MQ / 128);
        gemm_o<<<go, 256, O_SMEM>>>(p_ctx_h, p_ctx_l, p_wo_h, p_o);
    }

    // 5. residual + LN -> d_out
    res_ln_kernel<<<MQ, 256>>>(queries, p_o, on_w, on_b, out);
}

// round 14
// speedup vs baseline: 13.3990x; 1.0292x over previous
#include <cuda_runtime.h>
#include <cuda_bf16.h>
#include <math.h>
#include <float.h>
#include <stdint.h>

#define BATCH 2
#define NQ    1024
#define NK    4096
#define HID   1024
#define HEADS 16
#define HD    64
#define LN_EPS 1e-5f
#define LOG2E 1.4426950408889634f
#define QKSCALE (0.125f * LOG2E)
#define M0    32.0f

#define MQ (BATCH*NQ)   // 2048
#define MK (BATCH*NK)   // 8192

// ---------------- scratch (__device__ globals) ------------------------------
__device__ float g_o   [MQ*HID];
__device__ float g_bias[BATCH*3*NK];
__device__ int   g_nv[BATCH];
__device__ int   g_cidx[BATCH*NK];

__device__ __nv_bfloat16 g_qn [MQ*HID];
__device__ __nv_bfloat16 g_kvn[MK*HID];
__device__ __nv_bfloat16 g_wq_h[HID*HID];
__device__ __nv_bfloat16 g_wk_h[HID*HID];
__device__ __nv_bfloat16 g_wv_h[HID*HID];
__device__ __nv_bfloat16 g_wo_h[HID*HID];
__device__ __nv_bfloat16 g_qs [MQ*HID];
__device__ __nv_bfloat16 g_ks [MK*HID];
__device__ __nv_bfloat16 g_vt [MK*HID];       // [(b*H+h)*64 + d][slot]
__device__ __nv_bfloat16 g_ctx_h[MQ*HID], g_ctx_l[MQ*HID];

// ---------------- small helpers ---------------------------------------------
__device__ __forceinline__ uint32_t smem_u32(const void* p) {
    uint32_t a;
    asm("{ .reg .u64 t; cvta.to.shared.u64 t, %1; cvt.u32.u64 %0, t; }" : "=r"(a) : "l"(p));
    return a;
}

__device__ __forceinline__ void split_bf16(float x, __nv_bfloat16& h, __nv_bfloat16& l) {
    h = __float2bfloat16(x);
    l = __float2bfloat16(x - __bfloat162float(h));
}

__device__ __forceinline__ float2 block_reduce2(float a, float b, float* sh) {
    #pragma unroll
    for (int o = 16; o; o >>= 1) {
        a += __shfl_xor_sync(0xffffffffu, a, o);
        b += __shfl_xor_sync(0xffffffffu, b, o);
    }
    int w = threadIdx.x >> 5;
    if ((threadIdx.x & 31) == 0) { sh[w] = a; sh[8 + w] = b; }
    __syncthreads();
    if (threadIdx.x == 0) {
        float sa = 0.f, sb = 0.f;
        #pragma unroll
        for (int i = 0; i < 8; i++) { sa += sh[i]; sb += sh[8 + i]; }
        sh[0] = sa; sh[8] = sb;
    }
    __syncthreads();
    return make_float2(sh[0], sh[8]);
}

#define CP_ASYNC16(dst, src) \
    asm volatile("cp.async.cg.shared.global [%0], [%1], 16;" :: "r"(dst), "l"(src))
#define CP_COMMIT() asm volatile("cp.async.commit_group;" ::: "memory")
#define CP_WAIT0()  asm volatile("cp.async.wait_group 0;" ::: "memory")
#define CP_WAIT1()  asm volatile("cp.async.wait_group 1;" ::: "memory")

__device__ __forceinline__ void ldsm4(uint32_t* r, uint32_t addr) {
    asm volatile("ldmatrix.sync.aligned.m8n8.x4.shared.b16 {%0,%1,%2,%3}, [%4];"
                 : "=r"(r[0]), "=r"(r[1]), "=r"(r[2]), "=r"(r[3]) : "r"(addr));
}

__device__ __forceinline__ void mma16816(float* c, const uint32_t* a, const uint32_t* b) {
    asm volatile(
        "mma.sync.aligned.m16n8k16.row.col.f32.bf16.bf16.f32 "
        "{%0,%1,%2,%3}, {%4,%5,%6,%7}, {%8,%9}, {%0,%1,%2,%3};"
        : "+f"(c[0]), "+f"(c[1]), "+f"(c[2]), "+f"(c[3])
        : "r"(a[0]), "r"(a[1]), "r"(a[2]), "r"(a[3]), "r"(b[0]), "r"(b[1]));
}

// fast 2^x for x <= 0 (clamped at -80), magic-rounding + deg-4 poly
__device__ __forceinline__ float exp2m(float x) {
    x = fmaxf(x, -80.f);
    float t = __fadd_rn(x, 12582912.f);
    float r = __fadd_rn(t, -12582912.f);
    float f = x - r;
    int   n = __float_as_int(t) - 0x4B400000;
    float p = 9.6181291e-3f;
    p = fmaf(p, f, 5.5504109e-2f);
    p = fmaf(p, f, 2.4022651e-1f);
    p = fmaf(p, f, 6.9314718e-1f);
    p = fmaf(p, f, 1.0f);
    return __int_as_float((n + 127) << 23) * p;
}

// ------------- key compaction + fused bias table (one block per batch) -------
__global__ void compact_bias_kernel(const int* __restrict__ pad,
                                    const int* __restrict__ kt,
                                    const float* __restrict__ tb,
                                    int* __restrict__ nv, int* __restrict__ cidx,
                                    float* __restrict__ bias) {
    __shared__ int wsum[32];
    __shared__ float tbl[9];
    int b = blockIdx.x, tid = threadIdx.x;
    int lane = tid & 31, w = tid >> 5;
    int base = b * NK;
    if (tid < 9) tbl[tid] = tb[tid] * LOG2E - M0;
    int k0 = tid * 4;
    int f0 = pad[base + k0 + 0] != 0;
    int f1 = pad[base + k0 + 1] != 0;
    int f2 = pad[base + k0 + 2] != 0;
    int f3 = pad[base + k0 + 3] != 0;
    int c = f0 + f1 + f2 + f3;
    int inc = c;
    #pragma unroll
    for (int o = 1; o < 32; o <<= 1) {
        int t = __shfl_up_sync(0xffffffffu, inc, o);
        if (lane >= o) inc += t;
    }
    if (lane == 31) wsum[w] = inc;
    __syncthreads();
    if (w == 0) {
        int v = wsum[lane];
        #pragma unroll
        for (int o = 1; o < 32; o <<= 1) {
            int t = __shfl_up_sync(0xffffffffu, v, o);
            if (lane >= o) v += t;
        }
        wsum[lane] = v;
    }
    __syncthreads();
    int pos = inc - c + (w ? wsum[w - 1] : 0);
    if (f0) cidx[base + pos++] = k0 + 0;
    if (f1) cidx[base + pos++] = k0 + 1;
    if (f2) cidx[base + pos++] = k0 + 2;
    if (f3) cidx[base + pos++] = k0 + 3;
    int total = wsum[31];
    if (tid == 0) nv[b] = total;
    for (int s = total + tid; s < NK; s += 1024) cidx[base + s] = 0;
    __syncthreads();
    for (int s = tid; s < NK; s += 1024) {
        float t0, t1, t2;
        if (s < total) {
            int cc = kt[cidx[base + s]];
            t0 = tbl[cc]; t1 = tbl[3 + cc]; t2 = tbl[6 + cc];
        } else {
            t0 = t1 = t2 = -1e30f;
        }
        bias[(size_t)(b * 3 + 0) * NK + s] = t0;
        bias[(size_t)(b * 3 + 1) * NK + s] = t1;
        bias[(size_t)(b * 3 + 2) * NK + s] = t2;
    }
}

// ---- merged prep: LN (queries + kv) -> bf16, then 4x weight -> bf16 hi ------
__global__ void prep_all(const float* __restrict__ xq, const float* __restrict__ xk,
                         const float* __restrict__ qw, const float* __restrict__ qb,
                         const float* __restrict__ kw, const float* __restrict__ kb,
                         const float* __restrict__ w0, const float* __restrict__ w1,
                         const float* __restrict__ w2, const float* __restrict__ w3,
                         __nv_bfloat16* __restrict__ oq, __nv_bfloat16* __restrict__ ok,
                         __nv_bfloat16* __restrict__ h0, __nv_bfloat16* __restrict__ h1,
                         __nv_bfloat16* __restrict__ h2, __nv_bfloat16* __restrict__ h3) {
    __shared__ float sh[16];
    int bid = blockIdx.x;
    if (bid < MQ + MK) {
        size_t row = bid;
        const float* x; const float* w; const float* b; __nv_bfloat16* oh;
        if (row < MQ) { x = xq + row * HID; w = qw; b = qb; oh = oq + row * HID; }
        else { size_t r2 = row - MQ; x = xk + r2 * HID; w = kw; b = kb; oh = ok + r2 * HID; }
        float4 v = ((const float4*)x)[threadIdx.x];
        float s  = v.x + v.y + v.z + v.w;
        float s2 = v.x*v.x + v.y*v.y + v.z*v.z + v.w*v.w;
        float2 r = block_reduce2(s, s2, sh);
        float mean = r.x * (1.f / HID);
        float var  = r.y * (1.f / HID) - mean * mean;
        float rstd = rsqrtf(var + LN_EPS);
        float4 wv = ((const float4*)w)[threadIdx.x];
        float4 bv = ((const float4*)b)[threadIdx.x];
        float o0 = (v.x - mean) * rstd * wv.x + bv.x;
        float o1 = (v.y - mean) * rstd * wv.y + bv.y;
        float o2 = (v.z - mean) * rstd * wv.z + bv.z;
        float o3 = (v.w - mean) * rstd * wv.w + bv.w;
        __nv_bfloat162* ph = (__nv_bfloat162*)(oh + threadIdx.x * 4);
        ph[0] = __floats2bfloat162_rn(o0, o1);
        ph[1] = __floats2bfloat162_rn(o2, o3);
    } else {
        int blk = bid - (MQ + MK);
        int wi = blk >> 9, ib = blk & 511;
        const float* src = (wi == 0) ? w0 : (wi == 1) ? w1 : (wi == 2) ? w2 : w3;
        __nv_bfloat16* dh = (wi == 0) ? h0 : (wi == 1) ? h1 : (wi == 2) ? h2 : h3;
        const int n4 = HID * HID / 4;
        for (int i = ib * 256 + threadIdx.x; i < n4; i += 512 * 256) {
            float4 v = ((const float4*)src)[i];
            __nv_bfloat162* ph = (__nv_bfloat162*)(dh + (size_t)i * 4);
            ph[0] = __floats2bfloat162_rn(v.x, v.y);
            ph[1] = __floats2bfloat162_rn(v.z, v.w);
        }
    }
}

// -------- residual + LayerNorm -----------------------------------------------
__global__ void res_ln_kernel(const float* __restrict__ x,
                              const float* __restrict__ y,
                              const float* __restrict__ w,
                              const float* __restrict__ b,
                              float* __restrict__ out) {
    __shared__ float sh[16];
    size_t row = blockIdx.x;
    float4 v  = ((const float4*)(x + row * HID))[threadIdx.x];
    float4 yv = ((const float4*)(y + row * HID))[threadIdx.x];
    v.x += yv.x; v.y += yv.y; v.z += yv.z; v.w += yv.w;
    float s  = v.x + v.y + v.z + v.w;
    float s2 = v.x*v.x + v.y*v.y + v.z*v.z + v.w*v.w;
    float2 r = block_reduce2(s, s2, sh);
    float mean = r.x * (1.f / HID);
    float var  = r.y * (1.f / HID) - mean * mean;
    float rstd = rsqrtf(var + LN_EPS);
    float4 wv = ((const float4*)w)[threadIdx.x];
    float4 bv = ((const float4*)b)[threadIdx.x];
    float4 o;
    o.x = (v.x - mean) * rstd * wv.x + bv.x;
    o.y = (v.y - mean) * rstd * wv.y + bv.y;
    o.z = (v.z - mean) * rstd * wv.z + bv.z;
    o.w = (v.w - mean) * rstd * wv.w + bv.w;
    ((float4*)(out + row * HID))[threadIdx.x] = o;
}

// ================= Q projection: 1-term bf16 GEMM, 3-stage pipeline =========
#define G1_A 0
#define G1_B 16384
#define G1_STG 24576
#define G1_SMEM (3*G1_STG)   // 73728

__global__ void __launch_bounds__(256, 2) gemm_q(
    const __nv_bfloat16* __restrict__ A, const __nv_bfloat16* __restrict__ B,
    __nv_bfloat16* __restrict__ Cb) {
    extern __shared__ char sm[];
    uint32_t sb = smem_u32(sm);
    int tid = threadIdx.x;
    int wid = tid >> 5, lane = tid & 31;
    int wm = wid >> 1, wn = wid & 1;
    int rowBase = blockIdx.y * 128;
    int colBase = blockIdx.x * 64;
    int q = lane >> 3, ln8 = lane & 7;

    float acc[2][4][4];
    #pragma unroll
    for (int i = 0; i < 2; i++)
        #pragma unroll
        for (int j = 0; j < 4; j++)
            #pragma unroll
            for (int r = 0; r < 4; r++) acc[i][j][r] = 0.f;

    auto load_chunk = [&](int c, int st) {
        int k0 = c * 64;
        uint32_t so = sb + st * G1_STG;
        #pragma unroll
        for (int s = 0; s < 4; s++) {
            int row = (tid >> 3) + 32 * s, ch = tid & 7;
            uint32_t off = (uint32_t)row * 128 + (uint32_t)((ch ^ (row & 7)) * 16);
            CP_ASYNC16(so + G1_A + off, A + (size_t)(rowBase + row) * HID + k0 + ch * 8);
        }
        #pragma unroll
        for (int s = 0; s < 2; s++) {
            int idx = tid + s * 256;
            int row = idx >> 3, ch = idx & 7;
            uint32_t off = (uint32_t)row * 128 + (uint32_t)((ch ^ (row & 7)) * 16);
            CP_ASYNC16(so + G1_B + off, B + (size_t)(colBase + row) * HID + k0 + ch * 8);
        }
        CP_COMMIT();
    };

    load_chunk(0, 0);
    int st_ld = 1;       // stage for next load
    int st_cp = 0;       // stage for current compute

    for (int c = 0; c < 16; c++) {
        if (c < 15) { load_chunk(c + 1, st_ld); if (++st_ld == 3) st_ld = 0; CP_WAIT1(); }
        else        { CP_WAIT0(); }
        __syncthreads();
        uint32_t Ab = sb + st_cp * G1_STG + G1_A;
        uint32_t Bb = sb + st_cp * G1_STG + G1_B;
        if (++st_cp == 3) st_cp = 0;
        #pragma unroll
        for (int ti = 0; ti < 4; ti++) {
            uint32_t af[2][4];
            #pragma unroll
            for (int mi = 0; mi < 2; mi++) {
                int row = wm * 32 + mi * 16 + (q & 1) * 8 + ln8;
                int ch = ti * 2 + (q >> 1);
                ldsm4(af[mi], Ab + row * 128 + ((ch ^ (row & 7)) * 16));
            }
            uint32_t bf[2][4];
            #pragma unroll
            for (int g = 0; g < 2; g++) {
                int row = wn * 32 + g * 16 + (q >> 1) * 8 + ln8;
                int ch = ti * 2 + (q & 1);
                ldsm4(bf[g], Bb + row * 128 + ((ch ^ (row & 7)) * 16));
            }
            #pragma unroll
            for (int mi = 0; mi < 2; mi++) {
                mma16816(acc[mi][0], af[mi], &bf[0][0]);
                mma16816(acc[mi][1], af[mi], &bf[0][2]);
                mma16816(acc[mi][2], af[mi], &bf[1][0]);
                mma16816(acc[mi][3], af[mi], &bf[1][2]);
            }
        }
        // no trailing sync: 3-stage, 1-ahead loads never touch stages c or c-1
    }

    int r0 = rowBase + wm * 32 + (lane >> 2);
    int c0 = colBase + wn * 32 + (lane & 3) * 2;
    #pragma unroll
    for (int mi = 0; mi < 2; mi++) {
        #pragma unroll
        for (int ni = 0; ni < 4; ni++) {
            int rr = r0 + mi * 16;
            int cc = c0 + ni * 8;
            *(__nv_bfloat162*)&Cb[(size_t)rr * HID + cc] =
                __floats2bfloat162_rn(acc[mi][ni][0] * QKSCALE, acc[mi][ni][1] * QKSCALE);
            *(__nv_bfloat162*)&Cb[(size_t)(rr + 8) * HID + cc] =
                __floats2bfloat162_rn(acc[mi][ni][2] * QKSCALE, acc[mi][ni][3] * QKSCALE);
        }
    }
}

// ======== fused K+V projection: 3-stage pipeline, dual epilogue ==============
#define KV_A 0
#define KV_BK 16384
#define KV_BV 24576
#define KV_STG 32768
#define KV_SMEM (3*KV_STG)   // 98304

__global__ void __launch_bounds__(256) gemm_kv(
    const __nv_bfloat16* __restrict__ A,
    const __nv_bfloat16* __restrict__ Bk, const __nv_bfloat16* __restrict__ Bv,
    __nv_bfloat16* __restrict__ Ks, __nv_bfloat16* __restrict__ Vt,
    const int* __restrict__ cidx, const int* __restrict__ nv) {
    extern __shared__ char sm[];
    uint32_t sb = smem_u32(sm);
    int tid = threadIdx.x;
    int wid = tid >> 5, lane = tid & 31;
    int wm = wid >> 1, wn = wid & 1;
    int rowBase = blockIdx.y * 128;
    int colBase = blockIdx.x * 64;
    int q = lane >> 3, ln8 = lane & 7;

    int bb = rowBase / NK;
    int slot0 = rowBase % NK;
    if (slot0 >= ((nv[bb] + 63) & ~63)) return;

    const __nv_bfloat16* pA[4];
    #pragma unroll
    for (int s = 0; s < 4; s++) {
        int slot = slot0 + (tid >> 3) + 32 * s;
        int ar = cidx[bb * NK + slot];
        pA[s] = A + (size_t)(bb * NK + ar) * HID + (tid & 7) * 8;
    }

    float acck[2][4][4], accv[2][4][4];
    #pragma unroll
    for (int i = 0; i < 2; i++)
        #pragma unroll
        for (int j = 0; j < 4; j++)
            #pragma unroll
            for (int r = 0; r < 4; r++) { acck[i][j][r] = 0.f; accv[i][j][r] = 0.f; }

    auto load_chunk = [&](int c, int st) {
        int k0 = c * 64;
        uint32_t so = sb + st * KV_STG;
        #pragma unroll
        for (int s = 0; s < 4; s++) {
            int row = (tid >> 3) + 32 * s, ch = tid & 7;
            uint32_t off = (uint32_t)row * 128 + (uint32_t)((ch ^ (row & 7)) * 16);
            CP_ASYNC16(so + KV_A + off, pA[s] + k0);
        }
        #pragma unroll
        for (int s = 0; s < 2; s++) {
            int idx = tid + s * 256;
            int row = idx >> 3, ch = idx & 7;
            uint32_t off = (uint32_t)row * 128 + (uint32_t)((ch ^ (row & 7)) * 16);
            CP_ASYNC16(so + KV_BK + off, Bk + (size_t)(colBase + row) * HID + k0 + ch * 8);
            CP_ASYNC16(so + KV_BV + off, Bv + (size_t)(colBase + row) * HID + k0 + ch * 8);
        }
        CP_COMMIT();
    };

    load_chunk(0, 0);
    int st_ld = 1, st_cp = 0;

    for (int c = 0; c < 16; c++) {
        if (c < 15) { load_chunk(c + 1, st_ld); if (++st_ld == 3) st_ld = 0; CP_WAIT1(); }
        else        { CP_WAIT0(); }
        __syncthreads();
        uint32_t Ab  = sb + st_cp * KV_STG + KV_A;
        uint32_t Bkb = sb + st_cp * KV_STG + KV_BK;
        uint32_t Bvb = sb + st_cp * KV_STG + KV_BV;
        if (++st_cp == 3) st_cp = 0;
        #pragma unroll
        for (int ti = 0; ti < 4; ti++) {
            uint32_t af[2][4];
            #pragma unroll
            for (int mi = 0; mi < 2; mi++) {
                int row = wm * 32 + mi * 16 + (q & 1) * 8 + ln8;
                int ch = ti * 2 + (q >> 1);
                ldsm4(af[mi], Ab + row * 128 + ((ch ^ (row & 7)) * 16));
            }
            uint32_t bk[2][4], bv[2][4];
            #pragma unroll
            for (int g = 0; g < 2; g++) {
                int row = wn * 32 + g * 16 + (q >> 1) * 8 + ln8;
                int ch = ti * 2 + (q & 1);
                uint32_t off = row * 128 + ((ch ^ (row & 7)) * 16);
                ldsm4(bk[g], Bkb + off);
                ldsm4(bv[g], Bvb + off);
            }
            #pragma unroll
            for (int mi = 0; mi < 2; mi++) {
                mma16816(acck[mi][0], af[mi], &bk[0][0]);
                mma16816(acck[mi][1], af[mi], &bk[0][2]);
                mma16816(acck[mi][2], af[mi], &bk[1][0]);
                mma16816(acck[mi][3], af[mi], &bk[1][2]);
                mma16816(accv[mi][0], af[mi], &bv[0][0]);
                mma16816(accv[mi][1], af[mi], &bv[0][2]);
                mma16816(accv[mi][2], af[mi], &bv[1][0]);
                mma16816(accv[mi][3], af[mi], &bv[1][2]);
            }
        }
        // no trailing sync (3-stage)
    }

    // --- K epilogue: bf16 writes (row-major, no smem) ---
    {
        int r0 = rowBase + wm * 32 + (lane >> 2);
        int c0 = colBase + wn * 32 + (lane & 3) * 2;
        #pragma unroll
        for (int mi = 0; mi < 2; mi++) {
            #pragma unroll
            for (int ni = 0; ni < 4; ni++) {
                int rr = r0 + mi * 16;
                int cc = c0 + ni * 8;
                *(__nv_bfloat162*)&Ks[(size_t)rr * HID + cc] =
                    __floats2bfloat162_rn(acck[mi][ni][0], acck[mi][ni][1]);
                *(__nv_bfloat162*)&Ks[(size_t)(rr + 8) * HID + cc] =
                    __floats2bfloat162_rn(acck[mi][ni][2], acck[mi][ni][3]);
            }
        }
    }

    // --- V epilogue: transpose through smem -> Vt[(b,h,d)][slot] ---
    __syncthreads();   // protect stage smem from lagging readers before ts reuse
    {
        float* ts = (float*)sm;
        int r0l = wm * 32 + (lane >> 2);
        int c0l = wn * 32 + (lane & 3) * 2;
        #pragma unroll
        for (int mi = 0; mi < 2; mi++) {
            #pragma unroll
            for (int ni = 0; ni < 4; ni++) {
                int rr = r0l + mi * 16, cc = c0l + ni * 8;
                ts[rr * 65 + cc] = accv[mi][ni][0];
                ts[rr * 65 + cc + 1] = accv[mi][ni][1];
                ts[(rr + 8) * 65 + cc] = accv[mi][ni][2];
                ts[(rr + 8) * 65 + cc + 1] = accv[mi][ni][3];
            }
        }
        __syncthreads();
        int hh = blockIdx.x;
        int d = tid >> 2, kb = (tid & 3) * 32;
        __nv_bfloat16* dst = Vt + (size_t)((bb * HEADS + hh) * 64 + d) * NK + slot0 + kb;
        #pragma unroll
        for (int k = 0; k < 32; k += 2) {
            *(__nv_bfloat162*)(dst + k) =
                __floats2bfloat162_rn(ts[(kb + k) * 65 + d], ts[(kb + k + 1) * 65 + d]);
        }
    }
}

// ================= 2-term O projection: (ctx_h + ctx_l) @ Wo_h^T ============
#define O_AH 0
#define O_AL 16384
#define O_BH 32768
#define O_STG 40960
#define O_SMEM (2*O_STG)   // 81920

__global__ void __launch_bounds__(256, 2) gemm_o(
    const __nv_bfloat16* __restrict__ Ah, const __nv_bfloat16* __restrict__ Al,
    const __nv_bfloat16* __restrict__ Bh,
    float* __restrict__ C) {
    extern __shared__ char sm[];
    uint32_t sb = smem_u32(sm);
    int tid = threadIdx.x;
    int wid = tid >> 5, lane = tid & 31;
    int wm = wid >> 1, wn = wid & 1;
    int rowBase = blockIdx.y * 128;
    int colBase = blockIdx.x * 64;
    int q = lane >> 3, ln8 = lane & 7;

    float acc[2][4][4];
    #pragma unroll
    for (int i = 0; i < 2; i++)
        #pragma unroll
        for (int j = 0; j < 4; j++)
            #pragma unroll
            for (int r = 0; r < 4; r++) acc[i][j][r] = 0.f;

    auto load_chunk = [&](int c, int st) {
        int k0 = c * 64;
        uint32_t so = sb + st * O_STG;
        #pragma unroll
        for (int s = 0; s < 4; s++) {
            int idx = tid + s * 256;
            int row = idx >> 3, ch = idx & 7;
            uint32_t off = (uint32_t)row * 128 + (uint32_t)((ch ^ (row & 7)) * 16);
            CP_ASYNC16(so + O_AH + off, Ah + (size_t)(rowBase + row) * HID + k0 + ch * 8);
            CP_ASYNC16(so + O_AL + off, Al + (size_t)(rowBase + row) * HID + k0 + ch * 8);
        }
        #pragma unroll
        for (int s = 0; s < 2; s++) {
            int idx = tid + s * 256;
            int row = idx >> 3, ch = idx & 7;
            uint32_t off = (uint32_t)row * 128 + (uint32_t)((ch ^ (row & 7)) * 16);
            CP_ASYNC16(so + O_BH + off, Bh + (size_t)(colBase + row) * HID + k0 + ch * 8);
        }
        CP_COMMIT();
    };

    load_chunk(0, 0);

    for (int c = 0; c < 16; c++) {
        if (c < 15) { load_chunk(c + 1, (c + 1) & 1); CP_WAIT1(); }
        else        { CP_WAIT0(); }
        __syncthreads();
        uint32_t stBase = sb + (c & 1) * O_STG;
        #pragma unroll
        for (int pass = 0; pass < 2; pass++) {
            uint32_t Ab = stBase + ((pass == 0) ? O_AH : O_AL);
            uint32_t Bb = stBase + O_BH;
            #pragma unroll
            for (int ti = 0; ti < 4; ti++) {
                uint32_t af[2][4];
                #pragma unroll
                for (int mi = 0; mi < 2; mi++) {
                    int row = wm * 32 + mi * 16 + (q & 1) * 8 + ln8;
                    int ch = ti * 2 + (q >> 1);
                    ldsm4(af[mi], Ab + row * 128 + ((ch ^ (row & 7)) * 16));
                }
                uint32_t bf[2][4];
                #pragma unroll
                for (int g = 0; g < 2; g++) {
                    int row = wn * 32 + g * 16 + (q >> 1) * 8 + ln8;
                    int ch = ti * 2 + (q & 1);
                    ldsm4(bf[g], Bb + row * 128 + ((ch ^ (row & 7)) * 16));
                }
                #pragma unroll
                for (int mi = 0; mi < 2; mi++) {
                    mma16816(acc[mi][0], af[mi], &bf[0][0]);
                    mma16816(acc[mi][1], af[mi], &bf[0][2]);
                    mma16816(acc[mi][2], af[mi], &bf[1][0]);
                    mma16816(acc[mi][3], af[mi], &bf[1][2]);
                }
            }
        }
        __syncthreads();
    }

    int r0 = rowBase + wm * 32 + (lane >> 2);
    int c0 = colBase + wn * 32 + (lane & 3) * 2;
    #pragma unroll
    for (int mi = 0; mi < 2; mi++) {
        #pragma unroll
        for (int ni = 0; ni < 4; ni++) {
            int rr = r0 + mi * 16;
            int cc = c0 + ni * 8;
            *(float2*)&C[(size_t)rr * HID + cc] = make_float2(acc[mi][ni][0], acc[mi][ni][1]);
            *(float2*)&C[(size_t)(rr + 8) * HID + cc] = make_float2(acc[mi][ni][2], acc[mi][ni][3]);
        }
    }
}

// ================= HMMA flash attention: 3-stage, 128 q/CTA, 256 threads ====
#define AS_Q 0
#define AS_STG 16384
#define AS_KH 0
#define AS_VT 8192
#define AS_BIAS 16384
#define AS_STGSZ 17408
#define AT_SMEM (AS_STG + 3*AS_STGSZ)   // 68608

__global__ void __launch_bounds__(256) attn_hmma(
    const int* __restrict__ qt_ids, const int* __restrict__ nv,
    const __nv_bfloat16* __restrict__ Qs,
    const __nv_bfloat16* __restrict__ Ks,
    const __nv_bfloat16* __restrict__ Vt,
    const float* __restrict__ biasg,
    __nv_bfloat16* __restrict__ ctxh, __nv_bfloat16* __restrict__ ctxl) {
    extern __shared__ char sm[];
    uint32_t sb = smem_u32(sm);
    int tid = threadIdx.x, w = tid >> 5, lane = tid & 31;
    int q0 = blockIdx.x * 128, h = blockIdx.y, b = blockIdx.z;
    int group = lane >> 2, qp = lane & 3;
    int q8 = lane >> 3, ln8 = lane & 7;
    int ntiles = (nv[b] + 63) >> 6;

    #pragma unroll
    for (int s = 0; s < 4; s++) {
        int idx = tid + s * 256;
        int r = idx >> 3, ch = idx & 7;
        size_t go = (size_t)(b * NQ + q0 + r) * HID + h * 64 + ch * 8;
        uint32_t off = (uint32_t)r * 128 + (uint32_t)((ch ^ (r & 7)) * 16);
        *(uint4*)(sm + AS_Q + off) = *(const uint4*)(Qs + go);
    }

    auto load_stage = [&](int t, int st) {
        int k0 = t * 64;
        uint32_t so = sb + AS_STG + st * AS_STGSZ;
        #pragma unroll
        for (int s = 0; s < 4; s++) {
            int idx = tid + s * 256;
            int m = idx >> 9;
            int rc = idx & 511;
            int r = rc >> 3, ch = rc & 7;
            uint32_t off = so + m * 8192 + (uint32_t)r * 128 + (uint32_t)((ch ^ (r & 7)) * 16);
            const __nv_bfloat16* src;
            if (m == 0) src = Ks + (size_t)(b * NK + k0 + r) * HID + h * 64 + ch * 8;
            else        src = Vt + (size_t)((b * HEADS + h) * 64 + r) * NK + k0 + ch * 8;
            CP_ASYNC16(off, src);
        }
        if (tid < 48) {
            int qt = tid >> 4, j = tid & 15;
            CP_ASYNC16(so + AS_BIAS + qt * 256 + j * 16,
                       biasg + (size_t)(b * 3 + qt) * NK + k0 + j * 4);
        }
        CP_COMMIT();
    };

    load_stage(0, 0);
    __syncthreads();

    uint32_t QHf[4][4];
    #pragma unroll
    for (int c2 = 0; c2 < 4; c2++) {
        int r = w * 16 + (lane & 15);
        int ch = c2 * 2 + (lane >> 4);
        uint32_t off = (uint32_t)r * 128 + (uint32_t)((ch ^ (r & 7)) * 16);
        ldsm4(QHf[c2], sb + AS_Q + off);
    }
    int qtA = qt_ids[q0 + w * 16 + group];
    int qtB = qt_ids[q0 + w * 16 + group + 8];

    float acc[8][4];
    #pragma unroll
    for (int i = 0; i < 8; i++)
        #pragma unroll
        for (int j = 0; j < 4; j++) acc[i][j] = 0.f;
    float lA = 0.f, lB = 0.f;

    int st_ld = 1, st_cp = 0;
    for (int t = 0; t < ntiles; t++) {
        if (t + 1 < ntiles) { load_stage(t + 1, st_ld); if (++st_ld == 3) st_ld = 0; CP_WAIT1(); }
        else                { CP_WAIT0(); }
        __syncthreads();
        uint32_t st = sb + AS_STG + st_cp * AS_STGSZ;
        char*    stc = sm + AS_STG + st_cp * AS_STGSZ;
        if (++st_cp == 3) st_cp = 0;

        float S[8][4];
        #pragma unroll
        for (int np = 0; np < 4; np++) {
            #pragma unroll
            for (int j = 0; j < 4; j++) { S[2*np][j] = 0.f; S[2*np+1][j] = 0.f; }
            #pragma unroll
            for (int c2 = 0; c2 < 4; c2++) {
                int row = np * 16 + (q8 >> 1) * 8 + ln8;
                int ch = c2 * 2 + (q8 & 1);
                uint32_t off = (uint32_t)row * 128 + (uint32_t)((ch ^ (row & 7)) * 16);
                uint32_t kh[4];
                ldsm4(kh, st + AS_KH + off);
                mma16816(S[2*np],   QHf[c2], &kh[0]);
                mma16816(S[2*np+1], QHf[c2], &kh[2]);
            }
        }

        const float* bA = (const float*)(stc + AS_BIAS) + qtA * 64;
        const float* bB = (const float*)(stc + AS_BIAS) + qtB * 64;
        uint32_t P[4][4];
        #pragma unroll
        for (int kc = 0; kc < 4; kc++) {
            int t0 = kc * 2, t1 = t0 + 1;
            float2 a0 = *(const float2*)(bA + t0 * 8 + qp * 2);
            float2 b0 = *(const float2*)(bB + t0 * 8 + qp * 2);
            float2 a1 = *(const float2*)(bA + t1 * 8 + qp * 2);
            float2 b1 = *(const float2*)(bB + t1 * 8 + qp * 2);
            float p00 = exp2m(S[t0][0] + a0.x), p01 = exp2m(S[t0][1] + a0.y);
            float p02 = exp2m(S[t0][2] + b0.x), p03 = exp2m(S[t0][3] + b0.y);
            float p10 = exp2m(S[t1][0] + a1.x), p11 = exp2m(S[t1][1] + a1.y);
            float p12 = exp2m(S[t1][2] + b1.x), p13 = exp2m(S[t1][3] + b1.y);
            lA += p00 + p01 + p10 + p11;
            lB += p02 + p03 + p12 + p13;
            __nv_bfloat162 tt;
            tt = __floats2bfloat162_rn(p00, p01); P[kc][0] = *(uint32_t*)&tt;
            tt = __floats2bfloat162_rn(p02, p03); P[kc][1] = *(uint32_t*)&tt;
            tt = __floats2bfloat162_rn(p10, p11); P[kc][2] = *(uint32_t*)&tt;
            tt = __floats2bfloat162_rn(p12, p13); P[kc][3] = *(uint32_t*)&tt;
        }

        #pragma unroll
        for (int kc = 0; kc < 4; kc++) {
            #pragma unroll
            for (int tdp = 0; tdp < 4; tdp++) {
                int row = tdp * 16 + (q8 >> 1) * 8 + ln8;
                int ch = kc * 2 + (q8 & 1);
                uint32_t off = (uint32_t)row * 128 + (uint32_t)((ch ^ (row & 7)) * 16);
                uint32_t v4[4];
                ldsm4(v4, st + AS_VT + off);
                mma16816(acc[2*tdp],   P[kc], &v4[0]);
                mma16816(acc[2*tdp+1], P[kc], &v4[2]);
            }
        }
        // no trailing sync (3-stage)
    }

    lA += __shfl_xor_sync(0xffffffffu, lA, 1);
    lA += __shfl_xor_sync(0xffffffffu, lA, 2);
    lB += __shfl_xor_sync(0xffffffffu, lB, 1);
    lB += __shfl_xor_sync(0xffffffffu, lB, 2);
    float iA = 1.f / lA, iB = 1.f / lB;

    int rowA = q0 + w * 16 + group, rowB = rowA + 8;
    #pragma unroll
    for (int td = 0; td < 8; td++) {
        int col = h * 64 + td * 8 + qp * 2;
        float v0 = acc[td][0] * iA, v1 = acc[td][1] * iA;
        float v2 = acc[td][2] * iB, v3 = acc[td][3] * iB;
        __nv_bfloat16 h0,h1,h2,h3,l0,l1,l2,l3;
        split_bf16(v0,h0,l0); split_bf16(v1,h1,l1);
        split_bf16(v2,h2,l2); split_bf16(v3,h3,l3);
        size_t oA = (size_t)(b * NQ + rowA) * HID + col;
        size_t oB = (size_t)(b * NQ + rowB) * HID + col;
        *(__nv_bfloat162*)&ctxh[oA] = __nv_bfloat162(h0, h1);
        *(__nv_bfloat162*)&ctxl[oA] = __nv_bfloat162(l0, l1);
        *(__nv_bfloat162*)&ctxh[oB] = __nv_bfloat162(h2, h3);
        *(__nv_bfloat162*)&ctxl[oB] = __nv_bfloat162(l2, l3);
    }
}

// ---------------- launch ----------------------------------------------------
extern "C" void kernel_launch(void* const* d_in, const int* in_sizes, int n_in,
                              void* d_out, int out_size) {
    const float* queries = (const float*)d_in[0];
    const float* kv      = (const float*)d_in[1];
    const int*   qt_ids  = (const int*)d_in[2];
    const int*   kt_ids  = (const int*)d_in[3];
    const int*   pad     = (const int*)d_in[4];
    const float* Wq   = (const float*)d_in[5];
    const float* Wk   = (const float*)d_in[6];
    const float* Wv   = (const float*)d_in[7];
    const float* Wo   = (const float*)d_in[8];
    const float* qn_w = (const float*)d_in[9];
    const float* qn_b = (const float*)d_in[10];
    const float* kvn_w = (const float*)d_in[11];
    const float* kvn_b = (const float*)d_in[12];
    const float* on_w = (const float*)d_in[13];
    const float* on_b = (const float*)d_in[14];
    const float* tb   = (const float*)d_in[15];
    float* out = (float*)d_out;

    float *p_o, *p_bias;
    int *p_nv, *p_cidx;
    __nv_bfloat16 *p_qn, *p_kvn, *p_wq, *p_wk, *p_wv, *p_wo_h;
    __nv_bfloat16 *p_qs, *p_ks, *p_vt, *p_ctx_h, *p_ctx_l;
    cudaGetSymbolAddress((void**)&p_o,    g_o);
    cudaGetSymbolAddress((void**)&p_bias, g_bias);
    cudaGetSymbolAddress((void**)&p_nv,   g_nv);
    cudaGetSymbolAddress((void**)&p_cidx, g_cidx);
    cudaGetSymbolAddress((void**)&p_qn,   g_qn);
    cudaGetSymbolAddress((void**)&p_kvn,  g_kvn);
    cudaGetSymbolAddress((void**)&p_wq,   g_wq_h);
    cudaGetSymbolAddress((void**)&p_wk,   g_wk_h);
    cudaGetSymbolAddress((void**)&p_wv,   g_wv_h);
    cudaGetSymbolAddress((void**)&p_wo_h, g_wo_h);
    cudaGetSymbolAddress((void**)&p_qs,   g_qs);
    cudaGetSymbolAddress((void**)&p_ks,   g_ks);
    cudaGetSymbolAddress((void**)&p_vt,   g_vt);
    cudaGetSymbolAddress((void**)&p_ctx_h, g_ctx_h);
    cudaGetSymbolAddress((void**)&p_ctx_l, g_ctx_l);

    static int attr_set = 0;
    if (!attr_set) {
        cudaFuncSetAttribute(gemm_q,  cudaFuncAttributeMaxDynamicSharedMemorySize, G1_SMEM);
        cudaFuncSetAttribute(gemm_kv, cudaFuncAttributeMaxDynamicSharedMemorySize, KV_SMEM);
        cudaFuncSetAttribute(gemm_o,  cudaFuncAttributeMaxDynamicSharedMemorySize, O_SMEM);
        cudaFuncSetAttribute(attn_hmma, cudaFuncAttributeMaxDynamicSharedMemorySize, AT_SMEM);
        attr_set = 1;
    }

    // 0. key compaction + bias table (fused)
    compact_bias_kernel<<<BATCH, 1024>>>(pad, kt_ids, tb, p_nv, p_cidx, p_bias);

    // 1. LN + weight prep (one launch, block-range dispatch)
    prep_all<<<MQ + MK + 2048, 256>>>(queries, kv, qn_w, qn_b, kvn_w, kvn_b,
                                      Wq, Wk, Wv, Wo,
                                      p_qn, p_kvn, p_wq, p_wk, p_wv, p_wo_h);

    // 2. projections
    {
        dim3 gq(HID / 64, MQ / 128);
        dim3 gk(HID / 64, MK / 128);
        gemm_q<<<gq, 256, G1_SMEM>>>(p_qn, p_wq, p_qs);
        gemm_kv<<<gk, 256, KV_SMEM>>>(p_kvn, p_wk, p_wv, p_ks, p_vt, p_cidx, p_nv);
    }

    // 3. flash attention -> ctx hi/lo
    {
        dim3 ga(NQ / 128, HEADS, BATCH);
        attn_hmma<<<ga, 256, AT_SMEM>>>(qt_ids, p_nv, p_qs, p_ks, p_vt, p_bias,
                                        p_ctx_h, p_ctx_l);
    }

    // 4. output projection (2-term)
    {
        dim3 go(HID / 64, MQ / 128);
        gemm_o<<<go, 256, O_SMEM>>>(p_ctx_h, p_ctx_l, p_wo_h, p_o);
    }

    // 5. residual + LN -> d_out
    res_ln_kernel<<<MQ, 256>>>(queries, p_o, on_w, on_b, out);
}

// round 15
// speedup vs baseline: 14.7972x; 1.1043x over previous
#include <cuda_runtime.h>
#include <cuda_bf16.h>
#include <math.h>
#include <float.h>
#include <stdint.h>

#define BATCH 2
#define NQ    1024
#define NK    4096
#define HID   1024
#define HEADS 16
#define HD    64
#define LN_EPS 1e-5f
#define LOG2E 1.4426950408889634f
#define QKSCALE (0.125f * LOG2E)
#define M0    32.0f

#define MQ (BATCH*NQ)   // 2048
#define MK (BATCH*NK)   // 8192

// ---------------- scratch (__device__ globals) ------------------------------
__device__ float g_o   [MQ*HID];
__device__ float g_bias[BATCH*3*NK];
__device__ int   g_nv[BATCH];
__device__ int   g_cidx[BATCH*NK];

__device__ __nv_bfloat16 g_qn [MQ*HID];
__device__ __nv_bfloat16 g_kvn[MK*HID];
__device__ __nv_bfloat16 g_wq_h[HID*HID];
__device__ __nv_bfloat16 g_wk_h[HID*HID];
__device__ __nv_bfloat16 g_wv_h[HID*HID];
__device__ __nv_bfloat16 g_wo_h[HID*HID];
__device__ __nv_bfloat16 g_qs [MQ*HID];
__device__ __nv_bfloat16 g_ks [MK*HID];
__device__ __nv_bfloat16 g_vt [MK*HID];       // [(b*H+h)*64 + d][slot]
__device__ __nv_bfloat16 g_ctx[MQ*HID];

// ---------------- small helpers ---------------------------------------------
__device__ __forceinline__ uint32_t smem_u32(const void* p) {
    uint32_t a;
    asm("{ .reg .u64 t; cvta.to.shared.u64 t, %1; cvt.u32.u64 %0, t; }" : "=r"(a) : "l"(p));
    return a;
}

__device__ __forceinline__ float2 block_reduce2(float a, float b, float* sh) {
    #pragma unroll
    for (int o = 16; o; o >>= 1) {
        a += __shfl_xor_sync(0xffffffffu, a, o);
        b += __shfl_xor_sync(0xffffffffu, b, o);
    }
    int w = threadIdx.x >> 5;
    if ((threadIdx.x & 31) == 0) { sh[w] = a; sh[8 + w] = b; }
    __syncthreads();
    if (threadIdx.x == 0) {
        float sa = 0.f, sb = 0.f;
        #pragma unroll
        for (int i = 0; i < 8; i++) { sa += sh[i]; sb += sh[8 + i]; }
        sh[0] = sa; sh[8] = sb;
    }
    __syncthreads();
    return make_float2(sh[0], sh[8]);
}

#define CP_ASYNC16(dst, src) \
    asm volatile("cp.async.cg.shared.global [%0], [%1], 16;" :: "r"(dst), "l"(src))
#define CP_COMMIT() asm volatile("cp.async.commit_group;" ::: "memory")
#define CP_WAIT0()  asm volatile("cp.async.wait_group 0;" ::: "memory")
#define CP_WAIT1()  asm volatile("cp.async.wait_group 1;" ::: "memory")

__device__ __forceinline__ void ldsm4(uint32_t* r, uint32_t addr) {
    asm volatile("ldmatrix.sync.aligned.m8n8.x4.shared.b16 {%0,%1,%2,%3}, [%4];"
                 : "=r"(r[0]), "=r"(r[1]), "=r"(r[2]), "=r"(r[3]) : "r"(addr));
}

__device__ __forceinline__ void mma16816(float* c, const uint32_t* a, const uint32_t* b) {
    asm volatile(
        "mma.sync.aligned.m16n8k16.row.col.f32.bf16.bf16.f32 "
        "{%0,%1,%2,%3}, {%4,%5,%6,%7}, {%8,%9}, {%0,%1,%2,%3};"
        : "+f"(c[0]), "+f"(c[1]), "+f"(c[2]), "+f"(c[3])
        : "r"(a[0]), "r"(a[1]), "r"(a[2]), "r"(a[3]), "r"(b[0]), "r"(b[1]));
}

// fast 2^x for x <= 0 (clamped at -80), magic-rounding + deg-4 poly
__device__ __forceinline__ float exp2m(float x) {
    x = fmaxf(x, -80.f);
    float t = __fadd_rn(x, 12582912.f);
    float r = __fadd_rn(t, -12582912.f);
    float f = x - r;
    int   n = __float_as_int(t) - 0x4B400000;
    float p = 9.6181291e-3f;
    p = fmaf(p, f, 5.5504109e-2f);
    p = fmaf(p, f, 2.4022651e-1f);
    p = fmaf(p, f, 6.9314718e-1f);
    p = fmaf(p, f, 1.0f);
    return __int_as_float((n + 127) << 23) * p;
}

// ------------- key compaction + fused bias table (one block per batch) -------
__global__ void compact_bias_kernel(const int* __restrict__ pad,
                                    const int* __restrict__ kt,
                                    const float* __restrict__ tb,
                                    int* __restrict__ nv, int* __restrict__ cidx,
                                    float* __restrict__ bias) {
    __shared__ int wsum[32];
    __shared__ float tbl[9];
    int b = blockIdx.x, tid = threadIdx.x;
    int lane = tid & 31, w = tid >> 5;
    int base = b * NK;
    if (tid < 9) tbl[tid] = tb[tid] * LOG2E - M0;
    int k0 = tid * 4;
    int f0 = pad[base + k0 + 0] != 0;
    int f1 = pad[base + k0 + 1] != 0;
    int f2 = pad[base + k0 + 2] != 0;
    int f3 = pad[base + k0 + 3] != 0;
    int c = f0 + f1 + f2 + f3;
    int inc = c;
    #pragma unroll
    for (int o = 1; o < 32; o <<= 1) {
        int t = __shfl_up_sync(0xffffffffu, inc, o);
        if (lane >= o) inc += t;
    }
    if (lane == 31) wsum[w] = inc;
    __syncthreads();
    if (w == 0) {
        int v = wsum[lane];
        #pragma unroll
        for (int o = 1; o < 32; o <<= 1) {
            int t = __shfl_up_sync(0xffffffffu, v, o);
            if (lane >= o) v += t;
        }
        wsum[lane] = v;
    }
    __syncthreads();
    int pos = inc - c + (w ? wsum[w - 1] : 0);
    if (f0) cidx[base + pos++] = k0 + 0;
    if (f1) cidx[base + pos++] = k0 + 1;
    if (f2) cidx[base + pos++] = k0 + 2;
    if (f3) cidx[base + pos++] = k0 + 3;
    int total = wsum[31];
    if (tid == 0) nv[b] = total;
    for (int s = total + tid; s < NK; s += 1024) cidx[base + s] = 0;
    __syncthreads();
    for (int s = tid; s < NK; s += 1024) {
        float t0, t1, t2;
        if (s < total) {
            int cc = kt[cidx[base + s]];
            t0 = tbl[cc]; t1 = tbl[3 + cc]; t2 = tbl[6 + cc];
        } else {
            t0 = t1 = t2 = -1e30f;
        }
        bias[(size_t)(b * 3 + 0) * NK + s] = t0;
        bias[(size_t)(b * 3 + 1) * NK + s] = t1;
        bias[(size_t)(b * 3 + 2) * NK + s] = t2;
    }
}

// ---- merged prep: LN (queries + kv) -> bf16, then 4x weight -> bf16 hi ------
__global__ void prep_all(const float* __restrict__ xq, const float* __restrict__ xk,
                         const float* __restrict__ qw, const float* __restrict__ qb,
                         const float* __restrict__ kw, const float* __restrict__ kb,
                         const float* __restrict__ w0, const float* __restrict__ w1,
                         const float* __restrict__ w2, const float* __restrict__ w3,
                         __nv_bfloat16* __restrict__ oq, __nv_bfloat16* __restrict__ ok,
                         __nv_bfloat16* __restrict__ h0, __nv_bfloat16* __restrict__ h1,
                         __nv_bfloat16* __restrict__ h2, __nv_bfloat16* __restrict__ h3) {
    __shared__ float sh[16];
    int bid = blockIdx.x;
    if (bid < MQ + MK) {
        size_t row = bid;
        const float* x; const float* w; const float* b; __nv_bfloat16* oh;
        if (row < MQ) { x = xq + row * HID; w = qw; b = qb; oh = oq + row * HID; }
        else { size_t r2 = row - MQ; x = xk + r2 * HID; w = kw; b = kb; oh = ok + r2 * HID; }
        float4 v = ((const float4*)x)[threadIdx.x];
        float s  = v.x + v.y + v.z + v.w;
        float s2 = v.x*v.x + v.y*v.y + v.z*v.z + v.w*v.w;
        float2 r = block_reduce2(s, s2, sh);
        float mean = r.x * (1.f / HID);
        float var  = r.y * (1.f / HID) - mean * mean;
        float rstd = rsqrtf(var + LN_EPS);
        float4 wv = ((const float4*)w)[threadIdx.x];
        float4 bv = ((const float4*)b)[threadIdx.x];
        float o0 = (v.x - mean) * rstd * wv.x + bv.x;
        float o1 = (v.y - mean) * rstd * wv.y + bv.y;
        float o2 = (v.z - mean) * rstd * wv.z + bv.z;
        float o3 = (v.w - mean) * rstd * wv.w + bv.w;
        __nv_bfloat162* ph = (__nv_bfloat162*)(oh + threadIdx.x * 4);
        ph[0] = __floats2bfloat162_rn(o0, o1);
        ph[1] = __floats2bfloat162_rn(o2, o3);
    } else {
        int blk = bid - (MQ + MK);
        int wi = blk >> 9, ib = blk & 511;
        const float* src = (wi == 0) ? w0 : (wi == 1) ? w1 : (wi == 2) ? w2 : w3;
        __nv_bfloat16* dh = (wi == 0) ? h0 : (wi == 1) ? h1 : (wi == 2) ? h2 : h3;
        const int n4 = HID * HID / 4;
        for (int i = ib * 256 + threadIdx.x; i < n4; i += 512 * 256) {
            float4 v = ((const float4*)src)[i];
            __nv_bfloat162* ph = (__nv_bfloat162*)(dh + (size_t)i * 4);
            ph[0] = __floats2bfloat162_rn(v.x, v.y);
            ph[1] = __floats2bfloat162_rn(v.z, v.w);
        }
    }
}

// -------- residual + LayerNorm -----------------------------------------------
__global__ void res_ln_kernel(const float* __restrict__ x,
                              const float* __restrict__ y,
                              const float* __restrict__ w,
                              const float* __restrict__ b,
                              float* __restrict__ out) {
    __shared__ float sh[16];
    size_t row = blockIdx.x;
    float4 v  = ((const float4*)(x + row * HID))[threadIdx.x];
    float4 yv = ((const float4*)(y + row * HID))[threadIdx.x];
    v.x += yv.x; v.y += yv.y; v.z += yv.z; v.w += yv.w;
    float s  = v.x + v.y + v.z + v.w;
    float s2 = v.x*v.x + v.y*v.y + v.z*v.z + v.w*v.w;
    float2 r = block_reduce2(s, s2, sh);
    float mean = r.x * (1.f / HID);
    float var  = r.y * (1.f / HID) - mean * mean;
    float rstd = rsqrtf(var + LN_EPS);
    float4 wv = ((const float4*)w)[threadIdx.x];
    float4 bv = ((const float4*)b)[threadIdx.x];
    float4 o;
    o.x = (v.x - mean) * rstd * wv.x + bv.x;
    o.y = (v.y - mean) * rstd * wv.y + bv.y;
    o.z = (v.z - mean) * rstd * wv.z + bv.z;
    o.w = (v.w - mean) * rstd * wv.w + bv.w;
    ((float4*)(out + row * HID))[threadIdx.x] = o;
}

// ======== unified projections: Q (y>=KV_Y) + fused K/V (y<KV_Y) ==============
// 3-stage pipeline. KV path: gathered A, dual B, K row-major + V transposed out.
// Q path: dense A from qn, single B (Wq), scaled bf16 out.
#define KV_A 0
#define KV_BK 16384
#define KV_BV 24576
#define KV_STG 32768
#define KV_SMEM (3*KV_STG)   // 98304
#define KV_Y (MK/128)        // 64

__global__ void __launch_bounds__(256) gemm_proj(
    const __nv_bfloat16* __restrict__ A,   // kvn
    const __nv_bfloat16* __restrict__ Aq,  // qn
    const __nv_bfloat16* __restrict__ Bk, const __nv_bfloat16* __restrict__ Bv,
    const __nv_bfloat16* __restrict__ Bq,
    __nv_bfloat16* __restrict__ Ks, __nv_bfloat16* __restrict__ Vt,
    __nv_bfloat16* __restrict__ Qs,
    const int* __restrict__ cidx, const int* __restrict__ nv) {
    extern __shared__ char sm[];
    uint32_t sb = smem_u32(sm);
    int tid = threadIdx.x;
    int wid = tid >> 5, lane = tid & 31;
    int wm = wid >> 1, wn = wid & 1;
    int colBase = blockIdx.x * 64;
    int q = lane >> 3, ln8 = lane & 7;
    bool kvPath = (blockIdx.y < KV_Y);

    if (kvPath) {
        int rowBase = blockIdx.y * 128;
        int bb = rowBase / NK;
        int slot0 = rowBase % NK;
        if (slot0 >= ((nv[bb] + 63) & ~63)) return;

        const __nv_bfloat16* pA[4];
        #pragma unroll
        for (int s = 0; s < 4; s++) {
            int slot = slot0 + (tid >> 3) + 32 * s;
            int ar = cidx[bb * NK + slot];
            pA[s] = A + (size_t)(bb * NK + ar) * HID + (tid & 7) * 8;
        }

        float acck[2][4][4], accv[2][4][4];
        #pragma unroll
        for (int i = 0; i < 2; i++)
            #pragma unroll
            for (int j = 0; j < 4; j++)
                #pragma unroll
                for (int r = 0; r < 4; r++) { acck[i][j][r] = 0.f; accv[i][j][r] = 0.f; }

        auto load_chunk = [&](int c, int st) {
            int k0 = c * 64;
            uint32_t so = sb + st * KV_STG;
            #pragma unroll
            for (int s = 0; s < 4; s++) {
                int row = (tid >> 3) + 32 * s, ch = tid & 7;
                uint32_t off = (uint32_t)row * 128 + (uint32_t)((ch ^ (row & 7)) * 16);
                CP_ASYNC16(so + KV_A + off, pA[s] + k0);
            }
            #pragma unroll
            for (int s = 0; s < 2; s++) {
                int idx = tid + s * 256;
                int row = idx >> 3, ch = idx & 7;
                uint32_t off = (uint32_t)row * 128 + (uint32_t)((ch ^ (row & 7)) * 16);
                CP_ASYNC16(so + KV_BK + off, Bk + (size_t)(colBase + row) * HID + k0 + ch * 8);
                CP_ASYNC16(so + KV_BV + off, Bv + (size_t)(colBase + row) * HID + k0 + ch * 8);
            }
            CP_COMMIT();
        };

        load_chunk(0, 0);
        int st_ld = 1, st_cp = 0;

        for (int c = 0; c < 16; c++) {
            if (c < 15) { load_chunk(c + 1, st_ld); if (++st_ld == 3) st_ld = 0; CP_WAIT1(); }
            else        { CP_WAIT0(); }
            __syncthreads();
            uint32_t Ab  = sb + st_cp * KV_STG + KV_A;
            uint32_t Bkb = sb + st_cp * KV_STG + KV_BK;
            uint32_t Bvb = sb + st_cp * KV_STG + KV_BV;
            if (++st_cp == 3) st_cp = 0;
            #pragma unroll
            for (int ti = 0; ti < 4; ti++) {
                uint32_t af[2][4];
                #pragma unroll
                for (int mi = 0; mi < 2; mi++) {
                    int row = wm * 32 + mi * 16 + (q & 1) * 8 + ln8;
                    int ch = ti * 2 + (q >> 1);
                    ldsm4(af[mi], Ab + row * 128 + ((ch ^ (row & 7)) * 16));
                }
                uint32_t bk[2][4], bv[2][4];
                #pragma unroll
                for (int g = 0; g < 2; g++) {
                    int row = wn * 32 + g * 16 + (q >> 1) * 8 + ln8;
                    int ch = ti * 2 + (q & 1);
                    uint32_t off = row * 128 + ((ch ^ (row & 7)) * 16);
                    ldsm4(bk[g], Bkb + off);
                    ldsm4(bv[g], Bvb + off);
                }
                #pragma unroll
                for (int mi = 0; mi < 2; mi++) {
                    mma16816(acck[mi][0], af[mi], &bk[0][0]);
                    mma16816(acck[mi][1], af[mi], &bk[0][2]);
                    mma16816(acck[mi][2], af[mi], &bk[1][0]);
                    mma16816(acck[mi][3], af[mi], &bk[1][2]);
                    mma16816(accv[mi][0], af[mi], &bv[0][0]);
                    mma16816(accv[mi][1], af[mi], &bv[0][2]);
                    mma16816(accv[mi][2], af[mi], &bv[1][0]);
                    mma16816(accv[mi][3], af[mi], &bv[1][2]);
                }
            }
        }

        // K epilogue: bf16 row-major
        {
            int r0 = rowBase + wm * 32 + (lane >> 2);
            int c0 = colBase + wn * 32 + (lane & 3) * 2;
            #pragma unroll
            for (int mi = 0; mi < 2; mi++) {
                #pragma unroll
                for (int ni = 0; ni < 4; ni++) {
                    int rr = r0 + mi * 16;
                    int cc = c0 + ni * 8;
                    *(__nv_bfloat162*)&Ks[(size_t)rr * HID + cc] =
                        __floats2bfloat162_rn(acck[mi][ni][0], acck[mi][ni][1]);
                    *(__nv_bfloat162*)&Ks[(size_t)(rr + 8) * HID + cc] =
                        __floats2bfloat162_rn(acck[mi][ni][2], acck[mi][ni][3]);
                }
            }
        }

        // V epilogue: transpose through smem -> Vt[(b,h,d)][slot]
        __syncthreads();
        {
            float* ts = (float*)sm;
            int r0l = wm * 32 + (lane >> 2);
            int c0l = wn * 32 + (lane & 3) * 2;
            #pragma unroll
            for (int mi = 0; mi < 2; mi++) {
                #pragma unroll
                for (int ni = 0; ni < 4; ni++) {
                    int rr = r0l + mi * 16, cc = c0l + ni * 8;
                    ts[rr * 65 + cc] = accv[mi][ni][0];
                    ts[rr * 65 + cc + 1] = accv[mi][ni][1];
                    ts[(rr + 8) * 65 + cc] = accv[mi][ni][2];
                    ts[(rr + 8) * 65 + cc + 1] = accv[mi][ni][3];
                }
            }
            __syncthreads();
            int hh = blockIdx.x;
            int d = tid >> 2, kb = (tid & 3) * 32;
            __nv_bfloat16* dst = Vt + (size_t)((bb * HEADS + hh) * 64 + d) * NK + slot0 + kb;
            #pragma unroll
            for (int k = 0; k < 32; k += 2) {
                *(__nv_bfloat162*)(dst + k) =
                    __floats2bfloat162_rn(ts[(kb + k) * 65 + d], ts[(kb + k + 1) * 65 + d]);
            }
        }
    } else {
        // ---------------- Q path: dense A, single B ----------------
        int rowBase = (blockIdx.y - KV_Y) * 128;

        float acc[2][4][4];
        #pragma unroll
        for (int i = 0; i < 2; i++)
            #pragma unroll
            for (int j = 0; j < 4; j++)
                #pragma unroll
                for (int r = 0; r < 4; r++) acc[i][j][r] = 0.f;

        auto load_chunk = [&](int c, int st) {
            int k0 = c * 64;
            uint32_t so = sb + st * KV_STG;
            #pragma unroll
            for (int s = 0; s < 4; s++) {
                int row = (tid >> 3) + 32 * s, ch = tid & 7;
                uint32_t off = (uint32_t)row * 128 + (uint32_t)((ch ^ (row & 7)) * 16);
                CP_ASYNC16(so + KV_A + off,
                           Aq + (size_t)(rowBase + row) * HID + k0 + (tid & 7) * 8);
            }
            #pragma unroll
            for (int s = 0; s < 2; s++) {
                int idx = tid + s * 256;
                int row = idx >> 3, ch = idx & 7;
                uint32_t off = (uint32_t)row * 128 + (uint32_t)((ch ^ (row & 7)) * 16);
                CP_ASYNC16(so + KV_BK + off, Bq + (size_t)(colBase + row) * HID + k0 + ch * 8);
            }
            CP_COMMIT();
        };

        load_chunk(0, 0);
        int st_ld = 1, st_cp = 0;

        for (int c = 0; c < 16; c++) {
            if (c < 15) { load_chunk(c + 1, st_ld); if (++st_ld == 3) st_ld = 0; CP_WAIT1(); }
            else        { CP_WAIT0(); }
            __syncthreads();
            uint32_t Ab = sb + st_cp * KV_STG + KV_A;
            uint32_t Bb = sb + st_cp * KV_STG + KV_BK;
            if (++st_cp == 3) st_cp = 0;
            #pragma unroll
            for (int ti = 0; ti < 4; ti++) {
                uint32_t af[2][4];
                #pragma unroll
                for (int mi = 0; mi < 2; mi++) {
                    int row = wm * 32 + mi * 16 + (q & 1) * 8 + ln8;
                    int ch = ti * 2 + (q >> 1);
                    ldsm4(af[mi], Ab + row * 128 + ((ch ^ (row & 7)) * 16));
                }
                uint32_t bf[2][4];
                #pragma unroll
                for (int g = 0; g < 2; g++) {
                    int row = wn * 32 + g * 16 + (q >> 1) * 8 + ln8;
                    int ch = ti * 2 + (q & 1);
                    ldsm4(bf[g], Bb + row * 128 + ((ch ^ (row & 7)) * 16));
                }
                #pragma unroll
                for (int mi = 0; mi < 2; mi++) {
                    mma16816(acc[mi][0], af[mi], &bf[0][0]);
                    mma16816(acc[mi][1], af[mi], &bf[0][2]);
                    mma16816(acc[mi][2], af[mi], &bf[1][0]);
                    mma16816(acc[mi][3], af[mi], &bf[1][2]);
                }
            }
        }

        int r0 = rowBase + wm * 32 + (lane >> 2);
        int c0 = colBase + wn * 32 + (lane & 3) * 2;
        #pragma unroll
        for (int mi = 0; mi < 2; mi++) {
            #pragma unroll
            for (int ni = 0; ni < 4; ni++) {
                int rr = r0 + mi * 16;
                int cc = c0 + ni * 8;
                *(__nv_bfloat162*)&Qs[(size_t)rr * HID + cc] =
                    __floats2bfloat162_rn(acc[mi][ni][0] * QKSCALE, acc[mi][ni][1] * QKSCALE);
                *(__nv_bfloat162*)&Qs[(size_t)(rr + 8) * HID + cc] =
                    __floats2bfloat162_rn(acc[mi][ni][2] * QKSCALE, acc[mi][ni][3] * QKSCALE);
            }
        }
    }
}

// ============ O projection: 1-term bf16 (ctx @ Wo_h^T), fp32 out, 3-stage ===
#define O_A 0
#define O_B 16384
#define O_STG 24576
#define O_SMEM (3*O_STG)   // 73728

__global__ void __launch_bounds__(256, 2) gemm_o(
    const __nv_bfloat16* __restrict__ A, const __nv_bfloat16* __restrict__ B,
    float* __restrict__ C) {
    extern __shared__ char sm[];
    uint32_t sb = smem_u32(sm);
    int tid = threadIdx.x;
    int wid = tid >> 5, lane = tid & 31;
    int wm = wid >> 1, wn = wid & 1;
    int rowBase = blockIdx.y * 128;
    int colBase = blockIdx.x * 64;
    int q = lane >> 3, ln8 = lane & 7;

    float acc[2][4][4];
    #pragma unroll
    for (int i = 0; i < 2; i++)
        #pragma unroll
        for (int j = 0; j < 4; j++)
            #pragma unroll
            for (int r = 0; r < 4; r++) acc[i][j][r] = 0.f;

    auto load_chunk = [&](int c, int st) {
        int k0 = c * 64;
        uint32_t so = sb + st * O_STG;
        #pragma unroll
        for (int s = 0; s < 4; s++) {
            int row = (tid >> 3) + 32 * s, ch = tid & 7;
            uint32_t off = (uint32_t)row * 128 + (uint32_t)((ch ^ (row & 7)) * 16);
            CP_ASYNC16(so + O_A + off, A + (size_t)(rowBase + row) * HID + k0 + ch * 8);
        }
        #pragma unroll
        for (int s = 0; s < 2; s++) {
            int idx = tid + s * 256;
            int row = idx >> 3, ch = idx & 7;
            uint32_t off = (uint32_t)row * 128 + (uint32_t)((ch ^ (row & 7)) * 16);
            CP_ASYNC16(so + O_B + off, B + (size_t)(colBase + row) * HID + k0 + ch * 8);
        }
        CP_COMMIT();
    };

    load_chunk(0, 0);
    int st_ld = 1, st_cp = 0;

    for (int c = 0; c < 16; c++) {
        if (c < 15) { load_chunk(c + 1, st_ld); if (++st_ld == 3) st_ld = 0; CP_WAIT1(); }
        else        { CP_WAIT0(); }
        __syncthreads();
        uint32_t Ab = sb + st_cp * O_STG + O_A;
        uint32_t Bb = sb + st_cp * O_STG + O_B;
        if (++st_cp == 3) st_cp = 0;
        #pragma unroll
        for (int ti = 0; ti < 4; ti++) {
            uint32_t af[2][4];
            #pragma unroll
            for (int mi = 0; mi < 2; mi++) {
                int row = wm * 32 + mi * 16 + (q & 1) * 8 + ln8;
                int ch = ti * 2 + (q >> 1);
                ldsm4(af[mi], Ab + row * 128 + ((ch ^ (row & 7)) * 16));
            }
            uint32_t bf[2][4];
            #pragma unroll
            for (int g = 0; g < 2; g++) {
                int row = wn * 32 + g * 16 + (q >> 1) * 8 + ln8;
                int ch = ti * 2 + (q & 1);
                ldsm4(bf[g], Bb + row * 128 + ((ch ^ (row & 7)) * 16));
            }
            #pragma unroll
            for (int mi = 0; mi < 2; mi++) {
                mma16816(acc[mi][0], af[mi], &bf[0][0]);
                mma16816(acc[mi][1], af[mi], &bf[0][2]);
                mma16816(acc[mi][2], af[mi], &bf[1][0]);
                mma16816(acc[mi][3], af[mi], &bf[1][2]);
            }
        }
    }

    int r0 = rowBase + wm * 32 + (lane >> 2);
    int c0 = colBase + wn * 32 + (lane & 3) * 2;
    #pragma unroll
    for (int mi = 0; mi < 2; mi++) {
        #pragma unroll
        for (int ni = 0; ni < 4; ni++) {
            int rr = r0 + mi * 16;
            int cc = c0 + ni * 8;
            *(float2*)&C[(size_t)rr * HID + cc] = make_float2(acc[mi][ni][0], acc[mi][ni][1]);
            *(float2*)&C[(size_t)(rr + 8) * HID + cc] = make_float2(acc[mi][ni][2], acc[mi][ni][3]);
        }
    }
}

// ================= HMMA flash attention: 3-stage, 128 q/CTA, 256 threads ====
#define AS_Q 0
#define AS_STG 16384
#define AS_KH 0
#define AS_VT 8192
#define AS_BIAS 16384
#define AS_STGSZ 17408
#define AT_SMEM (AS_STG + 3*AS_STGSZ)   // 68608

__global__ void __launch_bounds__(256) attn_hmma(
    const int* __restrict__ qt_ids, const int* __restrict__ nv,
    const __nv_bfloat16* __restrict__ Qs,
    const __nv_bfloat16* __restrict__ Ks,
    const __nv_bfloat16* __restrict__ Vt,
    const float* __restrict__ biasg,
    __nv_bfloat16* __restrict__ ctx) {
    extern __shared__ char sm[];
    uint32_t sb = smem_u32(sm);
    int tid = threadIdx.x, w = tid >> 5, lane = tid & 31;
    int q0 = blockIdx.x * 128, h = blockIdx.y, b = blockIdx.z;
    int group = lane >> 2, qp = lane & 3;
    int q8 = lane >> 3, ln8 = lane & 7;
    int ntiles = (nv[b] + 63) >> 6;

    #pragma unroll
    for (int s = 0; s < 4; s++) {
        int idx = tid + s * 256;
        int r = idx >> 3, ch = idx & 7;
        size_t go = (size_t)(b * NQ + q0 + r) * HID + h * 64 + ch * 8;
        uint32_t off = (uint32_t)r * 128 + (uint32_t)((ch ^ (r & 7)) * 16);
        *(uint4*)(sm + AS_Q + off) = *(const uint4*)(Qs + go);
    }

    auto load_stage = [&](int t, int st) {
        int k0 = t * 64;
        uint32_t so = sb + AS_STG + st * AS_STGSZ;
        #pragma unroll
        for (int s = 0; s < 4; s++) {
            int idx = tid + s * 256;
            int m = idx >> 9;
            int rc = idx & 511;
            int r = rc >> 3, ch = rc & 7;
            uint32_t off = so + m * 8192 + (uint32_t)r * 128 + (uint32_t)((ch ^ (r & 7)) * 16);
            const __nv_bfloat16* src;
            if (m == 0) src = Ks + (size_t)(b * NK + k0 + r) * HID + h * 64 + ch * 8;
            else        src = Vt + (size_t)((b * HEADS + h) * 64 + r) * NK + k0 + ch * 8;
            CP_ASYNC16(off, src);
        }
        if (tid < 48) {
            int qt = tid >> 4, j = tid & 15;
            CP_ASYNC16(so + AS_BIAS + qt * 256 + j * 16,
                       biasg + (size_t)(b * 3 + qt) * NK + k0 + j * 4);
        }
        CP_COMMIT();
    };

    load_stage(0, 0);
    __syncthreads();

    uint32_t QHf[4][4];
    #pragma unroll
    for (int c2 = 0; c2 < 4; c2++) {
        int r = w * 16 + (lane & 15);
        int ch = c2 * 2 + (lane >> 4);
        uint32_t off = (uint32_t)r * 128 + (uint32_t)((ch ^ (r & 7)) * 16);
        ldsm4(QHf[c2], sb + AS_Q + off);
    }
    int qtA = qt_ids[q0 + w * 16 + group];
    int qtB = qt_ids[q0 + w * 16 + group + 8];

    float acc[8][4];
    #pragma unroll
    for (int i = 0; i < 8; i++)
        #pragma unroll
        for (int j = 0; j < 4; j++) acc[i][j] = 0.f;
    float lA = 0.f, lB = 0.f;

    int st_ld = 1, st_cp = 0;
    for (int t = 0; t < ntiles; t++) {
        if (t + 1 < ntiles) { load_stage(t + 1, st_ld); if (++st_ld == 3) st_ld = 0; CP_WAIT1(); }
        else                { CP_WAIT0(); }
        __syncthreads();
        uint32_t st = sb + AS_STG + st_cp * AS_STGSZ;
        char*    stc = sm + AS_STG + st_cp * AS_STGSZ;
        if (++st_cp == 3) st_cp = 0;

        float S[8][4];
        #pragma unroll
        for (int np = 0; np < 4; np++) {
            #pragma unroll
            for (int j = 0; j < 4; j++) { S[2*np][j] = 0.f; S[2*np+1][j] = 0.f; }
            #pragma unroll
            for (int c2 = 0; c2 < 4; c2++) {
                int row = np * 16 + (q8 >> 1) * 8 + ln8;
                int ch = c2 * 2 + (q8 & 1);
                uint32_t off = (uint32_t)row * 128 + (uint32_t)((ch ^ (row & 7)) * 16);
                uint32_t kh[4];
                ldsm4(kh, st + AS_KH + off);
                mma16816(S[2*np],   QHf[c2], &kh[0]);
                mma16816(S[2*np+1], QHf[c2], &kh[2]);
            }
        }

        const float* bA = (const float*)(stc + AS_BIAS) + qtA * 64;
        const float* bB = (const float*)(stc + AS_BIAS) + qtB * 64;
        uint32_t P[4][4];
        #pragma unroll
        for (int kc = 0; kc < 4; kc++) {
            int t0 = kc * 2, t1 = t0 + 1;
            float2 a0 = *(const float2*)(bA + t0 * 8 + qp * 2);
            float2 b0 = *(const float2*)(bB + t0 * 8 + qp * 2);
            float2 a1 = *(const float2*)(bA + t1 * 8 + qp * 2);
            float2 b1 = *(const float2*)(bB + t1 * 8 + qp * 2);
            float p00 = exp2m(S[t0][0] + a0.x), p01 = exp2m(S[t0][1] + a0.y);
            float p02 = exp2m(S[t0][2] + b0.x), p03 = exp2m(S[t0][3] + b0.y);
            float p10 = exp2m(S[t1][0] + a1.x), p11 = exp2m(S[t1][1] + a1.y);
            float p12 = exp2m(S[t1][2] + b1.x), p13 = exp2m(S[t1][3] + b1.y);
            lA += p00 + p01 + p10 + p11;
            lB += p02 + p03 + p12 + p13;
            __nv_bfloat162 tt;
            tt = __floats2bfloat162_rn(p00, p01); P[kc][0] = *(uint32_t*)&tt;
            tt = __floats2bfloat162_rn(p02, p03); P[kc][1] = *(uint32_t*)&tt;
            tt = __floats2bfloat162_rn(p10, p11); P[kc][2] = *(uint32_t*)&tt;
            tt = __floats2bfloat162_rn(p12, p13); P[kc][3] = *(uint32_t*)&tt;
        }

        #pragma unroll
        for (int kc = 0; kc < 4; kc++) {
            #pragma unroll
            for (int tdp = 0; tdp < 4; tdp++) {
                int row = tdp * 16 + (q8 >> 1) * 8 + ln8;
                int ch = kc * 2 + (q8 & 1);
                uint32_t off = (uint32_t)row * 128 + (uint32_t)((ch ^ (row & 7)) * 16);
                uint32_t v4[4];
                ldsm4(v4, st + AS_VT + off);
                mma16816(acc[2*tdp],   P[kc], &v4[0]);
                mma16816(acc[2*tdp+1], P[kc], &v4[2]);
            }
        }
    }

    lA += __shfl_xor_sync(0xffffffffu, lA, 1);
    lA += __shfl_xor_sync(0xffffffffu, lA, 2);
    lB += __shfl_xor_sync(0xffffffffu, lB, 1);
    lB += __shfl_xor_sync(0xffffffffu, lB, 2);
    float iA = 1.f / lA, iB = 1.f / lB;

    int rowA = q0 + w * 16 + group, rowB = rowA + 8;
    #pragma unroll
    for (int td = 0; td < 8; td++) {
        int col = h * 64 + td * 8 + qp * 2;
        size_t oA = (size_t)(b * NQ + rowA) * HID + col;
        size_t oB = (size_t)(b * NQ + rowB) * HID + col;
        *(__nv_bfloat162*)&ctx[oA] = __floats2bfloat162_rn(acc[td][0] * iA, acc[td][1] * iA);
        *(__nv_bfloat162*)&ctx[oB] = __floats2bfloat162_rn(acc[td][2] * iB, acc[td][3] * iB);
    }
}

// ---------------- launch ----------------------------------------------------
extern "C" void kernel_launch(void* const* d_in, const int* in_sizes, int n_in,
                              void* d_out, int out_size) {
    const float* queries = (const float*)d_in[0];
    const float* kv      = (const float*)d_in[1];
    const int*   qt_ids  = (const int*)d_in[2];
    const int*   kt_ids  = (const int*)d_in[3];
    const int*   pad     = (const int*)d_in[4];
    const float* Wq   = (const float*)d_in[5];
    const float* Wk   = (const float*)d_in[6];
    const float* Wv   = (const float*)d_in[7];
    const float* Wo   = (const float*)d_in[8];
    const float* qn_w = (const float*)d_in[9];
    const float* qn_b = (const float*)d_in[10];
    const float* kvn_w = (const float*)d_in[11];
    const float* kvn_b = (const float*)d_in[12];
    const float* on_w = (const float*)d_in[13];
    const float* on_b = (const float*)d_in[14];
    const float* tb   = (const float*)d_in[15];
    float* out = (float*)d_out;

    float *p_o, *p_bias;
    int *p_nv, *p_cidx;
    __nv_bfloat16 *p_qn, *p_kvn, *p_wq, *p_wk, *p_wv, *p_wo_h;
    __nv_bfloat16 *p_qs, *p_ks, *p_vt, *p_ctx;
    cudaGetSymbolAddress((void**)&p_o,    g_o);
    cudaGetSymbolAddress((void**)&p_bias, g_bias);
    cudaGetSymbolAddress((void**)&p_nv,   g_nv);
    cudaGetSymbolAddress((void**)&p_cidx, g_cidx);
    cudaGetSymbolAddress((void**)&p_qn,   g_qn);
    cudaGetSymbolAddress((void**)&p_kvn,  g_kvn);
    cudaGetSymbolAddress((void**)&p_wq,   g_wq_h);
    cudaGetSymbolAddress((void**)&p_wk,   g_wk_h);
    cudaGetSymbolAddress((void**)&p_wv,   g_wv_h);
    cudaGetSymbolAddress((void**)&p_wo_h, g_wo_h);
    cudaGetSymbolAddress((void**)&p_qs,   g_qs);
    cudaGetSymbolAddress((void**)&p_ks,   g_ks);
    cudaGetSymbolAddress((void**)&p_vt,   g_vt);
    cudaGetSymbolAddress((void**)&p_ctx,  g_ctx);

    static int attr_set = 0;
    if (!attr_set) {
        cudaFuncSetAttribute(gemm_proj, cudaFuncAttributeMaxDynamicSharedMemorySize, KV_SMEM);
        cudaFuncSetAttribute(gemm_o,    cudaFuncAttributeMaxDynamicSharedMemorySize, O_SMEM);
        cudaFuncSetAttribute(attn_hmma, cudaFuncAttributeMaxDynamicSharedMemorySize, AT_SMEM);
        attr_set = 1;
    }

    // 0. key compaction + bias table (fused)
    compact_bias_kernel<<<BATCH, 1024>>>(pad, kt_ids, tb, p_nv, p_cidx, p_bias);

    // 1. LN + weight prep (one launch, block-range dispatch)
    prep_all<<<MQ + MK + 2048, 256>>>(queries, kv, qn_w, qn_b, kvn_w, kvn_b,
                                      Wq, Wk, Wv, Wo,
                                      p_qn, p_kvn, p_wq, p_wk, p_wv, p_wo_h);

    // 2. unified projections (K/V fused + Q backfill)
    {
        dim3 gp(HID / 64, KV_Y + MQ / 128);
        gemm_proj<<<gp, 256, KV_SMEM>>>(p_kvn, p_qn, p_wk, p_wv, p_wq,
                                        p_ks, p_vt, p_qs, p_cidx, p_nv);
    }

    // 3. flash attention -> ctx (bf16)
    {
        dim3 ga(NQ / 128, HEADS, BATCH);
        attn_hmma<<<ga, 256, AT_SMEM>>>(qt_ids, p_nv, p_qs, p_ks, p_vt, p_bias, p_ctx);
    }

    // 4. output projection (1-term)
    {
        dim3 go(HID / 64, MQ / 128);
        gemm_o<<<go, 256, O_SMEM>>>(p_ctx, p_wo_h, p_o);
    }

    // 5. residual + LN -> d_out
    res_ln_kernel<<<MQ, 256>>>(queries, p_o, on_w, on_b, out);
}

// round 16
// speedup vs baseline: 15.5413x; 1.0503x over previous
#include <cuda_runtime.h>
#include <cuda_bf16.h>
#include <math.h>
#include <float.h>
#include <stdint.h>

#define BATCH 2
#define NQ    1024
#define NK    4096
#define HID   1024
#define HEADS 16
#define HD    64
#define LN_EPS 1e-5f
#define LOG2E 1.4426950408889634f
#define QKSCALE (0.125f * LOG2E)
#define M0    32.0f

#define MQ (BATCH*NQ)   // 2048
#define MK (BATCH*NK)   // 8192

// ---------------- scratch (__device__ globals) ------------------------------
__device__ float g_o   [MQ*HID];
__device__ float g_bias[BATCH*3*NK];
__device__ int   g_nv[BATCH];
__device__ int   g_cidx[BATCH*NK];

__device__ __nv_bfloat16 g_qn [MQ*HID];
__device__ __nv_bfloat16 g_kvn[MK*HID];
__device__ __nv_bfloat16 g_wq_h[HID*HID];
__device__ __nv_bfloat16 g_wk_h[HID*HID];
__device__ __nv_bfloat16 g_wv_h[HID*HID];
__device__ __nv_bfloat16 g_wo_h[HID*HID];
__device__ __nv_bfloat16 g_qs [MQ*HID];
__device__ __nv_bfloat16 g_ks [MK*HID];
__device__ __nv_bfloat16 g_vt [MK*HID];       // [(b*H+h)*64 + d][slot]
__device__ __nv_bfloat16 g_ctx[MQ*HID];

// ---------------- small helpers ---------------------------------------------
__device__ __forceinline__ uint32_t smem_u32(const void* p) {
    uint32_t a;
    asm("{ .reg .u64 t; cvta.to.shared.u64 t, %1; cvt.u32.u64 %0, t; }" : "=r"(a) : "l"(p));
    return a;
}

__device__ __forceinline__ float2 block_reduce2(float a, float b, float* sh) {
    #pragma unroll
    for (int o = 16; o; o >>= 1) {
        a += __shfl_xor_sync(0xffffffffu, a, o);
        b += __shfl_xor_sync(0xffffffffu, b, o);
    }
    int w = threadIdx.x >> 5;
    if ((threadIdx.x & 31) == 0) { sh[w] = a; sh[8 + w] = b; }
    __syncthreads();
    if (threadIdx.x == 0) {
        float sa = 0.f, sb = 0.f;
        #pragma unroll
        for (int i = 0; i < 8; i++) { sa += sh[i]; sb += sh[8 + i]; }
        sh[0] = sa; sh[8] = sb;
    }
    __syncthreads();
    return make_float2(sh[0], sh[8]);
}

#define CP_ASYNC16(dst, src) \
    asm volatile("cp.async.cg.shared.global [%0], [%1], 16;" :: "r"(dst), "l"(src))
#define CP_COMMIT() asm volatile("cp.async.commit_group;" ::: "memory")
#define CP_WAIT0()  asm volatile("cp.async.wait_group 0;" ::: "memory")
#define CP_WAIT1()  asm volatile("cp.async.wait_group 1;" ::: "memory")

__device__ __forceinline__ void ldsm4(uint32_t* r, uint32_t addr) {
    asm volatile("ldmatrix.sync.aligned.m8n8.x4.shared.b16 {%0,%1,%2,%3}, [%4];"
                 : "=r"(r[0]), "=r"(r[1]), "=r"(r[2]), "=r"(r[3]) : "r"(addr));
}

__device__ __forceinline__ void mma16816(float* c, const uint32_t* a, const uint32_t* b) {
    asm volatile(
        "mma.sync.aligned.m16n8k16.row.col.f32.bf16.bf16.f32 "
        "{%0,%1,%2,%3}, {%4,%5,%6,%7}, {%8,%9}, {%0,%1,%2,%3};"
        : "+f"(c[0]), "+f"(c[1]), "+f"(c[2]), "+f"(c[3])
        : "r"(a[0]), "r"(a[1]), "r"(a[2]), "r"(a[3]), "r"(b[0]), "r"(b[1]));
}

// ---------------- packed f32x2 exp2 pipeline --------------------------------
struct E2C { uint64_t MG, NMG, M1, C4, C3, C2, C1, C0; };

__device__ __forceinline__ uint64_t packf(float a, float b) {
    uint64_t r; asm("mov.b64 %0, {%1, %2};" : "=l"(r) : "f"(a), "f"(b)); return r;
}

// p = 2^(s + bias) for a pair; accumulates packed sum into lacc;
// returns bf16x2-packed probabilities. Requires s+bias in [-126, 0].
__device__ __forceinline__ uint32_t exp2p2(float s0, float s1, uint64_t bp,
                                           const E2C& K, uint64_t& lacc) {
    uint64_t x, t, r, f, p, sc;
    uint32_t tlo, thi;
    asm("mov.b64 %0, {%1, %2};" : "=l"(x) : "f"(s0), "f"(s1));
    asm("add.rn.f32x2 %0, %1, %2;" : "=l"(x) : "l"(x), "l"(bp));
    asm("add.rn.f32x2 %0, %1, %2;" : "=l"(t) : "l"(x), "l"(K.MG));
    asm("add.rn.f32x2 %0, %1, %2;" : "=l"(r) : "l"(t), "l"(K.NMG));
    asm("fma.rn.f32x2 %0, %1, %2, %3;" : "=l"(f) : "l"(r), "l"(K.M1), "l"(x));
    asm("fma.rn.f32x2 %0, %1, %2, %3;" : "=l"(p) : "l"(K.C4), "l"(f), "l"(K.C3));
    asm("fma.rn.f32x2 %0, %1, %2, %3;" : "=l"(p) : "l"(p), "l"(f), "l"(K.C2));
    asm("fma.rn.f32x2 %0, %1, %2, %3;" : "=l"(p) : "l"(p), "l"(f), "l"(K.C1));
    asm("fma.rn.f32x2 %0, %1, %2, %3;" : "=l"(p) : "l"(p), "l"(f), "l"(K.C0));
    asm("mov.b64 {%0, %1}, %2;" : "=r"(tlo), "=r"(thi) : "l"(t));
    uint32_t slo = (tlo << 23) + 0x3F800000u;
    uint32_t shi = (thi << 23) + 0x3F800000u;
    asm("mov.b64 %0, {%1, %2};" : "=l"(sc) : "r"(slo), "r"(shi));
    asm("mul.rn.f32x2 %0, %1, %2;" : "=l"(p) : "l"(p), "l"(sc));
    asm("add.rn.f32x2 %0, %1, %2;" : "=l"(lacc) : "l"(lacc), "l"(p));
    float p0, p1;
    asm("mov.b64 {%0, %1}, %2;" : "=f"(p0), "=f"(p1) : "l"(p));
    uint32_t out;
    asm("cvt.rn.bf16x2.f32 %0, %1, %2;" : "=r"(out) : "f"(p1), "f"(p0));
    return out;
}

// ------------- key compaction + fused bias table (one block per batch) -------
__global__ void compact_bias_kernel(const int* __restrict__ pad,
                                    const int* __restrict__ kt,
                                    const float* __restrict__ tb,
                                    int* __restrict__ nv, int* __restrict__ cidx,
                                    float* __restrict__ bias) {
    __shared__ int wsum[32];
    __shared__ float tbl[9];
    int b = blockIdx.x, tid = threadIdx.x;
    int lane = tid & 31, w = tid >> 5;
    int base = b * NK;
    if (tid < 9) tbl[tid] = tb[tid] * LOG2E - M0;
    int k0 = tid * 4;
    int f0 = pad[base + k0 + 0] != 0;
    int f1 = pad[base + k0 + 1] != 0;
    int f2 = pad[base + k0 + 2] != 0;
    int f3 = pad[base + k0 + 3] != 0;
    int c = f0 + f1 + f2 + f3;
    int inc = c;
    #pragma unroll
    for (int o = 1; o < 32; o <<= 1) {
        int t = __shfl_up_sync(0xffffffffu, inc, o);
        if (lane >= o) inc += t;
    }
    if (lane == 31) wsum[w] = inc;
    __syncthreads();
    if (w == 0) {
        int v = wsum[lane];
        #pragma unroll
        for (int o = 1; o < 32; o <<= 1) {
            int t = __shfl_up_sync(0xffffffffu, v, o);
            if (lane >= o) v += t;
        }
        wsum[lane] = v;
    }
    __syncthreads();
    int pos = inc - c + (w ? wsum[w - 1] : 0);
    if (f0) cidx[base + pos++] = k0 + 0;
    if (f1) cidx[base + pos++] = k0 + 1;
    if (f2) cidx[base + pos++] = k0 + 2;
    if (f3) cidx[base + pos++] = k0 + 3;
    int total = wsum[31];
    if (tid == 0) nv[b] = total;
    for (int s = total + tid; s < NK; s += 1024) cidx[base + s] = 0;
    __syncthreads();
    for (int s = tid; s < NK; s += 1024) {
        float t0, t1, t2;
        if (s < total) {
            int cc = kt[cidx[base + s]];
            t0 = tbl[cc]; t1 = tbl[3 + cc]; t2 = tbl[6 + cc];
        } else {
            t0 = t1 = t2 = -88.0f;   // p = 2^(S-88) negligible; keeps exp2p2 in range
        }
        bias[(size_t)(b * 3 + 0) * NK + s] = t0;
        bias[(size_t)(b * 3 + 1) * NK + s] = t1;
        bias[(size_t)(b * 3 + 2) * NK + s] = t2;
    }
}

// ---- merged prep: LN (queries + kv) -> bf16, then 4x weight -> bf16 hi ------
__global__ void prep_all(const float* __restrict__ xq, const float* __restrict__ xk,
                         const float* __restrict__ qw, const float* __restrict__ qb,
                         const float* __restrict__ kw, const float* __restrict__ kb,
                         const float* __restrict__ w0, const float* __restrict__ w1,
                         const float* __restrict__ w2, const float* __restrict__ w3,
                         __nv_bfloat16* __restrict__ oq, __nv_bfloat16* __restrict__ ok,
                         __nv_bfloat16* __restrict__ h0, __nv_bfloat16* __restrict__ h1,
                         __nv_bfloat16* __restrict__ h2, __nv_bfloat16* __restrict__ h3) {
    __shared__ float sh[16];
    int bid = blockIdx.x;
    if (bid < MQ + MK) {
        size_t row = bid;
        const float* x; const float* w; const float* b; __nv_bfloat16* oh;
        if (row < MQ) { x = xq + row * HID; w = qw; b = qb; oh = oq + row * HID; }
        else { size_t r2 = row - MQ; x = xk + r2 * HID; w = kw; b = kb; oh = ok + r2 * HID; }
        float4 v = ((const float4*)x)[threadIdx.x];
        float s  = v.x + v.y + v.z + v.w;
        float s2 = v.x*v.x + v.y*v.y + v.z*v.z + v.w*v.w;
        float2 r = block_reduce2(s, s2, sh);
        float mean = r.x * (1.f / HID);
        float var  = r.y * (1.f / HID) - mean * mean;
        float rstd = rsqrtf(var + LN_EPS);
        float4 wv = ((const float4*)w)[threadIdx.x];
        float4 bv = ((const float4*)b)[threadIdx.x];
        float o0 = (v.x - mean) * rstd * wv.x + bv.x;
        float o1 = (v.y - mean) * rstd * wv.y + bv.y;
        float o2 = (v.z - mean) * rstd * wv.z + bv.z;
        float o3 = (v.w - mean) * rstd * wv.w + bv.w;
        __nv_bfloat162* ph = (__nv_bfloat162*)(oh + threadIdx.x * 4);
        ph[0] = __floats2bfloat162_rn(o0, o1);
        ph[1] = __floats2bfloat162_rn(o2, o3);
    } else {
        int blk = bid - (MQ + MK);
        int wi = blk >> 9, ib = blk & 511;
        const float* src = (wi == 0) ? w0 : (wi == 1) ? w1 : (wi == 2) ? w2 : w3;
        __nv_bfloat16* dh = (wi == 0) ? h0 : (wi == 1) ? h1 : (wi == 2) ? h2 : h3;
        const int n4 = HID * HID / 4;
        for (int i = ib * 256 + threadIdx.x; i < n4; i += 512 * 256) {
            float4 v = ((const float4*)src)[i];
            __nv_bfloat162* ph = (__nv_bfloat162*)(dh + (size_t)i * 4);
            ph[0] = __floats2bfloat162_rn(v.x, v.y);
            ph[1] = __floats2bfloat162_rn(v.z, v.w);
        }
    }
}

// -------- residual + LayerNorm -----------------------------------------------
__global__ void res_ln_kernel(const float* __restrict__ x,
                              const float* __restrict__ y,
                              const float* __restrict__ w,
                              const float* __restrict__ b,
                              float* __restrict__ out) {
    __shared__ float sh[16];
    size_t row = blockIdx.x;
    float4 v  = ((const float4*)(x + row * HID))[threadIdx.x];
    float4 yv = ((const float4*)(y + row * HID))[threadIdx.x];
    v.x += yv.x; v.y += yv.y; v.z += yv.z; v.w += yv.w;
    float s  = v.x + v.y + v.z + v.w;
    float s2 = v.x*v.x + v.y*v.y + v.z*v.z + v.w*v.w;
    float2 r = block_reduce2(s, s2, sh);
    float mean = r.x * (1.f / HID);
    float var  = r.y * (1.f / HID) - mean * mean;
    float rstd = rsqrtf(var + LN_EPS);
    float4 wv = ((const float4*)w)[threadIdx.x];
    float4 bv = ((const float4*)b)[threadIdx.x];
    float4 o;
    o.x = (v.x - mean) * rstd * wv.x + bv.x;
    o.y = (v.y - mean) * rstd * wv.y + bv.y;
    o.z = (v.z - mean) * rstd * wv.z + bv.z;
    o.w = (v.w - mean) * rstd * wv.w + bv.w;
    ((float4*)(out + row * HID))[threadIdx.x] = o;
}

// ======== unified projections: Q (y>=KV_Y) + fused K/V (y<KV_Y) ==============
#define KV_A 0
#define KV_BK 16384
#define KV_BV 24576
#define KV_STG 32768
#define KV_SMEM (3*KV_STG)   // 98304
#define KV_Y (MK/128)        // 64

__global__ void __launch_bounds__(256) gemm_proj(
    const __nv_bfloat16* __restrict__ A,   // kvn
    const __nv_bfloat16* __restrict__ Aq,  // qn
    const __nv_bfloat16* __restrict__ Bk, const __nv_bfloat16* __restrict__ Bv,
    const __nv_bfloat16* __restrict__ Bq,
    __nv_bfloat16* __restrict__ Ks, __nv_bfloat16* __restrict__ Vt,
    __nv_bfloat16* __restrict__ Qs,
    const int* __restrict__ cidx, const int* __restrict__ nv) {
    extern __shared__ char sm[];
    uint32_t sb = smem_u32(sm);
    int tid = threadIdx.x;
    int wid = tid >> 5, lane = tid & 31;
    int wm = wid >> 1, wn = wid & 1;
    int colBase = blockIdx.x * 64;
    int q = lane >> 3, ln8 = lane & 7;
    bool kvPath = (blockIdx.y < KV_Y);

    if (kvPath) {
        int rowBase = blockIdx.y * 128;
        int bb = rowBase / NK;
        int slot0 = rowBase % NK;
        if (slot0 >= ((nv[bb] + 63) & ~63)) return;

        const __nv_bfloat16* pA[4];
        #pragma unroll
        for (int s = 0; s < 4; s++) {
            int slot = slot0 + (tid >> 3) + 32 * s;
            int ar = cidx[bb * NK + slot];
            pA[s] = A + (size_t)(bb * NK + ar) * HID + (tid & 7) * 8;
        }

        float acck[2][4][4], accv[2][4][4];
        #pragma unroll
        for (int i = 0; i < 2; i++)
            #pragma unroll
            for (int j = 0; j < 4; j++)
                #pragma unroll
                for (int r = 0; r < 4; r++) { acck[i][j][r] = 0.f; accv[i][j][r] = 0.f; }

        auto load_chunk = [&](int c, int st) {
            int k0 = c * 64;
            uint32_t so = sb + st * KV_STG;
            #pragma unroll
            for (int s = 0; s < 4; s++) {
                int row = (tid >> 3) + 32 * s, ch = tid & 7;
                uint32_t off = (uint32_t)row * 128 + (uint32_t)((ch ^ (row & 7)) * 16);
                CP_ASYNC16(so + KV_A + off, pA[s] + k0);
            }
            #pragma unroll
            for (int s = 0; s < 2; s++) {
                int idx = tid + s * 256;
                int row = idx >> 3, ch = idx & 7;
                uint32_t off = (uint32_t)row * 128 + (uint32_t)((ch ^ (row & 7)) * 16);
                CP_ASYNC16(so + KV_BK + off, Bk + (size_t)(colBase + row) * HID + k0 + ch * 8);
                CP_ASYNC16(so + KV_BV + off, Bv + (size_t)(colBase + row) * HID + k0 + ch * 8);
            }
            CP_COMMIT();
        };

        load_chunk(0, 0);
        int st_ld = 1, st_cp = 0;

        for (int c = 0; c < 16; c++) {
            if (c < 15) { load_chunk(c + 1, st_ld); if (++st_ld == 3) st_ld = 0; CP_WAIT1(); }
            else        { CP_WAIT0(); }
            __syncthreads();
            uint32_t Ab  = sb + st_cp * KV_STG + KV_A;
            uint32_t Bkb = sb + st_cp * KV_STG + KV_BK;
            uint32_t Bvb = sb + st_cp * KV_STG + KV_BV;
            if (++st_cp == 3) st_cp = 0;
            #pragma unroll
            for (int ti = 0; ti < 4; ti++) {
                uint32_t af[2][4];
                #pragma unroll
                for (int mi = 0; mi < 2; mi++) {
                    int row = wm * 32 + mi * 16 + (q & 1) * 8 + ln8;
                    int ch = ti * 2 + (q >> 1);
                    ldsm4(af[mi], Ab + row * 128 + ((ch ^ (row & 7)) * 16));
                }
                uint32_t bk[2][4], bv[2][4];
                #pragma unroll
                for (int g = 0; g < 2; g++) {
                    int row = wn * 32 + g * 16 + (q >> 1) * 8 + ln8;
                    int ch = ti * 2 + (q & 1);
                    uint32_t off = row * 128 + ((ch ^ (row & 7)) * 16);
                    ldsm4(bk[g], Bkb + off);
                    ldsm4(bv[g], Bvb + off);
                }
                #pragma unroll
                for (int mi = 0; mi < 2; mi++) {
                    mma16816(acck[mi][0], af[mi], &bk[0][0]);
                    mma16816(acck[mi][1], af[mi], &bk[0][2]);
                    mma16816(acck[mi][2], af[mi], &bk[1][0]);
                    mma16816(acck[mi][3], af[mi], &bk[1][2]);
                    mma16816(accv[mi][0], af[mi], &bv[0][0]);
                    mma16816(accv[mi][1], af[mi], &bv[0][2]);
                    mma16816(accv[mi][2], af[mi], &bv[1][0]);
                    mma16816(accv[mi][3], af[mi], &bv[1][2]);
                }
            }
        }

        // K epilogue: bf16 row-major
        {
            int r0 = rowBase + wm * 32 + (lane >> 2);
            int c0 = colBase + wn * 32 + (lane & 3) * 2;
            #pragma unroll
            for (int mi = 0; mi < 2; mi++) {
                #pragma unroll
                for (int ni = 0; ni < 4; ni++) {
                    int rr = r0 + mi * 16;
                    int cc = c0 + ni * 8;
                    *(__nv_bfloat162*)&Ks[(size_t)rr * HID + cc] =
                        __floats2bfloat162_rn(acck[mi][ni][0], acck[mi][ni][1]);
                    *(__nv_bfloat162*)&Ks[(size_t)(rr + 8) * HID + cc] =
                        __floats2bfloat162_rn(acck[mi][ni][2], acck[mi][ni][3]);
                }
            }
        }

        // V epilogue: transpose through smem -> Vt[(b,h,d)][slot]
        __syncthreads();
        {
            float* ts = (float*)sm;
            int r0l = wm * 32 + (lane >> 2);
            int c0l = wn * 32 + (lane & 3) * 2;
            #pragma unroll
            for (int mi = 0; mi < 2; mi++) {
                #pragma unroll
                for (int ni = 0; ni < 4; ni++) {
                    int rr = r0l + mi * 16, cc = c0l + ni * 8;
                    ts[rr * 65 + cc] = accv[mi][ni][0];
                    ts[rr * 65 + cc + 1] = accv[mi][ni][1];
                    ts[(rr + 8) * 65 + cc] = accv[mi][ni][2];
                    ts[(rr + 8) * 65 + cc + 1] = accv[mi][ni][3];
                }
            }
            __syncthreads();
            int hh = blockIdx.x;
            int d = tid >> 2, kb = (tid & 3) * 32;
            __nv_bfloat16* dst = Vt + (size_t)((bb * HEADS + hh) * 64 + d) * NK + slot0 + kb;
            #pragma unroll
            for (int k = 0; k < 32; k += 2) {
                *(__nv_bfloat162*)(dst + k) =
                    __floats2bfloat162_rn(ts[(kb + k) * 65 + d], ts[(kb + k + 1) * 65 + d]);
            }
        }
    } else {
        // ---------------- Q path: dense A, single B ----------------
        int rowBase = (blockIdx.y - KV_Y) * 128;

        float acc[2][4][4];
        #pragma unroll
        for (int i = 0; i < 2; i++)
            #pragma unroll
            for (int j = 0; j < 4; j++)
                #pragma unroll
                for (int r = 0; r < 4; r++) acc[i][j][r] = 0.f;

        auto load_chunk = [&](int c, int st) {
            int k0 = c * 64;
            uint32_t so = sb + st * KV_STG;
            #pragma unroll
            for (int s = 0; s < 4; s++) {
                int row = (tid >> 3) + 32 * s, ch = tid & 7;
                uint32_t off = (uint32_t)row * 128 + (uint32_t)((ch ^ (row & 7)) * 16);
                CP_ASYNC16(so + KV_A + off,
                           Aq + (size_t)(rowBase + row) * HID + k0 + (tid & 7) * 8);
            }
            #pragma unroll
            for (int s = 0; s < 2; s++) {
                int idx = tid + s * 256;
                int row = idx >> 3, ch = idx & 7;
                uint32_t off = (uint32_t)row * 128 + (uint32_t)((ch ^ (row & 7)) * 16);
                CP_ASYNC16(so + KV_BK + off, Bq + (size_t)(colBase + row) * HID + k0 + ch * 8);
            }
            CP_COMMIT();
        };

        load_chunk(0, 0);
        int st_ld = 1, st_cp = 0;

        for (int c = 0; c < 16; c++) {
            if (c < 15) { load_chunk(c + 1, st_ld); if (++st_ld == 3) st_ld = 0; CP_WAIT1(); }
            else        { CP_WAIT0(); }
            __syncthreads();
            uint32_t Ab = sb + st_cp * KV_STG + KV_A;
            uint32_t Bb = sb + st_cp * KV_STG + KV_BK;
            if (++st_cp == 3) st_cp = 0;
            #pragma unroll
            for (int ti = 0; ti < 4; ti++) {
                uint32_t af[2][4];
                #pragma unroll
                for (int mi = 0; mi < 2; mi++) {
                    int row = wm * 32 + mi * 16 + (q & 1) * 8 + ln8;
                    int ch = ti * 2 + (q >> 1);
                    ldsm4(af[mi], Ab + row * 128 + ((ch ^ (row & 7)) * 16));
                }
                uint32_t bf[2][4];
                #pragma unroll
                for (int g = 0; g < 2; g++) {
                    int row = wn * 32 + g * 16 + (q >> 1) * 8 + ln8;
                    int ch = ti * 2 + (q & 1);
                    ldsm4(bf[g], Bb + row * 128 + ((ch ^ (row & 7)) * 16));
                }
                #pragma unroll
                for (int mi = 0; mi < 2; mi++) {
                    mma16816(acc[mi][0], af[mi], &bf[0][0]);
                    mma16816(acc[mi][1], af[mi], &bf[0][2]);
                    mma16816(acc[mi][2], af[mi], &bf[1][0]);
                    mma16816(acc[mi][3], af[mi], &bf[1][2]);
                }
            }
        }

        int r0 = rowBase + wm * 32 + (lane >> 2);
        int c0 = colBase + wn * 32 + (lane & 3) * 2;
        #pragma unroll
        for (int mi = 0; mi < 2; mi++) {
            #pragma unroll
            for (int ni = 0; ni < 4; ni++) {
                int rr = r0 + mi * 16;
                int cc = c0 + ni * 8;
                *(__nv_bfloat162*)&Qs[(size_t)rr * HID + cc] =
                    __floats2bfloat162_rn(acc[mi][ni][0] * QKSCALE, acc[mi][ni][1] * QKSCALE);
                *(__nv_bfloat162*)&Qs[(size_t)(rr + 8) * HID + cc] =
                    __floats2bfloat162_rn(acc[mi][ni][2] * QKSCALE, acc[mi][ni][3] * QKSCALE);
            }
        }
    }
}

// ============ O projection: 1-term bf16 (ctx @ Wo_h^T), fp32 out, 3-stage ===
#define O_A 0
#define O_B 16384
#define O_STG 24576
#define O_SMEM (3*O_STG)   // 73728

__global__ void __launch_bounds__(256, 2) gemm_o(
    const __nv_bfloat16* __restrict__ A, const __nv_bfloat16* __restrict__ B,
    float* __restrict__ C) {
    extern __shared__ char sm[];
    uint32_t sb = smem_u32(sm);
    int tid = threadIdx.x;
    int wid = tid >> 5, lane = tid & 31;
    int wm = wid >> 1, wn = wid & 1;
    int rowBase = blockIdx.y * 128;
    int colBase = blockIdx.x * 64;
    int q = lane >> 3, ln8 = lane & 7;

    float acc[2][4][4];
    #pragma unroll
    for (int i = 0; i < 2; i++)
        #pragma unroll
        for (int j = 0; j < 4; j++)
            #pragma unroll
            for (int r = 0; r < 4; r++) acc[i][j][r] = 0.f;

    auto load_chunk = [&](int c, int st) {
        int k0 = c * 64;
        uint32_t so = sb + st * O_STG;
        #pragma unroll
        for (int s = 0; s < 4; s++) {
            int row = (tid >> 3) + 32 * s, ch = tid & 7;
            uint32_t off = (uint32_t)row * 128 + (uint32_t)((ch ^ (row & 7)) * 16);
            CP_ASYNC16(so + O_A + off, A + (size_t)(rowBase + row) * HID + k0 + ch * 8);
        }
        #pragma unroll
        for (int s = 0; s < 2; s++) {
            int idx = tid + s * 256;
            int row = idx >> 3, ch = idx & 7;
            uint32_t off = (uint32_t)row * 128 + (uint32_t)((ch ^ (row & 7)) * 16);
            CP_ASYNC16(so + O_B + off, B + (size_t)(colBase + row) * HID + k0 + ch * 8);
        }
        CP_COMMIT();
    };

    load_chunk(0, 0);
    int st_ld = 1, st_cp = 0;

    for (int c = 0; c < 16; c++) {
        if (c < 15) { load_chunk(c + 1, st_ld); if (++st_ld == 3) st_ld = 0; CP_WAIT1(); }
        else        { CP_WAIT0(); }
        __syncthreads();
        uint32_t Ab = sb + st_cp * O_STG + O_A;
        uint32_t Bb = sb + st_cp * O_STG + O_B;
        if (++st_cp == 3) st_cp = 0;
        #pragma unroll
        for (int ti = 0; ti < 4; ti++) {
            uint32_t af[2][4];
            #pragma unroll
            for (int mi = 0; mi < 2; mi++) {
                int row = wm * 32 + mi * 16 + (q & 1) * 8 + ln8;
                int ch = ti * 2 + (q >> 1);
                ldsm4(af[mi], Ab + row * 128 + ((ch ^ (row & 7)) * 16));
            }
            uint32_t bf[2][4];
            #pragma unroll
            for (int g = 0; g < 2; g++) {
                int row = wn * 32 + g * 16 + (q >> 1) * 8 + ln8;
                int ch = ti * 2 + (q & 1);
                ldsm4(bf[g], Bb + row * 128 + ((ch ^ (row & 7)) * 16));
            }
            #pragma unroll
            for (int mi = 0; mi < 2; mi++) {
                mma16816(acc[mi][0], af[mi], &bf[0][0]);
                mma16816(acc[mi][1], af[mi], &bf[0][2]);
                mma16816(acc[mi][2], af[mi], &bf[1][0]);
                mma16816(acc[mi][3], af[mi], &bf[1][2]);
            }
        }
    }

    int r0 = rowBase + wm * 32 + (lane >> 2);
    int c0 = colBase + wn * 32 + (lane & 3) * 2;
    #pragma unroll
    for (int mi = 0; mi < 2; mi++) {
        #pragma unroll
        for (int ni = 0; ni < 4; ni++) {
            int rr = r0 + mi * 16;
            int cc = c0 + ni * 8;
            *(float2*)&C[(size_t)rr * HID + cc] = make_float2(acc[mi][ni][0], acc[mi][ni][1]);
            *(float2*)&C[(size_t)(rr + 8) * HID + cc] = make_float2(acc[mi][ni][2], acc[mi][ni][3]);
        }
    }
}

// ================= HMMA flash attention: 3-stage, 128 q/CTA, 256 threads ====
#define AS_Q 0
#define AS_STG 16384
#define AS_KH 0
#define AS_VT 8192
#define AS_BIAS 16384
#define AS_STGSZ 17408
#define AT_SMEM (AS_STG + 3*AS_STGSZ)   // 68608

__global__ void __launch_bounds__(256, 2) attn_hmma(
    const int* __restrict__ qt_ids, const int* __restrict__ nv,
    const __nv_bfloat16* __restrict__ Qs,
    const __nv_bfloat16* __restrict__ Ks,
    const __nv_bfloat16* __restrict__ Vt,
    const float* __restrict__ biasg,
    __nv_bfloat16* __restrict__ ctx) {
    extern __shared__ char sm[];
    uint32_t sb = smem_u32(sm);
    int tid = threadIdx.x, w = tid >> 5, lane = tid & 31;
    int q0 = blockIdx.x * 128, h = blockIdx.y, b = blockIdx.z;
    int group = lane >> 2, qp = lane & 3;
    int q8 = lane >> 3, ln8 = lane & 7;
    int ntiles = (nv[b] + 63) >> 6;

    #pragma unroll
    for (int s = 0; s < 4; s++) {
        int idx = tid + s * 256;
        int r = idx >> 3, ch = idx & 7;
        size_t go = (size_t)(b * NQ + q0 + r) * HID + h * 64 + ch * 8;
        uint32_t off = (uint32_t)r * 128 + (uint32_t)((ch ^ (r & 7)) * 16);
        *(uint4*)(sm + AS_Q + off) = *(const uint4*)(Qs + go);
    }

    auto load_stage = [&](int t, int st) {
        int k0 = t * 64;
        uint32_t so = sb + AS_STG + st * AS_STGSZ;
        #pragma unroll
        for (int s = 0; s < 4; s++) {
            int idx = tid + s * 256;
            int m = idx >> 9;
            int rc = idx & 511;
            int r = rc >> 3, ch = rc & 7;
            uint32_t off = so + m * 8192 + (uint32_t)r * 128 + (uint32_t)((ch ^ (r & 7)) * 16);
            const __nv_bfloat16* src;
            if (m == 0) src = Ks + (size_t)(b * NK + k0 + r) * HID + h * 64 + ch * 8;
            else        src = Vt + (size_t)((b * HEADS + h) * 64 + r) * NK + k0 + ch * 8;
            CP_ASYNC16(off, src);
        }
        if (tid < 48) {
            int qt = tid >> 4, j = tid & 15;
            CP_ASYNC16(so + AS_BIAS + qt * 256 + j * 16,
                       biasg + (size_t)(b * 3 + qt) * NK + k0 + j * 4);
        }
        CP_COMMIT();
    };

    load_stage(0, 0);
    __syncthreads();

    // packed exp2 constants (built once; ptxas can rematerialize)
    E2C KC;
    KC.MG  = packf(12582912.f, 12582912.f);
    KC.NMG = packf(-12582912.f, -12582912.f);
    KC.M1  = packf(-1.f, -1.f);
    KC.C4  = packf(9.6181291e-3f, 9.6181291e-3f);
    KC.C3  = packf(5.5504109e-2f, 5.5504109e-2f);
    KC.C2  = packf(2.4022651e-1f, 2.4022651e-1f);
    KC.C1  = packf(6.9314718e-1f, 6.9314718e-1f);
    KC.C0  = packf(1.0f, 1.0f);

    uint32_t QHf[4][4];
    #pragma unroll
    for (int c2 = 0; c2 < 4; c2++) {
        int r = w * 16 + (lane & 15);
        int ch = c2 * 2 + (lane >> 4);
        uint32_t off = (uint32_t)r * 128 + (uint32_t)((ch ^ (r & 7)) * 16);
        ldsm4(QHf[c2], sb + AS_Q + off);
    }
    int qtA = qt_ids[q0 + w * 16 + group];
    int qtB = qt_ids[q0 + w * 16 + group + 8];

    float acc[8][4];
    #pragma unroll
    for (int i = 0; i < 8; i++)
        #pragma unroll
        for (int j = 0; j < 4; j++) acc[i][j] = 0.f;
    uint64_t lAp = 0ull, lBp = 0ull;   // packed (0.f, 0.f)

    int st_ld = 1, st_cp = 0;
    for (int t = 0; t < ntiles; t++) {
        if (t + 1 < ntiles) { load_stage(t + 1, st_ld); if (++st_ld == 3) st_ld = 0; CP_WAIT1(); }
        else                { CP_WAIT0(); }
        __syncthreads();
        uint32_t st = sb + AS_STG + st_cp * AS_STGSZ;
        char*    stc = sm + AS_STG + st_cp * AS_STGSZ;
        if (++st_cp == 3) st_cp = 0;

        float S[8][4];
        #pragma unroll
        for (int np = 0; np < 4; np++) {
            #pragma unroll
            for (int j = 0; j < 4; j++) { S[2*np][j] = 0.f; S[2*np+1][j] = 0.f; }
            #pragma unroll
            for (int c2 = 0; c2 < 4; c2++) {
                int row = np * 16 + (q8 >> 1) * 8 + ln8;
                int ch = c2 * 2 + (q8 & 1);
                uint32_t off = (uint32_t)row * 128 + (uint32_t)((ch ^ (row & 7)) * 16);
                uint32_t kh[4];
                ldsm4(kh, st + AS_KH + off);
                mma16816(S[2*np],   QHf[c2], &kh[0]);
                mma16816(S[2*np+1], QHf[c2], &kh[2]);
            }
        }

        const float* bA = (const float*)(stc + AS_BIAS) + qtA * 64;
        const float* bB = (const float*)(stc + AS_BIAS) + qtB * 64;
        uint32_t P[4][4];
        #pragma unroll
        for (int kc = 0; kc < 4; kc++) {
            int t0 = kc * 2, t1 = t0 + 1;
            uint64_t a0 = *(const uint64_t*)(bA + t0 * 8 + qp * 2);
            uint64_t b0 = *(const uint64_t*)(bB + t0 * 8 + qp * 2);
            uint64_t a1 = *(const uint64_t*)(bA + t1 * 8 + qp * 2);
            uint64_t b1 = *(const uint64_t*)(bB + t1 * 8 + qp * 2);
            P[kc][0] = exp2p2(S[t0][0], S[t0][1], a0, KC, lAp);
            P[kc][1] = exp2p2(S[t0][2], S[t0][3], b0, KC, lBp);
            P[kc][2] = exp2p2(S[t1][0], S[t1][1], a1, KC, lAp);
            P[kc][3] = exp2p2(S[t1][2], S[t1][3], b1, KC, lBp);
        }

        #pragma unroll
        for (int kc = 0; kc < 4; kc++) {
            #pragma unroll
            for (int tdp = 0; tdp < 4; tdp++) {
                int row = tdp * 16 + (q8 >> 1) * 8 + ln8;
                int ch = kc * 2 + (q8 & 1);
                uint32_t off = (uint32_t)row * 128 + (uint32_t)((ch ^ (row & 7)) * 16);
                uint32_t v4[4];
                ldsm4(v4, st + AS_VT + off);
                mma16816(acc[2*tdp],   P[kc], &v4[0]);
                mma16816(acc[2*tdp+1], P[kc], &v4[2]);
            }
        }
    }

    // unpack packed l-sums, then quad reduce
    float lA, lB;
    {
        float x0, x1, y0, y1;
        asm("mov.b64 {%0, %1}, %2;" : "=f"(x0), "=f"(x1) : "l"(lAp));
        asm("mov.b64 {%0, %1}, %2;" : "=f"(y0), "=f"(y1) : "l"(lBp));
        lA = x0 + x1; lB = y0 + y1;
    }
    lA += __shfl_xor_sync(0xffffffffu, lA, 1);
    lA += __shfl_xor_sync(0xffffffffu, lA, 2);
    lB += __shfl_xor_sync(0xffffffffu, lB, 1);
    lB += __shfl_xor_sync(0xffffffffu, lB, 2);
    float iA = 1.f / lA, iB = 1.f / lB;

    int rowA = q0 + w * 16 + group, rowB = rowA + 8;
    #pragma unroll
    for (int td = 0; td < 8; td++) {
        int col = h * 64 + td * 8 + qp * 2;
        size_t oA = (size_t)(b * NQ + rowA) * HID + col;
        size_t oB = (size_t)(b * NQ + rowB) * HID + col;
        *(__nv_bfloat162*)&ctx[oA] = __floats2bfloat162_rn(acc[td][0] * iA, acc[td][1] * iA);
        *(__nv_bfloat162*)&ctx[oB] = __floats2bfloat162_rn(acc[td][2] * iB, acc[td][3] * iB);
    }
}

// ---------------- launch ----------------------------------------------------
extern "C" void kernel_launch(void* const* d_in, const int* in_sizes, int n_in,
                              void* d_out, int out_size) {
    const float* queries = (const float*)d_in[0];
    const float* kv      = (const float*)d_in[1];
    const int*   qt_ids  = (const int*)d_in[2];
    const int*   kt_ids  = (const int*)d_in[3];
    const int*   pad     = (const int*)d_in[4];
    const float* Wq   = (const float*)d_in[5];
    const float* Wk   = (const float*)d_in[6];
    const float* Wv   = (const float*)d_in[7];
    const float* Wo   = (const float*)d_in[8];
    const float* qn_w = (const float*)d_in[9];
    const float* qn_b = (const float*)d_in[10];
    const float* kvn_w = (const float*)d_in[11];
    const float* kvn_b = (const float*)d_in[12];
    const float* on_w = (const float*)d_in[13];
    const float* on_b = (const float*)d_in[14];
    const float* tb   = (const float*)d_in[15];
    float* out = (float*)d_out;

    float *p_o, *p_bias;
    int *p_nv, *p_cidx;
    __nv_bfloat16 *p_qn, *p_kvn, *p_wq, *p_wk, *p_wv, *p_wo_h;
    __nv_bfloat16 *p_qs, *p_ks, *p_vt, *p_ctx;
    cudaGetSymbolAddress((void**)&p_o,    g_o);
    cudaGetSymbolAddress((void**)&p_bias, g_bias);
    cudaGetSymbolAddress((void**)&p_nv,   g_nv);
    cudaGetSymbolAddress((void**)&p_cidx, g_cidx);
    cudaGetSymbolAddress((void**)&p_qn,   g_qn);
    cudaGetSymbolAddress((void**)&p_kvn,  g_kvn);
    cudaGetSymbolAddress((void**)&p_wq,   g_wq_h);
    cudaGetSymbolAddress((void**)&p_wk,   g_wk_h);
    cudaGetSymbolAddress((void**)&p_wv,   g_wv_h);
    cudaGetSymbolAddress((void**)&p_wo_h, g_wo_h);
    cudaGetSymbolAddress((void**)&p_qs,   g_qs);
    cudaGetSymbolAddress((void**)&p_ks,   g_ks);
    cudaGetSymbolAddress((void**)&p_vt,   g_vt);
    cudaGetSymbolAddress((void**)&p_ctx,  g_ctx);

    static int attr_set = 0;
    if (!attr_set) {
        cudaFuncSetAttribute(gemm_proj, cudaFuncAttributeMaxDynamicSharedMemorySize, KV_SMEM);
        cudaFuncSetAttribute(gemm_o,    cudaFuncAttributeMaxDynamicSharedMemorySize, O_SMEM);
        cudaFuncSetAttribute(attn_hmma, cudaFuncAttributeMaxDynamicSharedMemorySize, AT_SMEM);
        attr_set = 1;
    }

    // 0. key compaction + bias table (fused)
    compact_bias_kernel<<<BATCH, 1024>>>(pad, kt_ids, tb, p_nv, p_cidx, p_bias);

    // 1. LN + weight prep (one launch, block-range dispatch)
    prep_all<<<MQ + MK + 2048, 256>>>(queries, kv, qn_w, qn_b, kvn_w, kvn_b,
                                      Wq, Wk, Wv, Wo,
                                      p_qn, p_kvn, p_wq, p_wk, p_wv, p_wo_h);

    // 2. unified projections (K/V fused + Q backfill)
    {
        dim3 gp(HID / 64, KV_Y + MQ / 128);
        gemm_proj<<<gp, 256, KV_SMEM>>>(p_kvn, p_qn, p_wk, p_wv, p_wq,
                                        p_ks, p_vt, p_qs, p_cidx, p_nv);
    }

    // 3. flash attention -> ctx (bf16)
    {
        dim3 ga(NQ / 128, HEADS, BATCH);
        attn_hmma<<<ga, 256, AT_SMEM>>>(qt_ids, p_nv, p_qs, p_ks, p_vt, p_bias, p_ctx);
    }

    // 4. output projection (1-term)
    {
        dim3 go(HID / 64, MQ / 128);
        gemm_o<<<go, 256, O_SMEM>>>(p_ctx, p_wo_h, p_o);
    }

    // 5. residual + LN -> d_out
    res_ln_kernel<<<MQ, 256>>>(queries, p_o, on_w, on_b, out);
}